// round 2
// baseline (speedup 1.0000x reference)
#include <cuda_runtime.h>
#include <math.h>

#define SS 1024
#define DD 1024
#define HH 16
#define HDIM 64
#define FFDIM 4096
#define NROW 4096      // B*S
#define D1 1025
#define HD1 65
#define BHN 64         // B*H
#define CATW 1040      // H*(HD+1)
#define FFP 4104       // FF+1 padded to mult of 8

// ---------------- scratch (device globals; no allocation allowed) ----------
__device__ float g_xn [NROW * D1];          // layernorm output (manifold, 1025)
__device__ float g_qkv[NROW * 3072];        // raw q|k|v projections
__device__ float g_qT [BHN * HD1 * SS];     // q, e-major [bh][e][s], e0 = -t
__device__ float g_kT [BHN * HD1 * SS];     // k, e-major [bh][e][s], e0 = +t
__device__ float g_v  [BHN * SS * HD1];     // v row-major [bh][s][e]
__device__ float g_att[(size_t)BHN * SS * SS];  // attention matrix (268MB)
__device__ float g_cat[NROW * CATW];        // concat of projected heads
__device__ float g_tmp[NROW * DD];          // GEMM outputs (attn_out / mlp space)
__device__ float g_x2 [NROW * D1];          // x after first residual
__device__ float g_ff [NROW * FFP];         // manifold FF activations (col0 = t)

// ---------------- helpers ---------------------------------------------------
__device__ __forceinline__ float blockReduceSum(float v, float* sm) {
    #pragma unroll
    for (int o = 16; o; o >>= 1) v += __shfl_xor_sync(0xffffffffu, v, o);
    int w = threadIdx.x >> 5;
    if ((threadIdx.x & 31) == 0) sm[w] = v;
    __syncthreads();
    if (threadIdx.x < 32) {
        float t = (threadIdx.x < 8) ? sm[threadIdx.x] : 0.f;
        #pragma unroll
        for (int o = 4; o; o >>= 1) t += __shfl_xor_sync(0xffffffffu, t, o);
        if (threadIdx.x == 0) sm[0] = t;
    }
    __syncthreads();
    float r = sm[0];
    __syncthreads();
    return r;
}

__device__ __forceinline__ float blockReduceMax(float v, float* sm) {
    #pragma unroll
    for (int o = 16; o; o >>= 1) v = fmaxf(v, __shfl_xor_sync(0xffffffffu, v, o));
    int w = threadIdx.x >> 5;
    if ((threadIdx.x & 31) == 0) sm[w] = v;
    __syncthreads();
    if (threadIdx.x < 32) {
        float t = (threadIdx.x < 8) ? sm[threadIdx.x] : -3.4e38f;
        #pragma unroll
        for (int o = 4; o; o >>= 1) t = fmaxf(t, __shfl_xor_sync(0xffffffffu, t, o));
        if (threadIdx.x == 0) sm[0] = t;
    }
    __syncthreads();
    float r = sm[0];
    __syncthreads();
    return r;
}

__device__ __forceinline__ float gelu_tanh(float x) {
    float x3 = x * x * x;
    float t = tanhf(0.7978845608028654f * (x + 0.044715f * x3));
    return 0.5f * x * (1.0f + t);
}

// ---------------- K1/K9: hyperbolic layernorm -------------------------------
// out[row] = to_manifold((s - mu) * rstd * g + b), s = in[row][1:]
__global__ void __launch_bounds__(256) ln_kernel(const float* __restrict__ Xext,
                                                 int useInternal,
                                                 const float* __restrict__ g,
                                                 const float* __restrict__ b) {
    __shared__ float sm[8];
    const float* X = useInternal ? g_x2 : Xext;
    int row = blockIdx.x;
    const float* xr = X + (size_t)row * D1 + 1;
    float v[4], s = 0.f, sq = 0.f;
    #pragma unroll
    for (int i = 0; i < 4; i++) {
        v[i] = xr[threadIdx.x + i * 256];
        s += v[i]; sq += v[i] * v[i];
    }
    s  = blockReduceSum(s,  sm);
    sq = blockReduceSum(sq, sm);
    float mu = s * (1.f / DD);
    float var = sq * (1.f / DD) - mu * mu;
    float rstd = rsqrtf(var + 1e-5f);
    float o[4], ss = 0.f;
    #pragma unroll
    for (int i = 0; i < 4; i++) {
        int c = threadIdx.x + i * 256;
        o[i] = (v[i] - mu) * rstd * g[c] + b[c];
        ss += o[i] * o[i];
    }
    ss = blockReduceSum(ss, sm);
    float* orow = g_xn + (size_t)row * D1;
    if (threadIdx.x == 0) orow[0] = sqrtf(1.f + ss);
    #pragma unroll
    for (int i = 0; i < 4; i++) orow[1 + threadIdx.x + i * 256] = o[i];
}

// ---------------- generic 128x128x8 SGEMM -----------------------------------
// C[m][n] = sum_k A[m][k] * B[k*bRow + ((nLoc+n)>>6)*bHead + ((nLoc+n)&63)] + bias
// asel: 0=g_xn 1=g_cat 2=g_ff ; csel: 0=g_qkv 1=g_tmp 2=g_ff+1
template<int EPI>
__global__ void __launch_bounds__(256) gemm_k(
    int asel, int csel,
    const float* __restrict__ B0, const float* __restrict__ B1, const float* __restrict__ B2,
    const float* __restrict__ bias0, const float* __restrict__ bias1, const float* __restrict__ bias2,
    int K, int lda, int bRow, int bHead, int ldc, int nPerMat)
{
    __shared__ float As[8][128];
    __shared__ float Bs[8][128];
    const float* A = (asel == 0) ? g_xn : (asel == 1 ? g_cat : g_ff);
    float*       C = (csel == 0) ? g_qkv : (csel == 1 ? g_tmp : (g_ff + 1));

    int bm = blockIdx.y, bn = blockIdx.x;
    int nBase = bn * 128;
    int sel = nBase / nPerMat;
    const float* B    = (sel == 0) ? B0    : (sel == 1 ? B1    : B2);
    const float* bias = (sel == 0) ? bias0 : (sel == 1 ? bias1 : bias2);
    int nLoc = nBase - sel * nPerMat;

    int tid = threadIdx.x;
    int arow = tid >> 1, acol = (tid & 1) * 4;
    int bkr = tid >> 5, bnc = (tid & 31) * 4;
    const float* Ap = A + (size_t)(bm * 128 + arow) * lda;

    float acc[8][8] = {};
    int tr = tid >> 4, tc = tid & 15;

    for (int k0 = 0; k0 < K; k0 += 8) {
        #pragma unroll
        for (int i = 0; i < 4; i++) {
            int kk = k0 + acol + i;
            As[acol + i][arow] = (kk < K) ? Ap[kk] : 0.f;
        }
        {
            int kk = k0 + bkr;
            int n = nLoc + bnc;
            float4 val = make_float4(0.f, 0.f, 0.f, 0.f);
            if (kk < K)
                val = *reinterpret_cast<const float4*>(
                        B + (size_t)kk * bRow + (size_t)(n >> 6) * bHead + (n & 63));
            *reinterpret_cast<float4*>(&Bs[bkr][bnc]) = val;
        }
        __syncthreads();
        #pragma unroll
        for (int kk = 0; kk < 8; kk++) {
            float ar[8], br[8];
            #pragma unroll
            for (int i = 0; i < 8; i++) ar[i] = As[kk][tr * 8 + i];
            #pragma unroll
            for (int j = 0; j < 8; j++) br[j] = Bs[kk][tc * 8 + j];
            #pragma unroll
            for (int i = 0; i < 8; i++)
                #pragma unroll
                for (int j = 0; j < 8; j++)
                    acc[i][j] += ar[i] * br[j];
        }
        __syncthreads();
    }
    #pragma unroll
    for (int i = 0; i < 8; i++) {
        int r = bm * 128 + tr * 8 + i;
        float* crow = C + (size_t)r * ldc + nBase;
        #pragma unroll
        for (int j = 0; j < 8; j++) {
            int col = tc * 8 + j;
            float v = acc[i][j] + bias[nLoc + col];
            if (EPI == 1) v = gelu_tanh(v);
            crow[col] = v;
        }
    }
}

// ---------------- K3: RoPE + unit-norm + manifold lift, layout shuffle ------
__global__ void __launch_bounds__(256) rope_k(const float* __restrict__ rc,
                                              const float* __restrict__ rs) {
    int gw = (blockIdx.x * 256 + threadIdx.x) >> 5;    // 0 .. 3*65536-1
    int lane = threadIdx.x & 31;
    int mat = gw / (NROW * HH);
    int rem = gw - mat * (NROW * HH);
    int row = rem >> 4;
    int h = rem & 15;
    int b = row >> 10, s = row & 1023;
    int bh = b * HH + h;
    const float* src = g_qkv + (size_t)row * 3072 + mat * 1024 + h * 64 + 2 * lane;
    float x0 = src[0], x1 = src[1];
    if (mat < 2) {
        float c = rc[s * 32 + lane], sn = rs[s * 32 + lane];
        float xr = x0 * c - x1 * sn;
        float xi = x0 * sn + x1 * c;
        float ss = xr * xr + xi * xi;
        #pragma unroll
        for (int o = 16; o; o >>= 1) ss += __shfl_xor_sync(0xffffffffu, ss, o);
        float inv = rsqrtf(ss + 1e-6f);
        float t = sqrtf(1.f + ss * inv * inv);
        float* dst = ((mat == 0) ? g_qT : g_kT) + (size_t)bh * HD1 * SS;
        dst[(size_t)(1 + 2 * lane) * SS + s] = xr * inv;
        dst[(size_t)(2 + 2 * lane) * SS + s] = xi * inv;
        if (lane == 0) dst[s] = (mat == 0) ? -t : t;   // q time-comp negated (sgn fold)
    } else {
        float ss = x0 * x0 + x1 * x1;
        #pragma unroll
        for (int o = 16; o; o >>= 1) ss += __shfl_xor_sync(0xffffffffu, ss, o);
        float* dst = g_v + (size_t)(bh * SS + s) * HD1;
        dst[1 + 2 * lane] = x0;
        dst[2 + 2 * lane] = x1;
        if (lane == 0) dst[0] = sqrtf(1.f + ss);
    }
}

// ---------------- K4: scores = (2/scale) * <q*sgn, k>  (NT batched GEMM) ----
__global__ void __launch_bounds__(256) scores_k(const float* __restrict__ scale_p) {
    int bh = blockIdx.z;
    const float* Qb = g_qT + (size_t)bh * HD1 * SS;
    const float* Kb = g_kT + (size_t)bh * HD1 * SS;
    float* Ab = g_att + (size_t)bh * SS * SS;
    __shared__ float As[8][128];
    __shared__ float Bs[8][128];
    int bm = blockIdx.y, bn = blockIdx.x;
    int tid = threadIdx.x;
    int kr = tid >> 5, mc = (tid & 31) * 4;
    float acc[8][8] = {};
    int tr = tid >> 4, tc = tid & 15;
    for (int k0 = 0; k0 < HD1; k0 += 8) {
        int kk = k0 + kr;
        float4 a4 = make_float4(0.f, 0.f, 0.f, 0.f);
        float4 b4 = make_float4(0.f, 0.f, 0.f, 0.f);
        if (kk < HD1) {
            a4 = *reinterpret_cast<const float4*>(Qb + (size_t)kk * SS + bm * 128 + mc);
            b4 = *reinterpret_cast<const float4*>(Kb + (size_t)kk * SS + bn * 128 + mc);
        }
        *reinterpret_cast<float4*>(&As[kr][mc]) = a4;
        *reinterpret_cast<float4*>(&Bs[kr][mc]) = b4;
        __syncthreads();
        #pragma unroll
        for (int kk2 = 0; kk2 < 8; kk2++) {
            float ar[8], br[8];
            #pragma unroll
            for (int i = 0; i < 8; i++) ar[i] = As[kk2][tr * 8 + i];
            #pragma unroll
            for (int j = 0; j < 8; j++) br[j] = Bs[kk2][tc * 8 + j];
            #pragma unroll
            for (int i = 0; i < 8; i++)
                #pragma unroll
                for (int j = 0; j < 8; j++)
                    acc[i][j] += ar[i] * br[j];
        }
        __syncthreads();
    }
    float scl = 2.0f / scale_p[0];
    #pragma unroll
    for (int i = 0; i < 8; i++) {
        float* crow = Ab + (size_t)(bm * 128 + tr * 8 + i) * SS + bn * 128;
        #pragma unroll
        for (int j = 0; j < 8; j++)
            crow[tc * 8 + j] = acc[i][j] * scl;
    }
}

// ---------------- K5: row softmax over 1024, in place -----------------------
__global__ void __launch_bounds__(256) softmax_k() {
    __shared__ float sm[8];
    size_t row = blockIdx.x;
    float4* p = reinterpret_cast<float4*>(g_att + row * SS) + threadIdx.x;
    float4 v = *p;
    float m = fmaxf(fmaxf(v.x, v.y), fmaxf(v.z, v.w));
    m = blockReduceMax(m, sm);
    v.x = expf(v.x - m); v.y = expf(v.y - m);
    v.z = expf(v.z - m); v.w = expf(v.w - m);
    float s = v.x + v.y + v.z + v.w;
    s = blockReduceSum(s, sm);
    float inv = 1.f / s;
    v.x *= inv; v.y *= inv; v.z *= inv; v.w *= inv;
    *p = v;
}

// ---------------- K6: m = P @ v, then Lorentz project, scatter to cat -------
__global__ void __launch_bounds__(256) pv_k() {
    __shared__ float Ps[64][65];
    __shared__ float Vs[64][66];
    __shared__ float invd[64];
    int st = blockIdx.x;        // 0..15 query tiles
    int bh = blockIdx.y;        // 0..63
    const float* Ab = g_att + (size_t)bh * SS * SS + (size_t)st * 64 * SS;
    const float* Vb = g_v + (size_t)bh * SS * HD1;
    int tid = threadIdx.x;
    int tr = tid >> 4, tc = tid & 15;
    float acc[4][5] = {};
    for (int kt = 0; kt < 16; kt++) {
        #pragma unroll
        for (int i = 0; i < 16; i++) {
            int lin = i * 256 + tid;
            int r = lin >> 6, c = lin & 63;
            Ps[r][c] = Ab[(size_t)r * SS + kt * 64 + c];
        }
        for (int lin = tid; lin < 64 * 65; lin += 256) {
            int t = lin / 65, e = lin - t * 65;
            Vs[t][e] = Vb[(size_t)(kt * 64 + t) * HD1 + e];
        }
        __syncthreads();
        #pragma unroll 8
        for (int kk = 0; kk < 64; kk++) {
            float p0[4], vv[5];
            #pragma unroll
            for (int i = 0; i < 4; i++) p0[i] = Ps[tr * 4 + i][kk];
            #pragma unroll
            for (int j = 0; j < 4; j++) vv[j] = Vs[kk][tc + j * 16];
            vv[4] = Vs[kk][64];
            #pragma unroll
            for (int i = 0; i < 4; i++)
                #pragma unroll
                for (int j = 0; j < 5; j++)
                    acc[i][j] += p0[i] * vv[j];
        }
        __syncthreads();
    }
    #pragma unroll
    for (int i = 0; i < 4; i++) {
        #pragma unroll
        for (int j = 0; j < 4; j++)
            Ps[tr * 4 + i][tc + j * 16] = acc[i][j];
        if (tc == 0) Ps[tr * 4 + i][64] = acc[i][4];
    }
    __syncthreads();
    if (tid < 64) {
        float m0 = Ps[tid][0];
        float ssum = 0.f;
        #pragma unroll
        for (int e = 1; e < 65; e++) ssum += Ps[tid][e] * Ps[tid][e];
        invd[tid] = rsqrtf(fmaxf(m0 * m0 - ssum, 1e-6f));
    }
    __syncthreads();
    int b = bh >> 4, h = bh & 15;
    for (int lin = tid; lin < 64 * 65; lin += 256) {
        int q = lin / 65, e = lin - q * 65;
        int s = st * 64 + q;
        g_cat[(size_t)(b * SS + s) * CATW + h * HD1 + e] = Ps[q][e] * invd[q];
    }
}

// ---------------- K8/K13: residual + to_manifold(ao) + project --------------
__global__ void __launch_bounds__(256) resproj_k(const float* __restrict__ Xext,
                                                 int useInternalX,
                                                 const float* __restrict__ wp,
                                                 float* __restrict__ Oext,
                                                 int outInternal) {
    __shared__ float sm[8];
    const float* X = useInternalX ? g_x2 : Xext;
    float* out = outInternal ? g_x2 : Oext;
    int row = blockIdx.x;
    const float* ao = g_tmp + (size_t)row * DD;
    const float* xr = X + (size_t)row * D1;
    float a[4], sa = 0.f;
    #pragma unroll
    for (int i = 0; i < 4; i++) {
        a[i] = ao[threadIdx.x + i * 256];
        sa += a[i] * a[i];
    }
    sa = blockReduceSum(sa, sm);
    float w = wp[0];
    float tao = sqrtf(1.f + sa);
    float z0 = xr[0] + w * tao;
    float z[4], sz = 0.f;
    #pragma unroll
    for (int i = 0; i < 4; i++) {
        z[i] = xr[1 + threadIdx.x + i * 256] + w * a[i];
        sz += z[i] * z[i];
    }
    sz = blockReduceSum(sz, sm);
    float dinv = rsqrtf(fmaxf(z0 * z0 - sz, 1e-6f));
    float* orow = out + (size_t)row * D1;
    if (threadIdx.x == 0) orow[0] = z0 * dinv;
    #pragma unroll
    for (int i = 0; i < 4; i++) orow[1 + threadIdx.x + i * 256] = z[i] * dinv;
}

// ---------------- K11: fill g_ff col0 with manifold time component ----------
__global__ void __launch_bounds__(256) ffT_k() {
    __shared__ float sm[8];
    int row = blockIdx.x;
    float* fr = g_ff + (size_t)row * FFP;
    float ss = 0.f;
    #pragma unroll
    for (int i = 0; i < 16; i++) {
        float v = fr[1 + threadIdx.x + i * 256];
        ss += v * v;
    }
    ss = blockReduceSum(ss, sm);
    if (threadIdx.x == 0) fr[0] = sqrtf(1.f + ss);
}

// ---------------- launcher ---------------------------------------------------
extern "C" void kernel_launch(void* const* d_in, const int* in_sizes, int n_in,
                              void* d_out, int out_size) {
    const float* x      = (const float*)d_in[0];
    const float* rc     = (const float*)d_in[1];
    const float* rs     = (const float*)d_in[2];
    const float* n1g    = (const float*)d_in[3];
    const float* n1b    = (const float*)d_in[4];
    const float* Wq     = (const float*)d_in[5];
    const float* bq     = (const float*)d_in[6];
    const float* Wk     = (const float*)d_in[7];
    const float* bk     = (const float*)d_in[8];
    const float* Wv     = (const float*)d_in[9];
    const float* bv     = (const float*)d_in[10];
    const float* ascale = (const float*)d_in[11];
    // d_in[12] = attn_bias: drops out of softmax (constant shift)
    const float* Wo     = (const float*)d_in[13];
    const float* bo     = (const float*)d_in[14];
    const float* wr1    = (const float*)d_in[15];
    const float* n2g    = (const float*)d_in[16];
    const float* n2b    = (const float*)d_in[17];
    const float* W1     = (const float*)d_in[18];
    const float* b1     = (const float*)d_in[19];
    const float* W2     = (const float*)d_in[20];
    const float* b2     = (const float*)d_in[21];
    const float* wr2    = (const float*)d_in[22];
    float* out = (float*)d_out;

    const int BIG = 1 << 30;

    // 1) layernorm 1 : x -> g_xn
    ln_kernel<<<NROW, 256>>>(x, 0, n1g, n1b);
    // 2) QKV projection: g_xn @ [Wq|Wk|Wv] -> g_qkv (N=3072)
    gemm_k<0><<<dim3(24, 32), 256>>>(0, 0, Wq, Wk, Wv, bq, bk, bv,
                                     1025, 1025, 64, 65600, 3072, 1024);
    // 3) RoPE + normalize + manifold lift + layout shuffle
    rope_k<<<24576, 256>>>(rc, rs);
    // 4) attention scores (bias/shift folded out by softmax invariance)
    scores_k<<<dim3(8, 8, 64), 256>>>(ascale);
    // 5) softmax over keys
    softmax_k<<<BHN * SS, 256>>>();
    // 6) P @ v + Lorentz project -> g_cat
    pv_k<<<dim3(16, 64), 256>>>();
    // 7) output projection: g_cat @ Wo -> g_tmp
    gemm_k<0><<<dim3(8, 32), 256>>>(1, 1, Wo, Wo, Wo, bo, bo, bo,
                                    1040, 1040, 1024, 64, 1024, BIG);
    // 8) x2 = project(x + w_res1 * to_manifold(attn_out))
    resproj_k<<<NROW, 256>>>(x, 0, wr1, nullptr, 1);
    // 9) layernorm 2 : g_x2 -> g_xn
    ln_kernel<<<NROW, 256>>>(nullptr, 1, n2g, n2b);
    // 10) FF up: g_xn @ W1, GELU -> g_ff cols 1..4096
    gemm_k<1><<<dim3(32, 32), 256>>>(0, 2, W1, W1, W1, b1, b1, b1,
                                     1025, 1025, 4096, 64, FFP, BIG);
    // 11) g_ff col0 = sqrt(1 + ||gelu||^2)
    ffT_k<<<NROW, 256>>>();
    // 12) FF down: g_ff @ W2 -> g_tmp
    gemm_k<0><<<dim3(8, 32), 256>>>(2, 1, W2, W2, W2, b2, b2, b2,
                                    4097, FFP, 1024, 64, 1024, BIG);
    // 13) out = project(x2 + w_res2 * to_manifold(mlp))
    resproj_k<<<NROW, 256>>>(nullptr, 1, wr2, out, 0);
}

// round 5
// speedup vs baseline: 2.0030x; 2.0030x over previous
#include <cuda_runtime.h>
#include <cuda_bf16.h>
#include <math.h>
#include <stdint.h>

#define SS 1024
#define DD 1024
#define HH 16
#define HDIM 64
#define FFDIM 4096
#define NROW 4096      // B*S
#define D1 1025
#define HD1 65
#define BHN 64         // B*H
#define CATW 1040      // H*(HD+1)
#define FFP 4104       // FF+1 padded to mult of 8

#define KP1 1088       // padded K for D+1-ish reductions (17*64)
#define KP2 4160       // padded K for FF+1 reduction (65*64)

// ---------------- scratch (device globals; no allocation allowed) ----------
__device__ float g_xn [NROW * D1];
__device__ float g_qkv[NROW * 3072];
__device__ float g_qT [BHN * HD1 * SS];
__device__ float g_kT [BHN * HD1 * SS];
__device__ float g_v  [BHN * SS * HD1];
__device__ float g_att[(size_t)BHN * SS * SS];
__device__ float g_cat[NROW * CATW];
__device__ float g_tmp[NROW * DD];
__device__ float g_x2 [NROW * D1];
__device__ float g_ff [NROW * FFP];

// bf16 split buffers
__device__ __nv_bfloat16 gA_hi[(size_t)NROW * KP2];
__device__ __nv_bfloat16 gA_lo[(size_t)NROW * KP2];
__device__ __nv_bfloat16 gB_hi[(size_t)4096 * KP1];   // also fits 1024*KP2
__device__ __nv_bfloat16 gB_lo[(size_t)4096 * KP1];

// ---------------- small helpers ----------------------------------------------
__device__ __forceinline__ uint32_t smem_u32(const void* p) {
    uint32_t a;
    asm("{ .reg .u64 t; cvta.to.shared.u64 t, %1; cvt.u32.u64 %0, t; }"
        : "=r"(a) : "l"(p));
    return a;
}
__device__ __forceinline__ void cp_async16(uint32_t s, const void* g) {
    asm volatile("{ .reg .u64 gp; cvta.to.global.u64 gp, %1; "
                 "cp.async.cg.shared.global [%0], [gp], 16; }"
                 :: "r"(s), "l"(g) : "memory");
}
__device__ __forceinline__ void cp_commit() {
    asm volatile("cp.async.commit_group;" ::: "memory");
}
template<int N>
__device__ __forceinline__ void cp_wait() {
    asm volatile("cp.async.wait_group %0;" :: "n"(N) : "memory");
}
__device__ __forceinline__ void ldsm_x4(uint32_t* r, uint32_t addr) {
    asm volatile("ldmatrix.sync.aligned.m8n8.x4.shared.b16 {%0,%1,%2,%3}, [%4];"
                 : "=r"(r[0]), "=r"(r[1]), "=r"(r[2]), "=r"(r[3]) : "r"(addr));
}
__device__ __forceinline__ void mma_bf16(float* c, const uint32_t* a, const uint32_t* b) {
    asm volatile("mma.sync.aligned.m16n8k16.row.col.f32.bf16.bf16.f32 "
                 "{%0,%1,%2,%3}, {%4,%5,%6,%7}, {%8,%9}, {%0,%1,%2,%3};"
                 : "+f"(c[0]), "+f"(c[1]), "+f"(c[2]), "+f"(c[3])
                 : "r"(a[0]), "r"(a[1]), "r"(a[2]), "r"(a[3]), "r"(b[0]), "r"(b[1]));
}

// ---------------- reductions --------------------------------------------------
__device__ __forceinline__ float blockReduceSum(float v, float* sm) {
    #pragma unroll
    for (int o = 16; o; o >>= 1) v += __shfl_xor_sync(0xffffffffu, v, o);
    int w = threadIdx.x >> 5;
    if ((threadIdx.x & 31) == 0) sm[w] = v;
    __syncthreads();
    if (threadIdx.x < 32) {
        float t = (threadIdx.x < 8) ? sm[threadIdx.x] : 0.f;
        #pragma unroll
        for (int o = 4; o; o >>= 1) t += __shfl_xor_sync(0xffffffffu, t, o);
        if (threadIdx.x == 0) sm[0] = t;
    }
    __syncthreads();
    float r = sm[0];
    __syncthreads();
    return r;
}
__device__ __forceinline__ float blockReduceMax(float v, float* sm) {
    #pragma unroll
    for (int o = 16; o; o >>= 1) v = fmaxf(v, __shfl_xor_sync(0xffffffffu, v, o));
    int w = threadIdx.x >> 5;
    if ((threadIdx.x & 31) == 0) sm[w] = v;
    __syncthreads();
    if (threadIdx.x < 32) {
        float t = (threadIdx.x < 8) ? sm[threadIdx.x] : -3.4e38f;
        #pragma unroll
        for (int o = 4; o; o >>= 1) t = fmaxf(t, __shfl_xor_sync(0xffffffffu, t, o));
        if (threadIdx.x == 0) sm[0] = t;
    }
    __syncthreads();
    float r = sm[0];
    __syncthreads();
    return r;
}
__device__ __forceinline__ float gelu_tanh(float x) {
    float x3 = x * x * x;
    float t = tanhf(0.7978845608028654f * (x + 0.044715f * x3));
    return 0.5f * x * (1.0f + t);
}

// ---------------- layernorm ---------------------------------------------------
__global__ void __launch_bounds__(256) ln_kernel(const float* __restrict__ Xext,
                                                 int useInternal,
                                                 const float* __restrict__ g,
                                                 const float* __restrict__ b) {
    __shared__ float sm[8];
    const float* X = useInternal ? g_x2 : Xext;
    int row = blockIdx.x;
    const float* xr = X + (size_t)row * D1 + 1;
    float v[4], s = 0.f, sq = 0.f;
    #pragma unroll
    for (int i = 0; i < 4; i++) {
        v[i] = xr[threadIdx.x + i * 256];
        s += v[i]; sq += v[i] * v[i];
    }
    s  = blockReduceSum(s,  sm);
    sq = blockReduceSum(sq, sm);
    float mu = s * (1.f / DD);
    float var = sq * (1.f / DD) - mu * mu;
    float rstd = rsqrtf(var + 1e-5f);
    float o[4], ss = 0.f;
    #pragma unroll
    for (int i = 0; i < 4; i++) {
        int c = threadIdx.x + i * 256;
        o[i] = (v[i] - mu) * rstd * g[c] + b[c];
        ss += o[i] * o[i];
    }
    ss = blockReduceSum(ss, sm);
    float* orow = g_xn + (size_t)row * D1;
    if (threadIdx.x == 0) orow[0] = sqrtf(1.f + ss);
    #pragma unroll
    for (int i = 0; i < 4; i++) orow[1 + threadIdx.x + i * 256] = o[i];
}

// ---------------- activation split (row-major, pad K) -------------------------
__global__ void __launch_bounds__(256) splitA_k(int sel, int lds, int Ks, int Kp) {
    int k = blockIdx.x * 256 + threadIdx.x;
    if (k >= Kp) return;
    int m = blockIdx.y;
    const float* src = (sel == 0) ? g_xn : (sel == 1 ? g_cat : g_ff);
    float v = (k < Ks) ? src[(size_t)m * lds + k] : 0.f;
    __nv_bfloat16 h = __float2bfloat16(v);
    __nv_bfloat16 l = __float2bfloat16(v - __bfloat162float(h));
    size_t o = (size_t)m * Kp + k;
    gA_hi[o] = h;
    gA_lo[o] = l;
}

// ---------------- weight transpose + split ------------------------------------
__global__ void __launch_bounds__(256) transW_k(const float* __restrict__ src,
                                                int dstRow0, int K, int Kp,
                                                int strideK, int headStride,
                                                int headWidth) {
    __shared__ float t[32][33];
    int tx = threadIdx.x & 31, ty = threadIdx.x >> 5;
    int k0 = blockIdx.x * 32, n0 = blockIdx.y * 32;
    #pragma unroll
    for (int i = 0; i < 4; i++) {
        int k = k0 + ty + i * 8;
        int n = n0 + tx;
        float v = 0.f;
        if (k < K)
            v = src[(size_t)(n / headWidth) * headStride + (size_t)k * strideK + (n % headWidth)];
        t[ty + i * 8][tx] = v;
    }
    __syncthreads();
    #pragma unroll
    for (int i = 0; i < 4; i++) {
        int n = n0 + ty + i * 8;
        int k = k0 + tx;
        float v = t[tx][ty + i * 8];
        __nv_bfloat16 h = __float2bfloat16(v);
        __nv_bfloat16 l = __float2bfloat16(v - __bfloat162float(h));
        size_t o = (size_t)(dstRow0 + n) * Kp + k;
        gB_hi[o] = h;
        gB_lo[o] = l;
    }
}

// ---------------- warp-MMA bf16-split GEMM (128x128 C tile) --------------------
// C[m][n] = sum_k A[m][k] * B[n][k]  (A = gA_hi+gA_lo rowmajor [M,Kp],
//                                     B = gB_hi+gB_lo rowmajor [N,Kp])
// 256 thr = 8 warps; warp (wm=wid&3, wn=wid>>2) owns 32x64; mma m16n8k16.
#define TCS 16384                 // bytes per tile buffer (128 rows x 128B)
#define STG 65536                 // stage = Ahi|Alo|Bhi|Blo
template<int EPI>
__global__ void __launch_bounds__(256, 1) mmagemm_k(
    int csel,
    const float* __restrict__ bias0, const float* __restrict__ bias1,
    const float* __restrict__ bias2,
    int Kp, int ldc, int nPerMat)
{
    extern __shared__ __align__(128) char dsm[];
    uint32_t sb0 = smem_u32(dsm);

    int tid = threadIdx.x;
    int wid = tid >> 5, lane = tid & 31;
    int wm = wid & 3, wn = wid >> 2;
    int m0 = blockIdx.y * 128, n0 = blockIdx.x * 128;

    // ---- load thread mapping: chunk = tid&7, rows tid>>3 + i*32
    int lchunk = tid & 7;
    int lrow = tid >> 3;

    const __nv_bfloat16* srcs[4] = {gA_hi, gA_lo, gB_hi, gB_lo};

    const int NC = Kp >> 6;

    // ---- fragment addresses (per lane, stage-relative)
    uint32_t aoff[2];
    {
        int khalf = lane >> 4;
        #pragma unroll
        for (int mi = 0; mi < 2; mi++) {
            int r = wm * 32 + mi * 16 + (lane & 15);
            aoff[mi] = (uint32_t)(r * 128) + (uint32_t)(((khalf) ^ (r & 7)) << 4);
        }
    }
    uint32_t boff[4];
    {
        int idx = lane >> 3;
        int khalf = idx & 1;
        #pragma unroll
        for (int jp = 0; jp < 4; jp++) {
            int r = wn * 64 + jp * 16 + (idx >> 1) * 8 + (lane & 7);
            boff[jp] = (uint32_t)(r * 128) + (uint32_t)((khalf ^ (r & 7)) << 4);
        }
    }

    float acc[2][8][4];
    #pragma unroll
    for (int i = 0; i < 2; i++)
        #pragma unroll
        for (int j = 0; j < 8; j++)
            #pragma unroll
            for (int q = 0; q < 4; q++) acc[i][j][q] = 0.f;

    // ---- stage loader
    auto load_stage = [&](int ic, int st) {
        size_t kbase = (size_t)ic * 64 + lchunk * 8;
        uint32_t sbase = sb0 + st * STG;
        #pragma unroll
        for (int t = 0; t < 4; t++) {          // Ahi, Alo, Bhi, Blo
            int rowBase = (t < 2) ? m0 : n0;
            const __nv_bfloat16* src = srcs[t];
            #pragma unroll
            for (int i = 0; i < 4; i++) {
                int r = lrow + i * 32;
                const void* gp = src + (size_t)(rowBase + r) * Kp + kbase;
                uint32_t sp = sbase + t * TCS + (uint32_t)(r * 128) +
                              (uint32_t)((lchunk ^ (r & 7)) << 4);
                cp_async16(sp, gp);
            }
        }
        cp_commit();
    };

    load_stage(0, 0);

    for (int ic = 0; ic < NC; ic++) {
        int st = ic & 1;
        if (ic + 1 < NC) {
            load_stage(ic + 1, st ^ 1);
            cp_wait<1>();
        } else {
            cp_wait<0>();
        }
        __syncthreads();

        uint32_t aH = sb0 + st * STG;
        uint32_t aL = aH + TCS;
        uint32_t bH = aH + 2 * TCS;
        uint32_t bL = aH + 3 * TCS;

        #pragma unroll
        for (int ks = 0; ks < 4; ks++) {
            // chunk index = 2*ks + khalf; khalf occupies bit0, 2*ks bits1-2 —
            // disjoint, so xor ≡ add and base ^ (2*ks<<4) addresses correctly.
            uint32_t kso = (uint32_t)(ks * 32);
            uint32_t Ah[2][4], Al[2][4];
            #pragma unroll
            for (int mi = 0; mi < 2; mi++) {
                ldsm_x4(Ah[mi], aH + (aoff[mi] ^ kso));
                ldsm_x4(Al[mi], aL + (aoff[mi] ^ kso));
            }
            uint32_t Bh[8][2], Bl[8][2];
            #pragma unroll
            for (int jp = 0; jp < 4; jp++) {
                uint32_t r4[4];
                ldsm_x4(r4, bH + (boff[jp] ^ kso));
                Bh[jp * 2][0] = r4[0]; Bh[jp * 2][1] = r4[1];
                Bh[jp * 2 + 1][0] = r4[2]; Bh[jp * 2 + 1][1] = r4[3];
                ldsm_x4(r4, bL + (boff[jp] ^ kso));
                Bl[jp * 2][0] = r4[0]; Bl[jp * 2][1] = r4[1];
                Bl[jp * 2 + 1][0] = r4[2]; Bl[jp * 2 + 1][1] = r4[3];
            }
            #pragma unroll
            for (int mi = 0; mi < 2; mi++)
                #pragma unroll
                for (int nj = 0; nj < 8; nj++) {
                    mma_bf16(acc[mi][nj], Ah[mi], Bh[nj]);
                    mma_bf16(acc[mi][nj], Ah[mi], Bl[nj]);
                    mma_bf16(acc[mi][nj], Al[mi], Bh[nj]);
                }
        }
        __syncthreads();
    }

    // ---- epilogue (scalar stores: C base may be odd-float-aligned, e.g. g_ff+1)
    float* C = (csel == 0) ? g_qkv : (csel == 1 ? g_tmp : (g_ff + 1));
    int selB = (n0 / nPerMat);
    const float* bias = (selB == 0) ? bias0 : (selB == 1 ? bias1 : bias2);
    int nL0 = n0 - selB * nPerMat;

    int g = lane >> 2, t = lane & 3;
    #pragma unroll
    for (int mi = 0; mi < 2; mi++) {
        int r0 = m0 + wm * 32 + mi * 16 + g;
        #pragma unroll
        for (int nj = 0; nj < 8; nj++) {
            int col = wn * 64 + nj * 8 + 2 * t;
            int cg = n0 + col;
            float b0 = bias[nL0 + col], b1 = bias[nL0 + col + 1];
            float v0 = acc[mi][nj][0] + b0;
            float v1 = acc[mi][nj][1] + b1;
            float v2 = acc[mi][nj][2] + b0;
            float v3 = acc[mi][nj][3] + b1;
            if (EPI == 1) {
                v0 = gelu_tanh(v0); v1 = gelu_tanh(v1);
                v2 = gelu_tanh(v2); v3 = gelu_tanh(v3);
            }
            float* p0 = C + (size_t)r0 * ldc + cg;
            float* p1 = C + (size_t)(r0 + 8) * ldc + cg;
            p0[0] = v0; p0[1] = v1;
            p1[0] = v2; p1[1] = v3;
        }
    }
}

// ---------------- RoPE + unit-norm + manifold lift ----------------------------
__global__ void __launch_bounds__(256) rope_k(const float* __restrict__ rc,
                                              const float* __restrict__ rs) {
    int gw = (blockIdx.x * 256 + threadIdx.x) >> 5;
    int lane = threadIdx.x & 31;
    int mat = gw / (NROW * HH);
    int rem = gw - mat * (NROW * HH);
    int row = rem >> 4;
    int h = rem & 15;
    int b = row >> 10, s = row & 1023;
    int bh = b * HH + h;
    const float* src = g_qkv + (size_t)row * 3072 + mat * 1024 + h * 64 + 2 * lane;
    float x0 = src[0], x1 = src[1];
    if (mat < 2) {
        float c = rc[s * 32 + lane], sn = rs[s * 32 + lane];
        float xr = x0 * c - x1 * sn;
        float xi = x0 * sn + x1 * c;
        float ss = xr * xr + xi * xi;
        #pragma unroll
        for (int o = 16; o; o >>= 1) ss += __shfl_xor_sync(0xffffffffu, ss, o);
        float inv = rsqrtf(ss + 1e-6f);
        float t = sqrtf(1.f + ss * inv * inv);
        float* dst = ((mat == 0) ? g_qT : g_kT) + (size_t)bh * HD1 * SS;
        dst[(size_t)(1 + 2 * lane) * SS + s] = xr * inv;
        dst[(size_t)(2 + 2 * lane) * SS + s] = xi * inv;
        if (lane == 0) dst[s] = (mat == 0) ? -t : t;
    } else {
        float ss = x0 * x0 + x1 * x1;
        #pragma unroll
        for (int o = 16; o; o >>= 1) ss += __shfl_xor_sync(0xffffffffu, ss, o);
        float* dst = g_v + (size_t)(bh * SS + s) * HD1;
        dst[1 + 2 * lane] = x0;
        dst[2 + 2 * lane] = x1;
        if (lane == 0) dst[0] = sqrtf(1.f + ss);
    }
}

// ---------------- scores ------------------------------------------------------
__global__ void __launch_bounds__(256) scores_k(const float* __restrict__ scale_p) {
    int bh = blockIdx.z;
    const float* Qb = g_qT + (size_t)bh * HD1 * SS;
    const float* Kb = g_kT + (size_t)bh * HD1 * SS;
    float* Ab = g_att + (size_t)bh * SS * SS;
    __shared__ float As[8][128];
    __shared__ float Bs[8][128];
    int bm = blockIdx.y, bn = blockIdx.x;
    int tid = threadIdx.x;
    int kr = tid >> 5, mc = (tid & 31) * 4;
    float acc[8][8] = {};
    int tr = tid >> 4, tc = tid & 15;
    for (int k0 = 0; k0 < HD1; k0 += 8) {
        int kk = k0 + kr;
        float4 a4 = make_float4(0.f, 0.f, 0.f, 0.f);
        float4 b4 = make_float4(0.f, 0.f, 0.f, 0.f);
        if (kk < HD1) {
            a4 = *reinterpret_cast<const float4*>(Qb + (size_t)kk * SS + bm * 128 + mc);
            b4 = *reinterpret_cast<const float4*>(Kb + (size_t)kk * SS + bn * 128 + mc);
        }
        *reinterpret_cast<float4*>(&As[kr][mc]) = a4;
        *reinterpret_cast<float4*>(&Bs[kr][mc]) = b4;
        __syncthreads();
        #pragma unroll
        for (int kk2 = 0; kk2 < 8; kk2++) {
            float ar[8], br[8];
            #pragma unroll
            for (int i = 0; i < 8; i++) ar[i] = As[kk2][tr * 8 + i];
            #pragma unroll
            for (int j = 0; j < 8; j++) br[j] = Bs[kk2][tc * 8 + j];
            #pragma unroll
            for (int i = 0; i < 8; i++)
                #pragma unroll
                for (int j = 0; j < 8; j++)
                    acc[i][j] += ar[i] * br[j];
        }
        __syncthreads();
    }
    float scl = 2.0f / scale_p[0];
    #pragma unroll
    for (int i = 0; i < 8; i++) {
        float* crow = Ab + (size_t)(bm * 128 + tr * 8 + i) * SS + bn * 128;
        #pragma unroll
        for (int j = 0; j < 8; j++)
            crow[tc * 8 + j] = acc[i][j] * scl;
    }
}

// ---------------- softmax -----------------------------------------------------
__global__ void __launch_bounds__(256) softmax_k() {
    __shared__ float sm[8];
    size_t row = blockIdx.x;
    float4* p = reinterpret_cast<float4*>(g_att + row * SS) + threadIdx.x;
    float4 v = *p;
    float m = fmaxf(fmaxf(v.x, v.y), fmaxf(v.z, v.w));
    m = blockReduceMax(m, sm);
    v.x = expf(v.x - m); v.y = expf(v.y - m);
    v.z = expf(v.z - m); v.w = expf(v.w - m);
    float s = v.x + v.y + v.z + v.w;
    s = blockReduceSum(s, sm);
    float inv = 1.f / s;
    v.x *= inv; v.y *= inv; v.z *= inv; v.w *= inv;
    *p = v;
}

// ---------------- PV + project ------------------------------------------------
__global__ void __launch_bounds__(256) pv_k() {
    __shared__ float Ps[64][65];
    __shared__ float Vs[64][66];
    __shared__ float invd[64];
    int st = blockIdx.x;
    int bh = blockIdx.y;
    const float* Ab = g_att + (size_t)bh * SS * SS + (size_t)st * 64 * SS;
    const float* Vb = g_v + (size_t)bh * SS * HD1;
    int tid = threadIdx.x;
    int tr = tid >> 4, tc = tid & 15;
    float acc[4][5] = {};
    for (int kt = 0; kt < 16; kt++) {
        #pragma unroll
        for (int i = 0; i < 16; i++) {
            int lin = i * 256 + tid;
            int r = lin >> 6, c = lin & 63;
            Ps[r][c] = Ab[(size_t)r * SS + kt * 64 + c];
        }
        for (int lin = tid; lin < 64 * 65; lin += 256) {
            int t = lin / 65, e = lin - t * 65;
            Vs[t][e] = Vb[(size_t)(kt * 64 + t) * HD1 + e];
        }
        __syncthreads();
        #pragma unroll 8
        for (int kk = 0; kk < 64; kk++) {
            float p0[4], vv[5];
            #pragma unroll
            for (int i = 0; i < 4; i++) p0[i] = Ps[tr * 4 + i][kk];
            #pragma unroll
            for (int j = 0; j < 4; j++) vv[j] = Vs[kk][tc + j * 16];
            vv[4] = Vs[kk][64];
            #pragma unroll
            for (int i = 0; i < 4; i++)
                #pragma unroll
                for (int j = 0; j < 5; j++)
                    acc[i][j] += p0[i] * vv[j];
        }
        __syncthreads();
    }
    #pragma unroll
    for (int i = 0; i < 4; i++) {
        #pragma unroll
        for (int j = 0; j < 4; j++)
            Ps[tr * 4 + i][tc + j * 16] = acc[i][j];
        if (tc == 0) Ps[tr * 4 + i][64] = acc[i][4];
    }
    __syncthreads();
    if (tid < 64) {
        float m0 = Ps[tid][0];
        float ssum = 0.f;
        #pragma unroll
        for (int e = 1; e < 65; e++) ssum += Ps[tid][e] * Ps[tid][e];
        invd[tid] = rsqrtf(fmaxf(m0 * m0 - ssum, 1e-6f));
    }
    __syncthreads();
    int b = bh >> 4, h = bh & 15;
    for (int lin = tid; lin < 64 * 65; lin += 256) {
        int q = lin / 65, e = lin - q * 65;
        int s = st * 64 + q;
        g_cat[(size_t)(b * SS + s) * CATW + h * HD1 + e] = Ps[q][e] * invd[q];
    }
}

// ---------------- residual + project ------------------------------------------
__global__ void __launch_bounds__(256) resproj_k(const float* __restrict__ Xext,
                                                 int useInternalX,
                                                 const float* __restrict__ wp,
                                                 float* __restrict__ Oext,
                                                 int outInternal) {
    __shared__ float sm[8];
    const float* X = useInternalX ? g_x2 : Xext;
    float* out = outInternal ? g_x2 : Oext;
    int row = blockIdx.x;
    const float* ao = g_tmp + (size_t)row * DD;
    const float* xr = X + (size_t)row * D1;
    float a[4], sa = 0.f;
    #pragma unroll
    for (int i = 0; i < 4; i++) {
        a[i] = ao[threadIdx.x + i * 256];
        sa += a[i] * a[i];
    }
    sa = blockReduceSum(sa, sm);
    float w = wp[0];
    float tao = sqrtf(1.f + sa);
    float z0 = xr[0] + w * tao;
    float z[4], sz = 0.f;
    #pragma unroll
    for (int i = 0; i < 4; i++) {
        z[i] = xr[1 + threadIdx.x + i * 256] + w * a[i];
        sz += z[i] * z[i];
    }
    sz = blockReduceSum(sz, sm);
    float dinv = rsqrtf(fmaxf(z0 * z0 - sz, 1e-6f));
    float* orow = out + (size_t)row * D1;
    if (threadIdx.x == 0) orow[0] = z0 * dinv;
    #pragma unroll
    for (int i = 0; i < 4; i++) orow[1 + threadIdx.x + i * 256] = z[i] * dinv;
}

// ---------------- ff time component -------------------------------------------
__global__ void __launch_bounds__(256) ffT_k() {
    __shared__ float sm[8];
    int row = blockIdx.x;
    float* fr = g_ff + (size_t)row * FFP;
    float ss = 0.f;
    #pragma unroll
    for (int i = 0; i < 16; i++) {
        float v = fr[1 + threadIdx.x + i * 256];
        ss += v * v;
    }
    ss = blockReduceSum(ss, sm);
    if (threadIdx.x == 0) fr[0] = sqrtf(1.f + ss);
}

// ---------------- launcher ----------------------------------------------------
extern "C" void kernel_launch(void* const* d_in, const int* in_sizes, int n_in,
                              void* d_out, int out_size) {
    const float* x      = (const float*)d_in[0];
    const float* rc     = (const float*)d_in[1];
    const float* rs     = (const float*)d_in[2];
    const float* n1g    = (const float*)d_in[3];
    const float* n1b    = (const float*)d_in[4];
    const float* Wq     = (const float*)d_in[5];
    const float* bq     = (const float*)d_in[6];
    const float* Wk     = (const float*)d_in[7];
    const float* bk     = (const float*)d_in[8];
    const float* Wv     = (const float*)d_in[9];
    const float* bv     = (const float*)d_in[10];
    const float* ascale = (const float*)d_in[11];
    const float* Wo     = (const float*)d_in[13];
    const float* bo     = (const float*)d_in[14];
    const float* wr1    = (const float*)d_in[15];
    const float* n2g    = (const float*)d_in[16];
    const float* n2b    = (const float*)d_in[17];
    const float* W1     = (const float*)d_in[18];
    const float* b1     = (const float*)d_in[19];
    const float* W2     = (const float*)d_in[20];
    const float* b2     = (const float*)d_in[21];
    const float* wr2    = (const float*)d_in[22];
    float* out = (float*)d_out;

    const int DSM = 2 * STG;   // 128 KB
    cudaFuncSetAttribute(mmagemm_k<0>, cudaFuncAttributeMaxDynamicSharedMemorySize, DSM);
    cudaFuncSetAttribute(mmagemm_k<1>, cudaFuncAttributeMaxDynamicSharedMemorySize, DSM);

    const int BIG = 1 << 30;

    // ---- attention half ----
    ln_kernel<<<NROW, 256>>>(x, 0, n1g, n1b);
    splitA_k<<<dim3((KP1 + 255) / 256, NROW), 256>>>(0, D1, D1, KP1);
    transW_k<<<dim3(KP1 / 32, 32), 256>>>(Wq, 0,    D1, KP1, HDIM, D1 * HDIM, HDIM);
    transW_k<<<dim3(KP1 / 32, 32), 256>>>(Wk, 1024, D1, KP1, HDIM, D1 * HDIM, HDIM);
    transW_k<<<dim3(KP1 / 32, 32), 256>>>(Wv, 2048, D1, KP1, HDIM, D1 * HDIM, HDIM);
    mmagemm_k<0><<<dim3(24, 32), 256, DSM>>>(0, bq, bk, bv, KP1, 3072, 1024);

    rope_k<<<24576, 256>>>(rc, rs);
    scores_k<<<dim3(8, 8, 64), 256>>>(ascale);
    softmax_k<<<BHN * SS, 256>>>();
    pv_k<<<dim3(16, 64), 256>>>();

    splitA_k<<<dim3((KP1 + 255) / 256, NROW), 256>>>(1, CATW, CATW, KP1);
    transW_k<<<dim3(KP1 / 32, 32), 256>>>(Wo, 0, CATW, KP1, DD, 0, DD);
    mmagemm_k<0><<<dim3(8, 32), 256, DSM>>>(1, bo, bo, bo, KP1, DD, BIG);
    resproj_k<<<NROW, 256>>>(x, 0, wr1, nullptr, 1);

    // ---- MLP half ----
    ln_kernel<<<NROW, 256>>>(nullptr, 1, n2g, n2b);
    splitA_k<<<dim3((KP1 + 255) / 256, NROW), 256>>>(0, D1, D1, KP1);
    transW_k<<<dim3(KP1 / 32, FFDIM / 32), 256>>>(W1, 0, D1, KP1, FFDIM, 0, FFDIM);
    mmagemm_k<1><<<dim3(32, 32), 256, DSM>>>(2, b1, b1, b1, KP1, FFP, BIG);
    ffT_k<<<NROW, 256>>>();

    splitA_k<<<dim3((KP2 + 255) / 256, NROW), 256>>>(2, FFP, FFDIM + 1, KP2);
    transW_k<<<dim3(KP2 / 32, 32), 256>>>(W2, 0, FFDIM + 1, KP2, DD, 0, DD);
    mmagemm_k<0><<<dim3(8, 32), 256, DSM>>>(1, b2, b2, b2, KP2, DD, BIG);
    resproj_k<<<NROW, 256>>>(nullptr, 1, wr2, out, 0);
}

// round 6
// speedup vs baseline: 2.4444x; 1.2204x over previous
#include <cuda_runtime.h>
#include <cuda_bf16.h>
#include <math.h>
#include <stdint.h>

#define SS 1024
#define DD 1024
#define HH 16
#define HDIM 64
#define FFDIM 4096
#define NROW 4096      // B*S
#define D1 1025
#define HD1 65
#define BHN 64         // B*H
#define CATW 1040      // H*(HD+1)
#define FFP 4104       // FF+1 padded to mult of 8
#define EP 80          // padded head-dim+1 (65 -> 80) for bf16 q/k

#define KP1 1088       // padded K for D+1-ish reductions (17*64)
#define KP2 4160       // padded K for FF+1 reduction (65*64)

// ---------------- scratch (device globals; no allocation allowed) ----------
__device__ float g_xn [NROW * D1];
__device__ float g_qkv[NROW * 3072];
__device__ float g_v  [BHN * SS * HD1];
__device__ float g_att[(size_t)BHN * SS * SS];
__device__ float g_cat[NROW * CATW];
__device__ float g_tmp[NROW * DD];
__device__ float g_x2 [NROW * D1];
__device__ float g_ff [NROW * FFP];

// bf16 split buffers (GEMM)
__device__ __align__(16) __nv_bfloat16 gA_hi[(size_t)NROW * KP2];
__device__ __align__(16) __nv_bfloat16 gA_lo[(size_t)NROW * KP2];
__device__ __align__(16) __nv_bfloat16 gB_hi[(size_t)4096 * KP1];
__device__ __align__(16) __nv_bfloat16 gB_lo[(size_t)4096 * KP1];

// bf16 split q/k for attention scores: [bh][s][EP], q time-comp pre-negated
__device__ __align__(16) __nv_bfloat16 g_qh[(size_t)BHN * SS * EP];
__device__ __align__(16) __nv_bfloat16 g_ql[(size_t)BHN * SS * EP];
__device__ __align__(16) __nv_bfloat16 g_kh[(size_t)BHN * SS * EP];
__device__ __align__(16) __nv_bfloat16 g_kl[(size_t)BHN * SS * EP];

// ---------------- small helpers ----------------------------------------------
__device__ __forceinline__ uint32_t smem_u32(const void* p) {
    uint32_t a;
    asm("{ .reg .u64 t; cvta.to.shared.u64 t, %1; cvt.u32.u64 %0, t; }"
        : "=r"(a) : "l"(p));
    return a;
}
__device__ __forceinline__ void cp_async16(uint32_t s, const void* g) {
    asm volatile("{ .reg .u64 gp; cvta.to.global.u64 gp, %1; "
                 "cp.async.cg.shared.global [%0], [gp], 16; }"
                 :: "r"(s), "l"(g) : "memory");
}
__device__ __forceinline__ void cp_commit() {
    asm volatile("cp.async.commit_group;" ::: "memory");
}
template<int N>
__device__ __forceinline__ void cp_wait() {
    asm volatile("cp.async.wait_group %0;" :: "n"(N) : "memory");
}
__device__ __forceinline__ void ldsm_x4(uint32_t* r, uint32_t addr) {
    asm volatile("ldmatrix.sync.aligned.m8n8.x4.shared.b16 {%0,%1,%2,%3}, [%4];"
                 : "=r"(r[0]), "=r"(r[1]), "=r"(r[2]), "=r"(r[3]) : "r"(addr));
}
__device__ __forceinline__ void mma_bf16(float* c, const uint32_t* a, const uint32_t* b) {
    asm volatile("mma.sync.aligned.m16n8k16.row.col.f32.bf16.bf16.f32 "
                 "{%0,%1,%2,%3}, {%4,%5,%6,%7}, {%8,%9}, {%0,%1,%2,%3};"
                 : "+f"(c[0]), "+f"(c[1]), "+f"(c[2]), "+f"(c[3])
                 : "r"(a[0]), "r"(a[1]), "r"(a[2]), "r"(a[3]), "r"(b[0]), "r"(b[1]));
}

// fast exp for softmax logits (range ~[-0.6, 0]); poly 2^f + exponent splice
__device__ __forceinline__ float exp_fast(float x) {
    float t = fmaxf(x * 1.4426950408889634f, -100.f);
    float r = t + 12582912.0f;              // round-to-nearest via mantissa
    int ri = __float_as_int(r);
    float fi = r - 12582912.0f;             // rint(t)
    float f = t - fi;                       // frac in [-0.5, 0.5]
    float p = 0.00133335581f;
    p = fmaf(p, f, 0.00961812911f);
    p = fmaf(p, f, 0.05550410866f);
    p = fmaf(p, f, 0.24022650696f);
    p = fmaf(p, f, 0.69314718056f);
    p = fmaf(p, f, 1.0f);
    float s = __int_as_float((ri + 127) << 23);
    return p * s;
}

// ---------------- reductions --------------------------------------------------
__device__ __forceinline__ float blockReduceSum(float v, float* sm) {
    #pragma unroll
    for (int o = 16; o; o >>= 1) v += __shfl_xor_sync(0xffffffffu, v, o);
    int w = threadIdx.x >> 5;
    if ((threadIdx.x & 31) == 0) sm[w] = v;
    __syncthreads();
    if (threadIdx.x < 32) {
        float t = (threadIdx.x < 8) ? sm[threadIdx.x] : 0.f;
        #pragma unroll
        for (int o = 4; o; o >>= 1) t += __shfl_xor_sync(0xffffffffu, t, o);
        if (threadIdx.x == 0) sm[0] = t;
    }
    __syncthreads();
    float r = sm[0];
    __syncthreads();
    return r;
}
__device__ __forceinline__ float gelu_tanh(float x) {
    float x3 = x * x * x;
    float t = tanhf(0.7978845608028654f * (x + 0.044715f * x3));
    return 0.5f * x * (1.0f + t);
}

// ---------------- layernorm ---------------------------------------------------
__global__ void __launch_bounds__(256) ln_kernel(const float* __restrict__ Xext,
                                                 int useInternal,
                                                 const float* __restrict__ g,
                                                 const float* __restrict__ b) {
    __shared__ float sm[8];
    const float* X = useInternal ? g_x2 : Xext;
    int row = blockIdx.x;
    const float* xr = X + (size_t)row * D1 + 1;
    float v[4], s = 0.f, sq = 0.f;
    #pragma unroll
    for (int i = 0; i < 4; i++) {
        v[i] = xr[threadIdx.x + i * 256];
        s += v[i]; sq += v[i] * v[i];
    }
    s  = blockReduceSum(s,  sm);
    sq = blockReduceSum(sq, sm);
    float mu = s * (1.f / DD);
    float var = sq * (1.f / DD) - mu * mu;
    float rstd = rsqrtf(var + 1e-5f);
    float o[4], ss = 0.f;
    #pragma unroll
    for (int i = 0; i < 4; i++) {
        int c = threadIdx.x + i * 256;
        o[i] = (v[i] - mu) * rstd * g[c] + b[c];
        ss += o[i] * o[i];
    }
    ss = blockReduceSum(ss, sm);
    float* orow = g_xn + (size_t)row * D1;
    if (threadIdx.x == 0) orow[0] = sqrtf(1.f + ss);
    #pragma unroll
    for (int i = 0; i < 4; i++) orow[1 + threadIdx.x + i * 256] = o[i];
}

// ---------------- activation split (row-major, pad K) -------------------------
__global__ void __launch_bounds__(256) splitA_k(int sel, int lds, int Ks, int Kp) {
    int k = blockIdx.x * 256 + threadIdx.x;
    if (k >= Kp) return;
    int m = blockIdx.y;
    const float* src = (sel == 0) ? g_xn : (sel == 1 ? g_cat : g_ff);
    float v = (k < Ks) ? src[(size_t)m * lds + k] : 0.f;
    __nv_bfloat16 h = __float2bfloat16(v);
    __nv_bfloat16 l = __float2bfloat16(v - __bfloat162float(h));
    size_t o = (size_t)m * Kp + k;
    gA_hi[o] = h;
    gA_lo[o] = l;
}

// ---------------- weight transpose + split ------------------------------------
__global__ void __launch_bounds__(256) transW_k(const float* __restrict__ src,
                                                int dstRow0, int K, int Kp,
                                                int strideK, int headStride,
                                                int headWidth) {
    __shared__ float t[32][33];
    int tx = threadIdx.x & 31, ty = threadIdx.x >> 5;
    int k0 = blockIdx.x * 32, n0 = blockIdx.y * 32;
    #pragma unroll
    for (int i = 0; i < 4; i++) {
        int k = k0 + ty + i * 8;
        int n = n0 + tx;
        float v = 0.f;
        if (k < K)
            v = src[(size_t)(n / headWidth) * headStride + (size_t)k * strideK + (n % headWidth)];
        t[ty + i * 8][tx] = v;
    }
    __syncthreads();
    #pragma unroll
    for (int i = 0; i < 4; i++) {
        int n = n0 + ty + i * 8;
        int k = k0 + tx;
        float v = t[tx][ty + i * 8];
        __nv_bfloat16 h = __float2bfloat16(v);
        __nv_bfloat16 l = __float2bfloat16(v - __bfloat162float(h));
        size_t o = (size_t)(dstRow0 + n) * Kp + k;
        gB_hi[o] = h;
        gB_lo[o] = l;
    }
}

// ---------------- warp-MMA bf16-split GEMM (128x128 C tile) --------------------
#define TCS 16384
#define STG 65536
template<int EPI>
__global__ void __launch_bounds__(256, 1) mmagemm_k(
    int csel,
    const float* __restrict__ bias0, const float* __restrict__ bias1,
    const float* __restrict__ bias2,
    int Kp, int ldc, int nPerMat)
{
    extern __shared__ __align__(128) char dsm[];
    uint32_t sb0 = smem_u32(dsm);

    int tid = threadIdx.x;
    int wid = tid >> 5, lane = tid & 31;
    int wm = wid & 3, wn = wid >> 2;
    int m0 = blockIdx.y * 128, n0 = blockIdx.x * 128;

    int lchunk = tid & 7;
    int lrow = tid >> 3;

    const __nv_bfloat16* srcs[4] = {gA_hi, gA_lo, gB_hi, gB_lo};
    const int NC = Kp >> 6;

    uint32_t aoff[2];
    {
        int khalf = lane >> 4;
        #pragma unroll
        for (int mi = 0; mi < 2; mi++) {
            int r = wm * 32 + mi * 16 + (lane & 15);
            aoff[mi] = (uint32_t)(r * 128) + (uint32_t)(((khalf) ^ (r & 7)) << 4);
        }
    }
    uint32_t boff[4];
    {
        int idx = lane >> 3;
        int khalf = idx & 1;
        #pragma unroll
        for (int jp = 0; jp < 4; jp++) {
            int r = wn * 64 + jp * 16 + (idx >> 1) * 8 + (lane & 7);
            boff[jp] = (uint32_t)(r * 128) + (uint32_t)((khalf ^ (r & 7)) << 4);
        }
    }

    float acc[2][8][4];
    #pragma unroll
    for (int i = 0; i < 2; i++)
        #pragma unroll
        for (int j = 0; j < 8; j++)
            #pragma unroll
            for (int q = 0; q < 4; q++) acc[i][j][q] = 0.f;

    auto load_stage = [&](int ic, int st) {
        size_t kbase = (size_t)ic * 64 + lchunk * 8;
        uint32_t sbase = sb0 + st * STG;
        #pragma unroll
        for (int t = 0; t < 4; t++) {
            int rowBase = (t < 2) ? m0 : n0;
            const __nv_bfloat16* src = srcs[t];
            #pragma unroll
            for (int i = 0; i < 4; i++) {
                int r = lrow + i * 32;
                const void* gp = src + (size_t)(rowBase + r) * Kp + kbase;
                uint32_t sp = sbase + t * TCS + (uint32_t)(r * 128) +
                              (uint32_t)((lchunk ^ (r & 7)) << 4);
                cp_async16(sp, gp);
            }
        }
        cp_commit();
    };

    load_stage(0, 0);

    for (int ic = 0; ic < NC; ic++) {
        int st = ic & 1;
        if (ic + 1 < NC) {
            load_stage(ic + 1, st ^ 1);
            cp_wait<1>();
        } else {
            cp_wait<0>();
        }
        __syncthreads();

        uint32_t aH = sb0 + st * STG;
        uint32_t aL = aH + TCS;
        uint32_t bH = aH + 2 * TCS;
        uint32_t bL = aH + 3 * TCS;

        #pragma unroll
        for (int ks = 0; ks < 4; ks++) {
            uint32_t kso = (uint32_t)(ks * 32);
            uint32_t Ah[2][4], Al[2][4];
            #pragma unroll
            for (int mi = 0; mi < 2; mi++) {
                ldsm_x4(Ah[mi], aH + (aoff[mi] ^ kso));
                ldsm_x4(Al[mi], aL + (aoff[mi] ^ kso));
            }
            uint32_t Bh[8][2], Bl[8][2];
            #pragma unroll
            for (int jp = 0; jp < 4; jp++) {
                uint32_t r4[4];
                ldsm_x4(r4, bH + (boff[jp] ^ kso));
                Bh[jp * 2][0] = r4[0]; Bh[jp * 2][1] = r4[1];
                Bh[jp * 2 + 1][0] = r4[2]; Bh[jp * 2 + 1][1] = r4[3];
                ldsm_x4(r4, bL + (boff[jp] ^ kso));
                Bl[jp * 2][0] = r4[0]; Bl[jp * 2][1] = r4[1];
                Bl[jp * 2 + 1][0] = r4[2]; Bl[jp * 2 + 1][1] = r4[3];
            }
            #pragma unroll
            for (int mi = 0; mi < 2; mi++)
                #pragma unroll
                for (int nj = 0; nj < 8; nj++) {
                    mma_bf16(acc[mi][nj], Ah[mi], Bh[nj]);
                    mma_bf16(acc[mi][nj], Ah[mi], Bl[nj]);
                    mma_bf16(acc[mi][nj], Al[mi], Bh[nj]);
                }
        }
        __syncthreads();
    }

    float* C = (csel == 0) ? g_qkv : (csel == 1 ? g_tmp : (g_ff + 1));
    int selB = (n0 / nPerMat);
    const float* bias = (selB == 0) ? bias0 : (selB == 1 ? bias1 : bias2);
    int nL0 = n0 - selB * nPerMat;

    int g = lane >> 2, t = lane & 3;
    #pragma unroll
    for (int mi = 0; mi < 2; mi++) {
        int r0 = m0 + wm * 32 + mi * 16 + g;
        #pragma unroll
        for (int nj = 0; nj < 8; nj++) {
            int col = wn * 64 + nj * 8 + 2 * t;
            int cg = n0 + col;
            float b0 = bias[nL0 + col], b1 = bias[nL0 + col + 1];
            float v0 = acc[mi][nj][0] + b0;
            float v1 = acc[mi][nj][1] + b1;
            float v2 = acc[mi][nj][2] + b0;
            float v3 = acc[mi][nj][3] + b1;
            if (EPI == 1) {
                v0 = gelu_tanh(v0); v1 = gelu_tanh(v1);
                v2 = gelu_tanh(v2); v3 = gelu_tanh(v3);
            }
            float* p0 = C + (size_t)r0 * ldc + cg;
            float* p1 = C + (size_t)(r0 + 8) * ldc + cg;
            p0[0] = v0; p0[1] = v1;
            p1[0] = v2; p1[1] = v3;
        }
    }
}

// ---------------- RoPE + unit-norm + manifold lift (q/k -> bf16 hi/lo) --------
__global__ void __launch_bounds__(256) rope_k(const float* __restrict__ rc,
                                              const float* __restrict__ rs) {
    int gw = (blockIdx.x * 256 + threadIdx.x) >> 5;
    int lane = threadIdx.x & 31;
    int mat = gw / (NROW * HH);
    int rem = gw - mat * (NROW * HH);
    int row = rem >> 4;
    int h = rem & 15;
    int b = row >> 10, s = row & 1023;
    int bh = b * HH + h;
    const float* src = g_qkv + (size_t)row * 3072 + mat * 1024 + h * 64 + 2 * lane;
    float x0 = src[0], x1 = src[1];
    if (mat < 2) {
        float c = rc[s * 32 + lane], sn = rs[s * 32 + lane];
        float xr = x0 * c - x1 * sn;
        float xi = x0 * sn + x1 * c;
        float ss = xr * xr + xi * xi;
        #pragma unroll
        for (int o = 16; o; o >>= 1) ss += __shfl_xor_sync(0xffffffffu, ss, o);
        float inv = rsqrtf(ss + 1e-6f);
        float t = sqrtf(1.f + ss * inv * inv);
        __nv_bfloat16* dh = ((mat == 0) ? g_qh : g_kh) + (size_t)(bh * SS + s) * EP;
        __nv_bfloat16* dl = ((mat == 0) ? g_ql : g_kl) + (size_t)(bh * SS + s) * EP;
        float e1 = xr * inv, e2 = xi * inv;
        __nv_bfloat16 h1 = __float2bfloat16(e1);
        __nv_bfloat16 h2 = __float2bfloat16(e2);
        dh[1 + 2 * lane] = h1; dl[1 + 2 * lane] = __float2bfloat16(e1 - __bfloat162float(h1));
        dh[2 + 2 * lane] = h2; dl[2 + 2 * lane] = __float2bfloat16(e2 - __bfloat162float(h2));
        if (lane == 0) {
            float e0 = (mat == 0) ? -t : t;     // sgn folded into q
            __nv_bfloat16 h0 = __float2bfloat16(e0);
            dh[0] = h0; dl[0] = __float2bfloat16(e0 - __bfloat162float(h0));
        }
        if (lane < 15) {                        // pad e = 65..79
            dh[65 + lane] = __float2bfloat16(0.f);
            dl[65 + lane] = __float2bfloat16(0.f);
        }
    } else {
        float ss = x0 * x0 + x1 * x1;
        #pragma unroll
        for (int o = 16; o; o >>= 1) ss += __shfl_xor_sync(0xffffffffu, ss, o);
        float* dst = g_v + (size_t)(bh * SS + s) * HD1;
        dst[1 + 2 * lane] = x0;
        dst[2 + 2 * lane] = x1;
        if (lane == 0) dst[0] = sqrtf(1.f + ss);
    }
}

// ---------------- scores via bf16-split MMA (128x128 tile, K=80) --------------
// att[bh][sq][sk] = (2/scale) * sum_e qh+ql [sq][e] * kh+kl [sk][e]
#define SROW 176                      // smem row stride bytes (11*16 -> bank rotate)
#define STILE (128 * SROW)            // 22528 bytes per tile
__global__ void __launch_bounds__(256) scores2_k(const float* __restrict__ scale_p) {
    extern __shared__ __align__(128) char dsm[];
    uint32_t sb = smem_u32(dsm);

    int tid = threadIdx.x;
    int wid = tid >> 5, lane = tid & 31;
    int wm = wid & 3, wn = wid >> 2;
    int bn = blockIdx.x, bm = blockIdx.y, bh = blockIdx.z;
    int m0 = bm * 128, n0 = bn * 128;

    // load 4 tiles: Qh, Ql, Kh, Kl (128 rows x 160B data, stride 176B)
    const __nv_bfloat16* gsrc[4] = {g_qh, g_ql, g_kh, g_kl};
    #pragma unroll
    for (int t = 0; t < 4; t++) {
        size_t rbase = (size_t)bh * SS + ((t < 2) ? m0 : n0);
        #pragma unroll
        for (int i = 0; i < 5; i++) {
            int id = i * 256 + tid;          // 0..1279
            int r = id / 10, c = id - r * 10;
            cp_async16(sb + t * STILE + r * SROW + c * 16,
                       gsrc[t] + (rbase + r) * EP + c * 8);
        }
    }
    cp_commit();
    cp_wait<0>();
    __syncthreads();

    uint32_t aoff[2];
    {
        int khalf = lane >> 4;
        #pragma unroll
        for (int mi = 0; mi < 2; mi++) {
            int r = wm * 32 + mi * 16 + (lane & 15);
            aoff[mi] = (uint32_t)(r * SROW + khalf * 16);
        }
    }
    uint32_t boff[4];
    {
        int idx = lane >> 3;
        int khalf = idx & 1;
        #pragma unroll
        for (int jp = 0; jp < 4; jp++) {
            int r = wn * 64 + jp * 16 + (idx >> 1) * 8 + (lane & 7);
            boff[jp] = (uint32_t)(r * SROW + khalf * 16);
        }
    }

    uint32_t qH = sb, qL = sb + STILE, kH = sb + 2 * STILE, kL = sb + 3 * STILE;

    float acc[2][8][4];
    #pragma unroll
    for (int i = 0; i < 2; i++)
        #pragma unroll
        for (int j = 0; j < 8; j++)
            #pragma unroll
            for (int q = 0; q < 4; q++) acc[i][j][q] = 0.f;

    #pragma unroll
    for (int ks = 0; ks < 5; ks++) {
        uint32_t co = (uint32_t)(ks * 32);
        uint32_t Ah[2][4], Al[2][4];
        #pragma unroll
        for (int mi = 0; mi < 2; mi++) {
            ldsm_x4(Ah[mi], qH + aoff[mi] + co);
            ldsm_x4(Al[mi], qL + aoff[mi] + co);
        }
        uint32_t Bh[8][2], Bl[8][2];
        #pragma unroll
        for (int jp = 0; jp < 4; jp++) {
            uint32_t r4[4];
            ldsm_x4(r4, kH + boff[jp] + co);
            Bh[jp * 2][0] = r4[0]; Bh[jp * 2][1] = r4[1];
            Bh[jp * 2 + 1][0] = r4[2]; Bh[jp * 2 + 1][1] = r4[3];
            ldsm_x4(r4, kL + boff[jp] + co);
            Bl[jp * 2][0] = r4[0]; Bl[jp * 2][1] = r4[1];
            Bl[jp * 2 + 1][0] = r4[2]; Bl[jp * 2 + 1][1] = r4[3];
        }
        #pragma unroll
        for (int mi = 0; mi < 2; mi++)
            #pragma unroll
            for (int nj = 0; nj < 8; nj++) {
                mma_bf16(acc[mi][nj], Ah[mi], Bh[nj]);
                mma_bf16(acc[mi][nj], Ah[mi], Bl[nj]);
                mma_bf16(acc[mi][nj], Al[mi], Bh[nj]);
            }
    }

    float scl = 2.0f / scale_p[0];
    float* Ab = g_att + (size_t)bh * SS * SS;
    int g = lane >> 2, t = lane & 3;
    #pragma unroll
    for (int mi = 0; mi < 2; mi++) {
        int r0 = m0 + wm * 32 + mi * 16 + g;
        #pragma unroll
        for (int nj = 0; nj < 8; nj++) {
            int cg = n0 + wn * 64 + nj * 8 + 2 * t;
            *reinterpret_cast<float2*>(Ab + (size_t)r0 * SS + cg) =
                make_float2(acc[mi][nj][0] * scl, acc[mi][nj][1] * scl);
            *reinterpret_cast<float2*>(Ab + (size_t)(r0 + 8) * SS + cg) =
                make_float2(acc[mi][nj][2] * scl, acc[mi][nj][3] * scl);
        }
    }
}

// ---------------- softmax (no max pass — logits bounded; poly exp) ------------
__global__ void __launch_bounds__(256) softmax_k() {
    __shared__ float sm[8];
    size_t row = blockIdx.x;
    float4* p = reinterpret_cast<float4*>(g_att + row * SS) + threadIdx.x;
    float4 v = *p;
    v.x = exp_fast(v.x); v.y = exp_fast(v.y);
    v.z = exp_fast(v.z); v.w = exp_fast(v.w);
    float s = v.x + v.y + v.z + v.w;
    s = blockReduceSum(s, sm);
    float inv = 1.f / s;
    v.x *= inv; v.y *= inv; v.z *= inv; v.w *= inv;
    *p = v;
}

// ---------------- PV + project ------------------------------------------------
__global__ void __launch_bounds__(256) pv_k() {
    __shared__ float Ps[64][65];
    __shared__ float Vs[64][66];
    __shared__ float invd[64];
    int st = blockIdx.x;
    int bh = blockIdx.y;
    const float* Ab = g_att + (size_t)bh * SS * SS + (size_t)st * 64 * SS;
    const float* Vb = g_v + (size_t)bh * SS * HD1;
    int tid = threadIdx.x;
    int tr = tid >> 4, tc = tid & 15;
    float acc[4][5] = {};
    for (int kt = 0; kt < 16; kt++) {
        #pragma unroll
        for (int i = 0; i < 16; i++) {
            int lin = i * 256 + tid;
            int r = lin >> 6, c = lin & 63;
            Ps[r][c] = Ab[(size_t)r * SS + kt * 64 + c];
        }
        for (int lin = tid; lin < 64 * 65; lin += 256) {
            int t = lin / 65, e = lin - t * 65;
            Vs[t][e] = Vb[(size_t)(kt * 64 + t) * HD1 + e];
        }
        __syncthreads();
        #pragma unroll 8
        for (int kk = 0; kk < 64; kk++) {
            float p0[4], vv[5];
            #pragma unroll
            for (int i = 0; i < 4; i++) p0[i] = Ps[tr * 4 + i][kk];
            #pragma unroll
            for (int j = 0; j < 4; j++) vv[j] = Vs[kk][tc + j * 16];
            vv[4] = Vs[kk][64];
            #pragma unroll
            for (int i = 0; i < 4; i++)
                #pragma unroll
                for (int j = 0; j < 5; j++)
                    acc[i][j] += p0[i] * vv[j];
        }
        __syncthreads();
    }
    #pragma unroll
    for (int i = 0; i < 4; i++) {
        #pragma unroll
        for (int j = 0; j < 4; j++)
            Ps[tr * 4 + i][tc + j * 16] = acc[i][j];
        if (tc == 0) Ps[tr * 4 + i][64] = acc[i][4];
    }
    __syncthreads();
    if (tid < 64) {
        float m0 = Ps[tid][0];
        float ssum = 0.f;
        #pragma unroll
        for (int e = 1; e < 65; e++) ssum += Ps[tid][e] * Ps[tid][e];
        invd[tid] = rsqrtf(fmaxf(m0 * m0 - ssum, 1e-6f));
    }
    __syncthreads();
    int b = bh >> 4, h = bh & 15;
    for (int lin = tid; lin < 64 * 65; lin += 256) {
        int q = lin / 65, e = lin - q * 65;
        int s = st * 64 + q;
        g_cat[(size_t)(b * SS + s) * CATW + h * HD1 + e] = Ps[q][e] * invd[q];
    }
}

// ---------------- residual + project ------------------------------------------
__global__ void __launch_bounds__(256) resproj_k(const float* __restrict__ Xext,
                                                 int useInternalX,
                                                 const float* __restrict__ wp,
                                                 float* __restrict__ Oext,
                                                 int outInternal) {
    __shared__ float sm[8];
    const float* X = useInternalX ? g_x2 : Xext;
    float* out = outInternal ? g_x2 : Oext;
    int row = blockIdx.x;
    const float* ao = g_tmp + (size_t)row * DD;
    const float* xr = X + (size_t)row * D1;
    float a[4], sa = 0.f;
    #pragma unroll
    for (int i = 0; i < 4; i++) {
        a[i] = ao[threadIdx.x + i * 256];
        sa += a[i] * a[i];
    }
    sa = blockReduceSum(sa, sm);
    float w = wp[0];
    float tao = sqrtf(1.f + sa);
    float z0 = xr[0] + w * tao;
    float z[4], sz = 0.f;
    #pragma unroll
    for (int i = 0; i < 4; i++) {
        z[i] = xr[1 + threadIdx.x + i * 256] + w * a[i];
        sz += z[i] * z[i];
    }
    sz = blockReduceSum(sz, sm);
    float dinv = rsqrtf(fmaxf(z0 * z0 - sz, 1e-6f));
    float* orow = out + (size_t)row * D1;
    if (threadIdx.x == 0) orow[0] = z0 * dinv;
    #pragma unroll
    for (int i = 0; i < 4; i++) orow[1 + threadIdx.x + i * 256] = z[i] * dinv;
}

// ---------------- ff time component -------------------------------------------
__global__ void __launch_bounds__(256) ffT_k() {
    __shared__ float sm[8];
    int row = blockIdx.x;
    float* fr = g_ff + (size_t)row * FFP;
    float ss = 0.f;
    #pragma unroll
    for (int i = 0; i < 16; i++) {
        float v = fr[1 + threadIdx.x + i * 256];
        ss += v * v;
    }
    ss = blockReduceSum(ss, sm);
    if (threadIdx.x == 0) fr[0] = sqrtf(1.f + ss);
}

// ---------------- launcher ----------------------------------------------------
extern "C" void kernel_launch(void* const* d_in, const int* in_sizes, int n_in,
                              void* d_out, int out_size) {
    const float* x      = (const float*)d_in[0];
    const float* rc     = (const float*)d_in[1];
    const float* rs     = (const float*)d_in[2];
    const float* n1g    = (const float*)d_in[3];
    const float* n1b    = (const float*)d_in[4];
    const float* Wq     = (const float*)d_in[5];
    const float* bq     = (const float*)d_in[6];
    const float* Wk     = (const float*)d_in[7];
    const float* bk     = (const float*)d_in[8];
    const float* Wv     = (const float*)d_in[9];
    const float* bv     = (const float*)d_in[10];
    const float* ascale = (const float*)d_in[11];
    const float* Wo     = (const float*)d_in[13];
    const float* bo     = (const float*)d_in[14];
    const float* wr1    = (const float*)d_in[15];
    const float* n2g    = (const float*)d_in[16];
    const float* n2b    = (const float*)d_in[17];
    const float* W1     = (const float*)d_in[18];
    const float* b1     = (const float*)d_in[19];
    const float* W2     = (const float*)d_in[20];
    const float* b2     = (const float*)d_in[21];
    const float* wr2    = (const float*)d_in[22];
    float* out = (float*)d_out;

    const int DSM = 2 * STG;          // 128 KB
    const int DSM_S = 4 * STILE;      // 90112 B
    cudaFuncSetAttribute(mmagemm_k<0>, cudaFuncAttributeMaxDynamicSharedMemorySize, DSM);
    cudaFuncSetAttribute(mmagemm_k<1>, cudaFuncAttributeMaxDynamicSharedMemorySize, DSM);
    cudaFuncSetAttribute(scores2_k, cudaFuncAttributeMaxDynamicSharedMemorySize, DSM_S);

    const int BIG = 1 << 30;

    // ---- attention half ----
    ln_kernel<<<NROW, 256>>>(x, 0, n1g, n1b);
    splitA_k<<<dim3((KP1 + 255) / 256, NROW), 256>>>(0, D1, D1, KP1);
    transW_k<<<dim3(KP1 / 32, 32), 256>>>(Wq, 0,    D1, KP1, HDIM, D1 * HDIM, HDIM);
    transW_k<<<dim3(KP1 / 32, 32), 256>>>(Wk, 1024, D1, KP1, HDIM, D1 * HDIM, HDIM);
    transW_k<<<dim3(KP1 / 32, 32), 256>>>(Wv, 2048, D1, KP1, HDIM, D1 * HDIM, HDIM);
    mmagemm_k<0><<<dim3(24, 32), 256, DSM>>>(0, bq, bk, bv, KP1, 3072, 1024);

    rope_k<<<24576, 256>>>(rc, rs);
    scores2_k<<<dim3(8, 8, 64), 256, DSM_S>>>(ascale);
    softmax_k<<<BHN * SS, 256>>>();
    pv_k<<<dim3(16, 64), 256>>>();

    splitA_k<<<dim3((KP1 + 255) / 256, NROW), 256>>>(1, CATW, CATW, KP1);
    transW_k<<<dim3(KP1 / 32, 32), 256>>>(Wo, 0, CATW, KP1, DD, 0, DD);
    mmagemm_k<0><<<dim3(8, 32), 256, DSM>>>(1, bo, bo, bo, KP1, DD, BIG);
    resproj_k<<<NROW, 256>>>(x, 0, wr1, nullptr, 1);

    // ---- MLP half ----
    ln_kernel<<<NROW, 256>>>(nullptr, 1, n2g, n2b);
    splitA_k<<<dim3((KP1 + 255) / 256, NROW), 256>>>(0, D1, D1, KP1);
    transW_k<<<dim3(KP1 / 32, FFDIM / 32), 256>>>(W1, 0, D1, KP1, FFDIM, 0, FFDIM);
    mmagemm_k<1><<<dim3(32, 32), 256, DSM>>>(2, b1, b1, b1, KP1, FFP, BIG);
    ffT_k<<<NROW, 256>>>();

    splitA_k<<<dim3((KP2 + 255) / 256, NROW), 256>>>(2, FFP, FFDIM + 1, KP2);
    transW_k<<<dim3(KP2 / 32, 32), 256>>>(W2, 0, FFDIM + 1, KP2, DD, 0, DD);
    mmagemm_k<0><<<dim3(8, 32), 256, DSM>>>(1, b2, b2, b2, KP2, DD, BIG);
    resproj_k<<<NROW, 256>>>(nullptr, 1, wr2, out, 0);
}

// round 7
// speedup vs baseline: 2.5899x; 1.0595x over previous
#include <cuda_runtime.h>
#include <cuda_bf16.h>
#include <math.h>
#include <stdint.h>

#define SS 1024
#define DD 1024
#define HH 16
#define HDIM 64
#define FFDIM 4096
#define NROW 4096      // B*S
#define D1 1025
#define HD1 65
#define BHN 64         // B*H
#define CATW 1040      // H*(HD+1)
#define FFP 4104       // FF+1 padded to mult of 8
#define EP 80          // padded head-dim+1 (65 -> 80) for bf16 q/k

#define KP1 1088       // padded K for D+1-ish reductions (17*64)
#define KP2 4160       // padded K for FF+1 reduction (65*64)

// ---------------- scratch (device globals; no allocation allowed) ----------
__device__ float g_xn [NROW * D1];
__device__ float g_qkv[NROW * 3072];
__device__ float g_v  [BHN * SS * HD1];
__device__ float g_att[(size_t)BHN * SS * SS];
__device__ float g_cat[NROW * CATW];
__device__ float g_tmp[NROW * DD];
__device__ float g_x2 [NROW * D1];
__device__ float g_ff [NROW * FFP];

// bf16 split buffers (GEMM)
__device__ __align__(16) __nv_bfloat16 gA_hi[(size_t)NROW * KP2];
__device__ __align__(16) __nv_bfloat16 gA_lo[(size_t)NROW * KP2];
__device__ __align__(16) __nv_bfloat16 gB_hi[(size_t)4096 * KP1];
__device__ __align__(16) __nv_bfloat16 gB_lo[(size_t)4096 * KP1];

// bf16 split q/k for attention scores: [bh][s][EP], q time-comp pre-negated
__device__ __align__(16) __nv_bfloat16 g_qh[(size_t)BHN * SS * EP];
__device__ __align__(16) __nv_bfloat16 g_ql[(size_t)BHN * SS * EP];
__device__ __align__(16) __nv_bfloat16 g_kh[(size_t)BHN * SS * EP];
__device__ __align__(16) __nv_bfloat16 g_kl[(size_t)BHN * SS * EP];

// ---------------- small helpers ----------------------------------------------
__device__ __forceinline__ uint32_t smem_u32(const void* p) {
    uint32_t a;
    asm("{ .reg .u64 t; cvta.to.shared.u64 t, %1; cvt.u32.u64 %0, t; }"
        : "=r"(a) : "l"(p));
    return a;
}
__device__ __forceinline__ void cp_async16(uint32_t s, const void* g) {
    asm volatile("{ .reg .u64 gp; cvta.to.global.u64 gp, %1; "
                 "cp.async.cg.shared.global [%0], [gp], 16; }"
                 :: "r"(s), "l"(g) : "memory");
}
__device__ __forceinline__ void cp_commit() {
    asm volatile("cp.async.commit_group;" ::: "memory");
}
template<int N>
__device__ __forceinline__ void cp_wait() {
    asm volatile("cp.async.wait_group %0;" :: "n"(N) : "memory");
}
__device__ __forceinline__ void ldsm_x4(uint32_t* r, uint32_t addr) {
    asm volatile("ldmatrix.sync.aligned.m8n8.x4.shared.b16 {%0,%1,%2,%3}, [%4];"
                 : "=r"(r[0]), "=r"(r[1]), "=r"(r[2]), "=r"(r[3]) : "r"(addr));
}
__device__ __forceinline__ void mma_bf16(float* c, const uint32_t* a, const uint32_t* b) {
    asm volatile("mma.sync.aligned.m16n8k16.row.col.f32.bf16.bf16.f32 "
                 "{%0,%1,%2,%3}, {%4,%5,%6,%7}, {%8,%9}, {%0,%1,%2,%3};"
                 : "+f"(c[0]), "+f"(c[1]), "+f"(c[2]), "+f"(c[3])
                 : "r"(a[0]), "r"(a[1]), "r"(a[2]), "r"(a[3]), "r"(b[0]), "r"(b[1]));
}

// fast exp for softmax logits (range ~[-0.6, 0]); poly 2^f + exponent splice
__device__ __forceinline__ float exp_fast(float x) {
    float t = fmaxf(x * 1.4426950408889634f, -100.f);
    float r = t + 12582912.0f;              // round-to-nearest via mantissa
    int ri = __float_as_int(r);
    float fi = r - 12582912.0f;             // rint(t)
    float f = t - fi;                       // frac in [-0.5, 0.5]
    float p = 0.00133335581f;
    p = fmaf(p, f, 0.00961812911f);
    p = fmaf(p, f, 0.05550410866f);
    p = fmaf(p, f, 0.24022650696f);
    p = fmaf(p, f, 0.69314718056f);
    p = fmaf(p, f, 1.0f);
    float s = __int_as_float((ri + 127) << 23);
    return p * s;
}

// ---------------- reductions --------------------------------------------------
__device__ __forceinline__ float blockReduceSum(float v, float* sm) {
    #pragma unroll
    for (int o = 16; o; o >>= 1) v += __shfl_xor_sync(0xffffffffu, v, o);
    int w = threadIdx.x >> 5;
    if ((threadIdx.x & 31) == 0) sm[w] = v;
    __syncthreads();
    if (threadIdx.x < 32) {
        float t = (threadIdx.x < 8) ? sm[threadIdx.x] : 0.f;
        #pragma unroll
        for (int o = 4; o; o >>= 1) t += __shfl_xor_sync(0xffffffffu, t, o);
        if (threadIdx.x == 0) sm[0] = t;
    }
    __syncthreads();
    float r = sm[0];
    __syncthreads();
    return r;
}
__device__ __forceinline__ float gelu_tanh(float x) {
    float x3 = x * x * x;
    float t = tanhf(0.7978845608028654f * (x + 0.044715f * x3));
    return 0.5f * x * (1.0f + t);
}

// ---------------- layernorm ---------------------------------------------------
__global__ void __launch_bounds__(256) ln_kernel(const float* __restrict__ Xext,
                                                 int useInternal,
                                                 const float* __restrict__ g,
                                                 const float* __restrict__ b) {
    __shared__ float sm[8];
    const float* X = useInternal ? g_x2 : Xext;
    int row = blockIdx.x;
    const float* xr = X + (size_t)row * D1 + 1;
    float v[4], s = 0.f, sq = 0.f;
    #pragma unroll
    for (int i = 0; i < 4; i++) {
        v[i] = xr[threadIdx.x + i * 256];
        s += v[i]; sq += v[i] * v[i];
    }
    s  = blockReduceSum(s,  sm);
    sq = blockReduceSum(sq, sm);
    float mu = s * (1.f / DD);
    float var = sq * (1.f / DD) - mu * mu;
    float rstd = rsqrtf(var + 1e-5f);
    float o[4], ss = 0.f;
    #pragma unroll
    for (int i = 0; i < 4; i++) {
        int c = threadIdx.x + i * 256;
        o[i] = (v[i] - mu) * rstd * g[c] + b[c];
        ss += o[i] * o[i];
    }
    ss = blockReduceSum(ss, sm);
    float* orow = g_xn + (size_t)row * D1;
    if (threadIdx.x == 0) orow[0] = sqrtf(1.f + ss);
    #pragma unroll
    for (int i = 0; i < 4; i++) orow[1 + threadIdx.x + i * 256] = o[i];
}

// ---------------- activation split (row-major, pad K) -------------------------
__global__ void __launch_bounds__(256) splitA_k(int sel, int lds, int Ks, int Kp) {
    int k = blockIdx.x * 256 + threadIdx.x;
    if (k >= Kp) return;
    int m = blockIdx.y;
    const float* src = (sel == 0) ? g_xn : (sel == 1 ? g_cat : g_ff);
    float v = (k < Ks) ? src[(size_t)m * lds + k] : 0.f;
    __nv_bfloat16 h = __float2bfloat16(v);
    __nv_bfloat16 l = __float2bfloat16(v - __bfloat162float(h));
    size_t o = (size_t)m * Kp + k;
    gA_hi[o] = h;
    gA_lo[o] = l;
}

// ---------------- weight transpose + split ------------------------------------
__global__ void __launch_bounds__(256) transW_k(const float* __restrict__ src,
                                                int dstRow0, int K, int Kp,
                                                int strideK, int headStride,
                                                int headWidth) {
    __shared__ float t[32][33];
    int tx = threadIdx.x & 31, ty = threadIdx.x >> 5;
    int k0 = blockIdx.x * 32, n0 = blockIdx.y * 32;
    #pragma unroll
    for (int i = 0; i < 4; i++) {
        int k = k0 + ty + i * 8;
        int n = n0 + tx;
        float v = 0.f;
        if (k < K)
            v = src[(size_t)(n / headWidth) * headStride + (size_t)k * strideK + (n % headWidth)];
        t[ty + i * 8][tx] = v;
    }
    __syncthreads();
    #pragma unroll
    for (int i = 0; i < 4; i++) {
        int n = n0 + ty + i * 8;
        int k = k0 + tx;
        float v = t[tx][ty + i * 8];
        __nv_bfloat16 h = __float2bfloat16(v);
        __nv_bfloat16 l = __float2bfloat16(v - __bfloat162float(h));
        size_t o = (size_t)(dstRow0 + n) * Kp + k;
        gB_hi[o] = h;
        gB_lo[o] = l;
    }
}

// ---------------- warp-MMA bf16-split GEMM (128x128 C tile, 3-stage) ----------
#define TCS 16384
#define STG 65536
template<int EPI>
__global__ void __launch_bounds__(256, 1) mmagemm_k(
    int csel,
    const float* __restrict__ bias0, const float* __restrict__ bias1,
    const float* __restrict__ bias2,
    int Kp, int ldc, int nPerMat)
{
    extern __shared__ __align__(128) char dsm[];
    uint32_t sb0 = smem_u32(dsm);

    int tid = threadIdx.x;
    int wid = tid >> 5, lane = tid & 31;
    int wm = wid & 3, wn = wid >> 2;
    int m0 = blockIdx.y * 128, n0 = blockIdx.x * 128;

    int lchunk = tid & 7;
    int lrow = tid >> 3;

    const __nv_bfloat16* srcs[4] = {gA_hi, gA_lo, gB_hi, gB_lo};
    const int NC = Kp >> 6;

    uint32_t aoff[2];
    {
        int khalf = lane >> 4;
        #pragma unroll
        for (int mi = 0; mi < 2; mi++) {
            int r = wm * 32 + mi * 16 + (lane & 15);
            aoff[mi] = (uint32_t)(r * 128) + (uint32_t)(((khalf) ^ (r & 7)) << 4);
        }
    }
    uint32_t boff[4];
    {
        int idx = lane >> 3;
        int khalf = idx & 1;
        #pragma unroll
        for (int jp = 0; jp < 4; jp++) {
            int r = wn * 64 + jp * 16 + (idx >> 1) * 8 + (lane & 7);
            boff[jp] = (uint32_t)(r * 128) + (uint32_t)((khalf ^ (r & 7)) << 4);
        }
    }

    float acc[2][8][4];
    #pragma unroll
    for (int i = 0; i < 2; i++)
        #pragma unroll
        for (int j = 0; j < 8; j++)
            #pragma unroll
            for (int q = 0; q < 4; q++) acc[i][j][q] = 0.f;

    auto load_stage = [&](int ic, int st) {
        size_t kbase = (size_t)ic * 64 + lchunk * 8;
        uint32_t sbase = sb0 + st * STG;
        #pragma unroll
        for (int t = 0; t < 4; t++) {
            int rowBase = (t < 2) ? m0 : n0;
            const __nv_bfloat16* src = srcs[t];
            #pragma unroll
            for (int i = 0; i < 4; i++) {
                int r = lrow + i * 32;
                const void* gp = src + (size_t)(rowBase + r) * Kp + kbase;
                uint32_t sp = sbase + t * TCS + (uint32_t)(r * 128) +
                              (uint32_t)((lchunk ^ (r & 7)) << 4);
                cp_async16(sp, gp);
            }
        }
        cp_commit();
    };

    load_stage(0, 0);
    if (NC > 1) load_stage(1, 1);

    int st = 0;
    for (int ic = 0; ic < NC; ic++) {
        if (ic + 2 < NC) {
            int st2 = (st + 2) % 3;
            load_stage(ic + 2, st2);
            cp_wait<2>();
        } else if (ic + 1 < NC) {
            cp_wait<1>();
        } else {
            cp_wait<0>();
        }
        __syncthreads();

        uint32_t aH = sb0 + st * STG;
        uint32_t aL = aH + TCS;
        uint32_t bH = aH + 2 * TCS;
        uint32_t bL = aH + 3 * TCS;

        #pragma unroll
        for (int ks = 0; ks < 4; ks++) {
            uint32_t kso = (uint32_t)(ks * 32);
            uint32_t Ah[2][4], Al[2][4];
            #pragma unroll
            for (int mi = 0; mi < 2; mi++) {
                ldsm_x4(Ah[mi], aH + (aoff[mi] ^ kso));
                ldsm_x4(Al[mi], aL + (aoff[mi] ^ kso));
            }
            uint32_t Bh[8][2], Bl[8][2];
            #pragma unroll
            for (int jp = 0; jp < 4; jp++) {
                uint32_t r4[4];
                ldsm_x4(r4, bH + (boff[jp] ^ kso));
                Bh[jp * 2][0] = r4[0]; Bh[jp * 2][1] = r4[1];
                Bh[jp * 2 + 1][0] = r4[2]; Bh[jp * 2 + 1][1] = r4[3];
                ldsm_x4(r4, bL + (boff[jp] ^ kso));
                Bl[jp * 2][0] = r4[0]; Bl[jp * 2][1] = r4[1];
                Bl[jp * 2 + 1][0] = r4[2]; Bl[jp * 2 + 1][1] = r4[3];
            }
            #pragma unroll
            for (int mi = 0; mi < 2; mi++)
                #pragma unroll
                for (int nj = 0; nj < 8; nj++) {
                    mma_bf16(acc[mi][nj], Ah[mi], Bh[nj]);
                    mma_bf16(acc[mi][nj], Ah[mi], Bl[nj]);
                    mma_bf16(acc[mi][nj], Al[mi], Bh[nj]);
                }
        }
        __syncthreads();
        st = (st + 1) % 3;
    }

    float* C = (csel == 0) ? g_qkv : (csel == 1 ? g_tmp : (g_ff + 1));
    int selB = (n0 / nPerMat);
    const float* bias = (selB == 0) ? bias0 : (selB == 1 ? bias1 : bias2);
    int nL0 = n0 - selB * nPerMat;

    int g = lane >> 2, t = lane & 3;
    #pragma unroll
    for (int mi = 0; mi < 2; mi++) {
        int r0 = m0 + wm * 32 + mi * 16 + g;
        #pragma unroll
        for (int nj = 0; nj < 8; nj++) {
            int col = wn * 64 + nj * 8 + 2 * t;
            int cg = n0 + col;
            float b0 = bias[nL0 + col], b1 = bias[nL0 + col + 1];
            float v0 = acc[mi][nj][0] + b0;
            float v1 = acc[mi][nj][1] + b1;
            float v2 = acc[mi][nj][2] + b0;
            float v3 = acc[mi][nj][3] + b1;
            if (EPI == 1) {
                v0 = gelu_tanh(v0); v1 = gelu_tanh(v1);
                v2 = gelu_tanh(v2); v3 = gelu_tanh(v3);
            }
            float* p0 = C + (size_t)r0 * ldc + cg;
            float* p1 = C + (size_t)(r0 + 8) * ldc + cg;
            p0[0] = v0; p0[1] = v1;
            p1[0] = v2; p1[1] = v3;
        }
    }
}

// ---------------- RoPE + unit-norm + manifold lift (q/k -> bf16 hi/lo) --------
__global__ void __launch_bounds__(256) rope_k(const float* __restrict__ rc,
                                              const float* __restrict__ rs) {
    int gw = (blockIdx.x * 256 + threadIdx.x) >> 5;
    int lane = threadIdx.x & 31;
    int mat = gw / (NROW * HH);
    int rem = gw - mat * (NROW * HH);
    int row = rem >> 4;
    int h = rem & 15;
    int b = row >> 10, s = row & 1023;
    int bh = b * HH + h;
    const float* src = g_qkv + (size_t)row * 3072 + mat * 1024 + h * 64 + 2 * lane;
    float x0 = src[0], x1 = src[1];
    if (mat < 2) {
        float c = rc[s * 32 + lane], sn = rs[s * 32 + lane];
        float xr = x0 * c - x1 * sn;
        float xi = x0 * sn + x1 * c;
        float ss = xr * xr + xi * xi;
        #pragma unroll
        for (int o = 16; o; o >>= 1) ss += __shfl_xor_sync(0xffffffffu, ss, o);
        float inv = rsqrtf(ss + 1e-6f);
        float t = sqrtf(1.f + ss * inv * inv);
        __nv_bfloat16* dh = ((mat == 0) ? g_qh : g_kh) + (size_t)(bh * SS + s) * EP;
        __nv_bfloat16* dl = ((mat == 0) ? g_ql : g_kl) + (size_t)(bh * SS + s) * EP;
        float e1 = xr * inv, e2 = xi * inv;
        __nv_bfloat16 h1 = __float2bfloat16(e1);
        __nv_bfloat16 h2 = __float2bfloat16(e2);
        dh[1 + 2 * lane] = h1; dl[1 + 2 * lane] = __float2bfloat16(e1 - __bfloat162float(h1));
        dh[2 + 2 * lane] = h2; dl[2 + 2 * lane] = __float2bfloat16(e2 - __bfloat162float(h2));
        if (lane == 0) {
            float e0 = (mat == 0) ? -t : t;     // sgn folded into q
            __nv_bfloat16 h0 = __float2bfloat16(e0);
            dh[0] = h0; dl[0] = __float2bfloat16(e0 - __bfloat162float(h0));
        }
        if (lane < 15) {                        // pad e = 65..79
            dh[65 + lane] = __float2bfloat16(0.f);
            dl[65 + lane] = __float2bfloat16(0.f);
        }
    } else {
        float ss = x0 * x0 + x1 * x1;
        #pragma unroll
        for (int o = 16; o; o >>= 1) ss += __shfl_xor_sync(0xffffffffu, ss, o);
        float* dst = g_v + (size_t)(bh * SS + s) * HD1;
        dst[1 + 2 * lane] = x0;
        dst[2 + 2 * lane] = x1;
        if (lane == 0) dst[0] = sqrtf(1.f + ss);
    }
}

// ---------------- scores via bf16-split MMA, fused exp ------------------------
// g_att[bh][sq][sk] = exp((2/scale) * <q,k>_L)  -- UNNORMALIZED.
// Softmax normalization is skipped entirely: project() downstream is
// homogeneous degree-0, so the per-row scale cancels exactly.
#define SROW 176                      // smem row stride bytes (11*16 -> bank rotate)
#define STILE (128 * SROW)            // 22528 bytes per tile
__global__ void __launch_bounds__(256) scores2_k(const float* __restrict__ scale_p) {
    extern __shared__ __align__(128) char dsm[];
    uint32_t sb = smem_u32(dsm);

    int tid = threadIdx.x;
    int wid = tid >> 5, lane = tid & 31;
    int wm = wid & 3, wn = wid >> 2;
    int bn = blockIdx.x, bm = blockIdx.y, bh = blockIdx.z;
    int m0 = bm * 128, n0 = bn * 128;

    const __nv_bfloat16* gsrc[4] = {g_qh, g_ql, g_kh, g_kl};
    #pragma unroll
    for (int t = 0; t < 4; t++) {
        size_t rbase = (size_t)bh * SS + ((t < 2) ? m0 : n0);
        #pragma unroll
        for (int i = 0; i < 5; i++) {
            int id = i * 256 + tid;          // 0..1279
            int r = id / 10, c = id - r * 10;
            cp_async16(sb + t * STILE + r * SROW + c * 16,
                       gsrc[t] + (rbase + r) * EP + c * 8);
        }
    }
    cp_commit();
    cp_wait<0>();
    __syncthreads();

    uint32_t aoff[2];
    {
        int khalf = lane >> 4;
        #pragma unroll
        for (int mi = 0; mi < 2; mi++) {
            int r = wm * 32 + mi * 16 + (lane & 15);
            aoff[mi] = (uint32_t)(r * SROW + khalf * 16);
        }
    }
    uint32_t boff[4];
    {
        int idx = lane >> 3;
        int khalf = idx & 1;
        #pragma unroll
        for (int jp = 0; jp < 4; jp++) {
            int r = wn * 64 + jp * 16 + (idx >> 1) * 8 + (lane & 7);
            boff[jp] = (uint32_t)(r * SROW + khalf * 16);
        }
    }

    uint32_t qH = sb, qL = sb + STILE, kH = sb + 2 * STILE, kL = sb + 3 * STILE;

    float acc[2][8][4];
    #pragma unroll
    for (int i = 0; i < 2; i++)
        #pragma unroll
        for (int j = 0; j < 8; j++)
            #pragma unroll
            for (int q = 0; q < 4; q++) acc[i][j][q] = 0.f;

    #pragma unroll
    for (int ks = 0; ks < 5; ks++) {
        uint32_t co = (uint32_t)(ks * 32);
        uint32_t Ah[2][4], Al[2][4];
        #pragma unroll
        for (int mi = 0; mi < 2; mi++) {
            ldsm_x4(Ah[mi], qH + aoff[mi] + co);
            ldsm_x4(Al[mi], qL + aoff[mi] + co);
        }
        uint32_t Bh[8][2], Bl[8][2];
        #pragma unroll
        for (int jp = 0; jp < 4; jp++) {
            uint32_t r4[4];
            ldsm_x4(r4, kH + boff[jp] + co);
            Bh[jp * 2][0] = r4[0]; Bh[jp * 2][1] = r4[1];
            Bh[jp * 2 + 1][0] = r4[2]; Bh[jp * 2 + 1][1] = r4[3];
            ldsm_x4(r4, kL + boff[jp] + co);
            Bl[jp * 2][0] = r4[0]; Bl[jp * 2][1] = r4[1];
            Bl[jp * 2 + 1][0] = r4[2]; Bl[jp * 2 + 1][1] = r4[3];
        }
        #pragma unroll
        for (int mi = 0; mi < 2; mi++)
            #pragma unroll
            for (int nj = 0; nj < 8; nj++) {
                mma_bf16(acc[mi][nj], Ah[mi], Bh[nj]);
                mma_bf16(acc[mi][nj], Ah[mi], Bl[nj]);
                mma_bf16(acc[mi][nj], Al[mi], Bh[nj]);
            }
    }

    float scl = 2.0f / scale_p[0];
    float* Ab = g_att + (size_t)bh * SS * SS;
    int g = lane >> 2, t = lane & 3;
    #pragma unroll
    for (int mi = 0; mi < 2; mi++) {
        int r0 = m0 + wm * 32 + mi * 16 + g;
        #pragma unroll
        for (int nj = 0; nj < 8; nj++) {
            int cg = n0 + wn * 64 + nj * 8 + 2 * t;
            *reinterpret_cast<float2*>(Ab + (size_t)r0 * SS + cg) =
                make_float2(exp_fast(acc[mi][nj][0] * scl), exp_fast(acc[mi][nj][1] * scl));
            *reinterpret_cast<float2*>(Ab + (size_t)(r0 + 8) * SS + cg) =
                make_float2(exp_fast(acc[mi][nj][2] * scl), exp_fast(acc[mi][nj][3] * scl));
        }
    }
}

// ---------------- PV + project (scale-invariant: P unnormalized) --------------
__global__ void __launch_bounds__(256) pv_k() {
    __shared__ float Ps[64][65];
    __shared__ float Vs[64][66];
    __shared__ float invd[64];
    int st = blockIdx.x;
    int bh = blockIdx.y;
    const float* Ab = g_att + (size_t)bh * SS * SS + (size_t)st * 64 * SS;
    const float* Vb = g_v + (size_t)bh * SS * HD1;
    int tid = threadIdx.x;
    int tr = tid >> 4, tc = tid & 15;
    float acc[4][5] = {};
    for (int kt = 0; kt < 16; kt++) {
        #pragma unroll
        for (int i = 0; i < 16; i++) {
            int lin = i * 256 + tid;
            int r = lin >> 6, c = lin & 63;
            Ps[r][c] = Ab[(size_t)r * SS + kt * 64 + c];
        }
        for (int lin = tid; lin < 64 * 65; lin += 256) {
            int t = lin / 65, e = lin - t * 65;
            Vs[t][e] = Vb[(size_t)(kt * 64 + t) * HD1 + e];
        }
        __syncthreads();
        #pragma unroll 8
        for (int kk = 0; kk < 64; kk++) {
            float p0[4], vv[5];
            #pragma unroll
            for (int i = 0; i < 4; i++) p0[i] = Ps[tr * 4 + i][kk];
            #pragma unroll
            for (int j = 0; j < 4; j++) vv[j] = Vs[kk][tc + j * 16];
            vv[4] = Vs[kk][64];
            #pragma unroll
            for (int i = 0; i < 4; i++)
                #pragma unroll
                for (int j = 0; j < 5; j++)
                    acc[i][j] += p0[i] * vv[j];
        }
        __syncthreads();
    }
    #pragma unroll
    for (int i = 0; i < 4; i++) {
        #pragma unroll
        for (int j = 0; j < 4; j++)
            Ps[tr * 4 + i][tc + j * 16] = acc[i][j];
        if (tc == 0) Ps[tr * 4 + i][64] = acc[i][4];
    }
    __syncthreads();
    if (tid < 64) {
        float m0 = Ps[tid][0];
        float ssum = 0.f;
        #pragma unroll
        for (int e = 1; e < 65; e++) ssum += Ps[tid][e] * Ps[tid][e];
        invd[tid] = rsqrtf(fmaxf(m0 * m0 - ssum, 1e-6f));
    }
    __syncthreads();
    int b = bh >> 4, h = bh & 15;
    for (int lin = tid; lin < 64 * 65; lin += 256) {
        int q = lin / 65, e = lin - q * 65;
        int s = st * 64 + q;
        g_cat[(size_t)(b * SS + s) * CATW + h * HD1 + e] = Ps[q][e] * invd[q];
    }
}

// ---------------- residual + project ------------------------------------------
__global__ void __launch_bounds__(256) resproj_k(const float* __restrict__ Xext,
                                                 int useInternalX,
                                                 const float* __restrict__ wp,
                                                 float* __restrict__ Oext,
                                                 int outInternal) {
    __shared__ float sm[8];
    const float* X = useInternalX ? g_x2 : Xext;
    float* out = outInternal ? g_x2 : Oext;
    int row = blockIdx.x;
    const float* ao = g_tmp + (size_t)row * DD;
    const float* xr = X + (size_t)row * D1;
    float a[4], sa = 0.f;
    #pragma unroll
    for (int i = 0; i < 4; i++) {
        a[i] = ao[threadIdx.x + i * 256];
        sa += a[i] * a[i];
    }
    sa = blockReduceSum(sa, sm);
    float w = wp[0];
    float tao = sqrtf(1.f + sa);
    float z0 = xr[0] + w * tao;
    float z[4], sz = 0.f;
    #pragma unroll
    for (int i = 0; i < 4; i++) {
        z[i] = xr[1 + threadIdx.x + i * 256] + w * a[i];
        sz += z[i] * z[i];
    }
    sz = blockReduceSum(sz, sm);
    float dinv = rsqrtf(fmaxf(z0 * z0 - sz, 1e-6f));
    float* orow = out + (size_t)row * D1;
    if (threadIdx.x == 0) orow[0] = z0 * dinv;
    #pragma unroll
    for (int i = 0; i < 4; i++) orow[1 + threadIdx.x + i * 256] = z[i] * dinv;
}

// ---------------- ff time component -------------------------------------------
__global__ void __launch_bounds__(256) ffT_k() {
    __shared__ float sm[8];
    int row = blockIdx.x;
    float* fr = g_ff + (size_t)row * FFP;
    float ss = 0.f;
    #pragma unroll
    for (int i = 0; i < 16; i++) {
        float v = fr[1 + threadIdx.x + i * 256];
        ss += v * v;
    }
    ss = blockReduceSum(ss, sm);
    if (threadIdx.x == 0) fr[0] = sqrtf(1.f + ss);
}

// ---------------- launcher ----------------------------------------------------
extern "C" void kernel_launch(void* const* d_in, const int* in_sizes, int n_in,
                              void* d_out, int out_size) {
    const float* x      = (const float*)d_in[0];
    const float* rc     = (const float*)d_in[1];
    const float* rs     = (const float*)d_in[2];
    const float* n1g    = (const float*)d_in[3];
    const float* n1b    = (const float*)d_in[4];
    const float* Wq     = (const float*)d_in[5];
    const float* bq     = (const float*)d_in[6];
    const float* Wk     = (const float*)d_in[7];
    const float* bk     = (const float*)d_in[8];
    const float* Wv     = (const float*)d_in[9];
    const float* bv     = (const float*)d_in[10];
    const float* ascale = (const float*)d_in[11];
    const float* Wo     = (const float*)d_in[13];
    const float* bo     = (const float*)d_in[14];
    const float* wr1    = (const float*)d_in[15];
    const float* n2g    = (const float*)d_in[16];
    const float* n2b    = (const float*)d_in[17];
    const float* W1     = (const float*)d_in[18];
    const float* b1     = (const float*)d_in[19];
    const float* W2     = (const float*)d_in[20];
    const float* b2     = (const float*)d_in[21];
    const float* wr2    = (const float*)d_in[22];
    float* out = (float*)d_out;

    const int DSM = 3 * STG;          // 192 KB (3-stage)
    const int DSM_S = 4 * STILE;      // 90112 B
    cudaFuncSetAttribute(mmagemm_k<0>, cudaFuncAttributeMaxDynamicSharedMemorySize, DSM);
    cudaFuncSetAttribute(mmagemm_k<1>, cudaFuncAttributeMaxDynamicSharedMemorySize, DSM);
    cudaFuncSetAttribute(scores2_k, cudaFuncAttributeMaxDynamicSharedMemorySize, DSM_S);

    const int BIG = 1 << 30;

    // ---- attention half ----
    ln_kernel<<<NROW, 256>>>(x, 0, n1g, n1b);
    splitA_k<<<dim3((KP1 + 255) / 256, NROW), 256>>>(0, D1, D1, KP1);
    transW_k<<<dim3(KP1 / 32, 32), 256>>>(Wq, 0,    D1, KP1, HDIM, D1 * HDIM, HDIM);
    transW_k<<<dim3(KP1 / 32, 32), 256>>>(Wk, 1024, D1, KP1, HDIM, D1 * HDIM, HDIM);
    transW_k<<<dim3(KP1 / 32, 32), 256>>>(Wv, 2048, D1, KP1, HDIM, D1 * HDIM, HDIM);
    mmagemm_k<0><<<dim3(24, 32), 256, DSM>>>(0, bq, bk, bv, KP1, 3072, 1024);

    rope_k<<<24576, 256>>>(rc, rs);
    scores2_k<<<dim3(8, 8, 64), 256, DSM_S>>>(ascale);
    pv_k<<<dim3(16, 64), 256>>>();

    splitA_k<<<dim3((KP1 + 255) / 256, NROW), 256>>>(1, CATW, CATW, KP1);
    transW_k<<<dim3(KP1 / 32, 32), 256>>>(Wo, 0, CATW, KP1, DD, 0, DD);
    mmagemm_k<0><<<dim3(8, 32), 256, DSM>>>(1, bo, bo, bo, KP1, DD, BIG);
    resproj_k<<<NROW, 256>>>(x, 0, wr1, nullptr, 1);

    // ---- MLP half ----
    ln_kernel<<<NROW, 256>>>(nullptr, 1, n2g, n2b);
    splitA_k<<<dim3((KP1 + 255) / 256, NROW), 256>>>(0, D1, D1, KP1);
    transW_k<<<dim3(KP1 / 32, FFDIM / 32), 256>>>(W1, 0, D1, KP1, FFDIM, 0, FFDIM);
    mmagemm_k<1><<<dim3(32, 32), 256, DSM>>>(2, b1, b1, b1, KP1, FFP, BIG);
    ffT_k<<<NROW, 256>>>();

    splitA_k<<<dim3((KP2 + 255) / 256, NROW), 256>>>(2, FFP, FFDIM + 1, KP2);
    transW_k<<<dim3(KP2 / 32, 32), 256>>>(W2, 0, FFDIM + 1, KP2, DD, 0, DD);
    mmagemm_k<0><<<dim3(8, 32), 256, DSM>>>(1, b2, b2, b2, KP2, DD, BIG);
    resproj_k<<<NROW, 256>>>(nullptr, 1, wr2, out, 0);
}

// round 9
// speedup vs baseline: 2.8150x; 1.0869x over previous
#include <cuda_runtime.h>
#include <cuda_bf16.h>
#include <math.h>
#include <stdint.h>

#define SS 1024
#define DD 1024
#define HH 16
#define HDIM 64
#define FFDIM 4096
#define NROW 4096      // B*S
#define D1 1025
#define HD1 65
#define BHN 64         // B*H
#define CATW 1040      // H*(HD+1)
#define FFP 4104       // FF+1 padded to mult of 8
#define EP 80          // padded head-dim+1 (65 -> 80) for bf16 q/k
#define VE 80          // e-major V rows (65 data + 15 zero pad)

#define KP1 1088       // padded K (17*64)
#define KP2 4160       // padded K (65*64)

// ---------------- scratch (device globals; no allocation allowed) ----------
__device__ float g_qkv[NROW * 3072];
__device__ float g_cat[NROW * CATW];
__device__ float g_tmp[NROW * DD];
__device__ float g_x2 [NROW * D1];
__device__ float g_ff [NROW * FFP];

// bf16 split buffers (GEMM)
__device__ __align__(16) __nv_bfloat16 gA_hi[(size_t)NROW * KP2];
__device__ __align__(16) __nv_bfloat16 gA_lo[(size_t)NROW * KP2];
__device__ __align__(16) __nv_bfloat16 gB_hi[(size_t)4096 * KP1];
__device__ __align__(16) __nv_bfloat16 gB_lo[(size_t)4096 * KP1];

// bf16 split q/k for scores: [bh][s][EP], q time-comp pre-negated
__device__ __align__(16) __nv_bfloat16 g_qh[(size_t)BHN * SS * EP];
__device__ __align__(16) __nv_bfloat16 g_ql[(size_t)BHN * SS * EP];
__device__ __align__(16) __nv_bfloat16 g_kh[(size_t)BHN * SS * EP];
__device__ __align__(16) __nv_bfloat16 g_kl[(size_t)BHN * SS * EP];

// unnormalized exp(scores), bf16 hi/lo: [bh][sq][sk]
__device__ __align__(16) __nv_bfloat16 g_ath[(size_t)BHN * SS * SS];
__device__ __align__(16) __nv_bfloat16 g_atl[(size_t)BHN * SS * SS];

// V e-major bf16 hi/lo: [bh][e(80)][s]
__device__ __align__(16) __nv_bfloat16 g_vh[(size_t)BHN * VE * SS];
__device__ __align__(16) __nv_bfloat16 g_vl[(size_t)BHN * VE * SS];

// ---------------- small helpers ----------------------------------------------
__device__ __forceinline__ uint32_t smem_u32(const void* p) {
    uint32_t a;
    asm("{ .reg .u64 t; cvta.to.shared.u64 t, %1; cvt.u32.u64 %0, t; }"
        : "=r"(a) : "l"(p));
    return a;
}
__device__ __forceinline__ void cp_async16(uint32_t s, const void* g) {
    asm volatile("{ .reg .u64 gp; cvta.to.global.u64 gp, %1; "
                 "cp.async.cg.shared.global [%0], [gp], 16; }"
                 :: "r"(s), "l"(g) : "memory");
}
__device__ __forceinline__ void cp_commit() {
    asm volatile("cp.async.commit_group;" ::: "memory");
}
template<int N>
__device__ __forceinline__ void cp_wait() {
    asm volatile("cp.async.wait_group %0;" :: "n"(N) : "memory");
}
__device__ __forceinline__ void ldsm_x4(uint32_t* r, uint32_t addr) {
    asm volatile("ldmatrix.sync.aligned.m8n8.x4.shared.b16 {%0,%1,%2,%3}, [%4];"
                 : "=r"(r[0]), "=r"(r[1]), "=r"(r[2]), "=r"(r[3]) : "r"(addr));
}
__device__ __forceinline__ void mma_bf16(float* c, const uint32_t* a, const uint32_t* b) {
    asm volatile("mma.sync.aligned.m16n8k16.row.col.f32.bf16.bf16.f32 "
                 "{%0,%1,%2,%3}, {%4,%5,%6,%7}, {%8,%9}, {%0,%1,%2,%3};"
                 : "+f"(c[0]), "+f"(c[1]), "+f"(c[2]), "+f"(c[3])
                 : "r"(a[0]), "r"(a[1]), "r"(a[2]), "r"(a[3]), "r"(b[0]), "r"(b[1]));
}

// fast exp for logits in ~[-0.6, 0]
__device__ __forceinline__ float exp_fast(float x) {
    float t = fmaxf(x * 1.4426950408889634f, -100.f);
    float r = t + 12582912.0f;
    int ri = __float_as_int(r);
    float fi = r - 12582912.0f;
    float f = t - fi;
    float p = 0.00133335581f;
    p = fmaf(p, f, 0.00961812911f);
    p = fmaf(p, f, 0.05550410866f);
    p = fmaf(p, f, 0.24022650696f);
    p = fmaf(p, f, 0.69314718056f);
    p = fmaf(p, f, 1.0f);
    float s = __int_as_float((ri + 127) << 23);
    return p * s;
}

// ---------------- reductions --------------------------------------------------
__device__ __forceinline__ float blockReduceSum(float v, float* sm) {
    #pragma unroll
    for (int o = 16; o; o >>= 1) v += __shfl_xor_sync(0xffffffffu, v, o);
    int w = threadIdx.x >> 5;
    if ((threadIdx.x & 31) == 0) sm[w] = v;
    __syncthreads();
    if (threadIdx.x < 32) {
        float t = (threadIdx.x < 8) ? sm[threadIdx.x] : 0.f;
        #pragma unroll
        for (int o = 4; o; o >>= 1) t += __shfl_xor_sync(0xffffffffu, t, o);
        if (threadIdx.x == 0) sm[0] = t;
    }
    __syncthreads();
    float r = sm[0];
    __syncthreads();
    return r;
}
__device__ __forceinline__ float gelu_tanh(float x) {
    float x3 = x * x * x;
    float t = tanhf(0.7978845608028654f * (x + 0.044715f * x3));
    return 0.5f * x * (1.0f + t);
}

// ---------------- layernorm (writes bf16 hi/lo A buffers directly) ------------
__global__ void __launch_bounds__(256) ln_kernel(const float* __restrict__ Xext,
                                                 int useInternal,
                                                 const float* __restrict__ g,
                                                 const float* __restrict__ b) {
    __shared__ float sm[8];
    const float* X = useInternal ? g_x2 : Xext;
    int row = blockIdx.x;
    const float* xr = X + (size_t)row * D1 + 1;
    float v[4], s = 0.f, sq = 0.f;
    #pragma unroll
    for (int i = 0; i < 4; i++) {
        v[i] = xr[threadIdx.x + i * 256];
        s += v[i]; sq += v[i] * v[i];
    }
    s  = blockReduceSum(s,  sm);
    sq = blockReduceSum(sq, sm);
    float mu = s * (1.f / DD);
    float var = sq * (1.f / DD) - mu * mu;
    float rstd = rsqrtf(var + 1e-5f);
    float o[4], ss = 0.f;
    #pragma unroll
    for (int i = 0; i < 4; i++) {
        int c = threadIdx.x + i * 256;
        o[i] = (v[i] - mu) * rstd * g[c] + b[c];
        ss += o[i] * o[i];
    }
    ss = blockReduceSum(ss, sm);
    size_t ob = (size_t)row * KP1;
    if (threadIdx.x == 0) {
        float t = sqrtf(1.f + ss);
        __nv_bfloat16 h = __float2bfloat16(t);
        gA_hi[ob] = h;
        gA_lo[ob] = __float2bfloat16(t - __bfloat162float(h));
    }
    #pragma unroll
    for (int i = 0; i < 4; i++) {
        __nv_bfloat16 h = __float2bfloat16(o[i]);
        size_t idx = ob + 1 + threadIdx.x + i * 256;
        gA_hi[idx] = h;
        gA_lo[idx] = __float2bfloat16(o[i] - __bfloat162float(h));
    }
    if (threadIdx.x < KP1 - 1025) {
        size_t idx = ob + 1025 + threadIdx.x;
        gA_hi[idx] = __float2bfloat16(0.f);
        gA_lo[idx] = __float2bfloat16(0.f);
    }
}

// ---------------- activation split (row-major, pad K) -------------------------
__global__ void __launch_bounds__(256) splitA_k(int sel, int lds, int Ks, int Kp) {
    int k = blockIdx.x * 256 + threadIdx.x;
    if (k >= Kp) return;
    int m = blockIdx.y;
    const float* src = (sel == 1) ? g_cat : g_ff;
    float v = (k < Ks) ? src[(size_t)m * lds + k] : 0.f;
    __nv_bfloat16 h = __float2bfloat16(v);
    __nv_bfloat16 l = __float2bfloat16(v - __bfloat162float(h));
    size_t o = (size_t)m * Kp + k;
    gA_hi[o] = h;
    gA_lo[o] = l;
}

// ---------------- weight transpose + split ------------------------------------
__global__ void __launch_bounds__(256) transW_k(const float* __restrict__ src,
                                                int dstRow0, int K, int Kp,
                                                int strideK, int headStride,
                                                int headWidth) {
    __shared__ float t[32][33];
    int tx = threadIdx.x & 31, ty = threadIdx.x >> 5;
    int k0 = blockIdx.x * 32, n0 = blockIdx.y * 32;
    #pragma unroll
    for (int i = 0; i < 4; i++) {
        int k = k0 + ty + i * 8;
        int n = n0 + tx;
        float v = 0.f;
        if (k < K)
            v = src[(size_t)(n / headWidth) * headStride + (size_t)k * strideK + (n % headWidth)];
        t[ty + i * 8][tx] = v;
    }
    __syncthreads();
    #pragma unroll
    for (int i = 0; i < 4; i++) {
        int n = n0 + ty + i * 8;
        int k = k0 + tx;
        float v = t[tx][ty + i * 8];
        __nv_bfloat16 h = __float2bfloat16(v);
        __nv_bfloat16 l = __float2bfloat16(v - __bfloat162float(h));
        size_t o = (size_t)(dstRow0 + n) * Kp + k;
        gB_hi[o] = h;
        gB_lo[o] = l;
    }
}

// ---------------- warp-MMA bf16-split GEMM (128x128 C tile, 3-stage) ----------
#define TCS 16384
#define STG 65536
template<int EPI>
__global__ void __launch_bounds__(256, 1) mmagemm_k(
    int csel,
    const float* __restrict__ bias0, const float* __restrict__ bias1,
    const float* __restrict__ bias2,
    int Kp, int ldc, int nPerMat)
{
    extern __shared__ __align__(128) char dsm[];
    uint32_t sb0 = smem_u32(dsm);

    int tid = threadIdx.x;
    int wid = tid >> 5, lane = tid & 31;
    int wm = wid & 3, wn = wid >> 2;
    int m0 = blockIdx.y * 128, n0 = blockIdx.x * 128;

    int lchunk = tid & 7;
    int lrow = tid >> 3;

    const __nv_bfloat16* srcs[4] = {gA_hi, gA_lo, gB_hi, gB_lo};
    const int NC = Kp >> 6;

    uint32_t aoff[2];
    {
        int khalf = lane >> 4;
        #pragma unroll
        for (int mi = 0; mi < 2; mi++) {
            int r = wm * 32 + mi * 16 + (lane & 15);
            aoff[mi] = (uint32_t)(r * 128) + (uint32_t)(((khalf) ^ (r & 7)) << 4);
        }
    }
    uint32_t boff[4];
    {
        int idx = lane >> 3;
        int khalf = idx & 1;
        #pragma unroll
        for (int jp = 0; jp < 4; jp++) {
            int r = wn * 64 + jp * 16 + (idx >> 1) * 8 + (lane & 7);
            boff[jp] = (uint32_t)(r * 128) + (uint32_t)((khalf ^ (r & 7)) << 4);
        }
    }

    float acc[2][8][4];
    #pragma unroll
    for (int i = 0; i < 2; i++)
        #pragma unroll
        for (int j = 0; j < 8; j++)
            #pragma unroll
            for (int q = 0; q < 4; q++) acc[i][j][q] = 0.f;

    auto load_stage = [&](int ic, int st) {
        size_t kbase = (size_t)ic * 64 + lchunk * 8;
        uint32_t sbase = sb0 + st * STG;
        #pragma unroll
        for (int t = 0; t < 4; t++) {
            int rowBase = (t < 2) ? m0 : n0;
            const __nv_bfloat16* src = srcs[t];
            #pragma unroll
            for (int i = 0; i < 4; i++) {
                int r = lrow + i * 32;
                const void* gp = src + (size_t)(rowBase + r) * Kp + kbase;
                uint32_t sp = sbase + t * TCS + (uint32_t)(r * 128) +
                              (uint32_t)((lchunk ^ (r & 7)) << 4);
                cp_async16(sp, gp);
            }
        }
        cp_commit();
    };

    load_stage(0, 0);
    if (NC > 1) load_stage(1, 1);

    int st = 0;
    for (int ic = 0; ic < NC; ic++) {
        if (ic + 2 < NC) {
            int st2 = (st + 2) % 3;
            load_stage(ic + 2, st2);
            cp_wait<2>();
        } else if (ic + 1 < NC) {
            cp_wait<1>();
        } else {
            cp_wait<0>();
        }
        __syncthreads();

        uint32_t aH = sb0 + st * STG;
        uint32_t aL = aH + TCS;
        uint32_t bH = aH + 2 * TCS;
        uint32_t bL = aH + 3 * TCS;

        #pragma unroll
        for (int ks = 0; ks < 4; ks++) {
            uint32_t kso = (uint32_t)(ks * 32);
            uint32_t Ah[2][4], Al[2][4];
            #pragma unroll
            for (int mi = 0; mi < 2; mi++) {
                ldsm_x4(Ah[mi], aH + (aoff[mi] ^ kso));
                ldsm_x4(Al[mi], aL + (aoff[mi] ^ kso));
            }
            uint32_t Bh[8][2], Bl[8][2];
            #pragma unroll
            for (int jp = 0; jp < 4; jp++) {
                uint32_t r4[4];
                ldsm_x4(r4, bH + (boff[jp] ^ kso));
                Bh[jp * 2][0] = r4[0]; Bh[jp * 2][1] = r4[1];
                Bh[jp * 2 + 1][0] = r4[2]; Bh[jp * 2 + 1][1] = r4[3];
                ldsm_x4(r4, bL + (boff[jp] ^ kso));
                Bl[jp * 2][0] = r4[0]; Bl[jp * 2][1] = r4[1];
                Bl[jp * 2 + 1][0] = r4[2]; Bl[jp * 2 + 1][1] = r4[3];
            }
            #pragma unroll
            for (int mi = 0; mi < 2; mi++)
                #pragma unroll
                for (int nj = 0; nj < 8; nj++) {
                    mma_bf16(acc[mi][nj], Ah[mi], Bh[nj]);
                    mma_bf16(acc[mi][nj], Ah[mi], Bl[nj]);
                    mma_bf16(acc[mi][nj], Al[mi], Bh[nj]);
                }
        }
        __syncthreads();
        st = (st + 1) % 3;
    }

    float* C = (csel == 0) ? g_qkv : (csel == 1 ? g_tmp : (g_ff + 1));
    int selB = (n0 / nPerMat);
    const float* bias = (selB == 0) ? bias0 : (selB == 1 ? bias1 : bias2);
    int nL0 = n0 - selB * nPerMat;

    int g = lane >> 2, t = lane & 3;
    #pragma unroll
    for (int mi = 0; mi < 2; mi++) {
        int r0 = m0 + wm * 32 + mi * 16 + g;
        #pragma unroll
        for (int nj = 0; nj < 8; nj++) {
            int col = wn * 64 + nj * 8 + 2 * t;
            int cg = n0 + col;
            float b0 = bias[nL0 + col], b1 = bias[nL0 + col + 1];
            float v0 = acc[mi][nj][0] + b0;
            float v1 = acc[mi][nj][1] + b1;
            float v2 = acc[mi][nj][2] + b0;
            float v3 = acc[mi][nj][3] + b1;
            if (EPI == 1) {
                v0 = gelu_tanh(v0); v1 = gelu_tanh(v1);
                v2 = gelu_tanh(v2); v3 = gelu_tanh(v3);
            }
            float* p0 = C + (size_t)r0 * ldc + cg;
            float* p1 = C + (size_t)(r0 + 8) * ldc + cg;
            p0[0] = v0; p0[1] = v1;
            p1[0] = v2; p1[1] = v3;
        }
    }
}

// ---------------- RoPE + unit-norm + lift; q/k row-major, V e-major -----------
__global__ void __launch_bounds__(256) rope_k(const float* __restrict__ rc,
                                              const float* __restrict__ rs) {
    int gw = (blockIdx.x * 256 + threadIdx.x) >> 5;
    int lane = threadIdx.x & 31;
    int mat = gw / (NROW * HH);
    int rem = gw - mat * (NROW * HH);
    int row = rem >> 4;
    int h = rem & 15;
    int b = row >> 10, s = row & 1023;
    int bh = b * HH + h;
    const float* src = g_qkv + (size_t)row * 3072 + mat * 1024 + h * 64 + 2 * lane;
    float x0 = src[0], x1 = src[1];
    if (mat < 2) {
        float c = rc[s * 32 + lane], sn = rs[s * 32 + lane];
        float xr = x0 * c - x1 * sn;
        float xi = x0 * sn + x1 * c;
        float ss = xr * xr + xi * xi;
        #pragma unroll
        for (int o = 16; o; o >>= 1) ss += __shfl_xor_sync(0xffffffffu, ss, o);
        float inv = rsqrtf(ss + 1e-6f);
        float t = sqrtf(1.f + ss * inv * inv);
        __nv_bfloat16* dh = ((mat == 0) ? g_qh : g_kh) + (size_t)(bh * SS + s) * EP;
        __nv_bfloat16* dl = ((mat == 0) ? g_ql : g_kl) + (size_t)(bh * SS + s) * EP;
        float e1 = xr * inv, e2 = xi * inv;
        __nv_bfloat16 h1 = __float2bfloat16(e1);
        __nv_bfloat16 h2 = __float2bfloat16(e2);
        dh[1 + 2 * lane] = h1; dl[1 + 2 * lane] = __float2bfloat16(e1 - __bfloat162float(h1));
        dh[2 + 2 * lane] = h2; dl[2 + 2 * lane] = __float2bfloat16(e2 - __bfloat162float(h2));
        if (lane == 0) {
            float e0 = (mat == 0) ? -t : t;
            __nv_bfloat16 h0 = __float2bfloat16(e0);
            dh[0] = h0; dl[0] = __float2bfloat16(e0 - __bfloat162float(h0));
        }
        if (lane < 15) {
            dh[65 + lane] = __float2bfloat16(0.f);
            dl[65 + lane] = __float2bfloat16(0.f);
        }
    } else {
        float ss = x0 * x0 + x1 * x1;
        #pragma unroll
        for (int o = 16; o; o >>= 1) ss += __shfl_xor_sync(0xffffffffu, ss, o);
        __nv_bfloat16* vh = g_vh + (size_t)bh * VE * SS;
        __nv_bfloat16* vl = g_vl + (size_t)bh * VE * SS;
        __nv_bfloat16 h1 = __float2bfloat16(x0);
        __nv_bfloat16 h2 = __float2bfloat16(x1);
        vh[(size_t)(1 + 2 * lane) * SS + s] = h1;
        vl[(size_t)(1 + 2 * lane) * SS + s] = __float2bfloat16(x0 - __bfloat162float(h1));
        vh[(size_t)(2 + 2 * lane) * SS + s] = h2;
        vl[(size_t)(2 + 2 * lane) * SS + s] = __float2bfloat16(x1 - __bfloat162float(h2));
        if (lane == 0) {
            float t = sqrtf(1.f + ss);
            __nv_bfloat16 h0 = __float2bfloat16(t);
            vh[s] = h0;
            vl[s] = __float2bfloat16(t - __bfloat162float(h0));
        }
        if (lane < 15) {
            vh[(size_t)(65 + lane) * SS + s] = __float2bfloat16(0.f);
            vl[(size_t)(65 + lane) * SS + s] = __float2bfloat16(0.f);
        }
    }
}

// ---------------- scores: bf16-split MMA + fused exp -> bf16 hi/lo ------------
#define SROW 176
#define STILE (128 * SROW)
__global__ void __launch_bounds__(256) scores2_k(const float* __restrict__ scale_p) {
    extern __shared__ __align__(128) char dsm[];
    uint32_t sb = smem_u32(dsm);

    int tid = threadIdx.x;
    int wid = tid >> 5, lane = tid & 31;
    int wm = wid & 3, wn = wid >> 2;
    int bn = blockIdx.x, bm = blockIdx.y, bh = blockIdx.z;
    int m0 = bm * 128, n0 = bn * 128;

    const __nv_bfloat16* gsrc[4] = {g_qh, g_ql, g_kh, g_kl};
    #pragma unroll
    for (int t = 0; t < 4; t++) {
        size_t rbase = (size_t)bh * SS + ((t < 2) ? m0 : n0);
        #pragma unroll
        for (int i = 0; i < 5; i++) {
            int id = i * 256 + tid;
            int r = id / 10, c = id - r * 10;
            cp_async16(sb + t * STILE + r * SROW + c * 16,
                       gsrc[t] + (rbase + r) * EP + c * 8);
        }
    }
    cp_commit();
    cp_wait<0>();
    __syncthreads();

    uint32_t aoff[2];
    {
        int khalf = lane >> 4;
        #pragma unroll
        for (int mi = 0; mi < 2; mi++) {
            int r = wm * 32 + mi * 16 + (lane & 15);
            aoff[mi] = (uint32_t)(r * SROW + khalf * 16);
        }
    }
    uint32_t boff[4];
    {
        int idx = lane >> 3;
        int khalf = idx & 1;
        #pragma unroll
        for (int jp = 0; jp < 4; jp++) {
            int r = wn * 64 + jp * 16 + (idx >> 1) * 8 + (lane & 7);
            boff[jp] = (uint32_t)(r * SROW + khalf * 16);
        }
    }

    uint32_t qH = sb, qL = sb + STILE, kH = sb + 2 * STILE, kL = sb + 3 * STILE;

    float acc[2][8][4];
    #pragma unroll
    for (int i = 0; i < 2; i++)
        #pragma unroll
        for (int j = 0; j < 8; j++)
            #pragma unroll
            for (int q = 0; q < 4; q++) acc[i][j][q] = 0.f;

    #pragma unroll
    for (int ks = 0; ks < 5; ks++) {
        uint32_t co = (uint32_t)(ks * 32);
        uint32_t Ah[2][4], Al[2][4];
        #pragma unroll
        for (int mi = 0; mi < 2; mi++) {
            ldsm_x4(Ah[mi], qH + aoff[mi] + co);
            ldsm_x4(Al[mi], qL + aoff[mi] + co);
        }
        uint32_t Bh[8][2], Bl[8][2];
        #pragma unroll
        for (int jp = 0; jp < 4; jp++) {
            uint32_t r4[4];
            ldsm_x4(r4, kH + boff[jp] + co);
            Bh[jp * 2][0] = r4[0]; Bh[jp * 2][1] = r4[1];
            Bh[jp * 2 + 1][0] = r4[2]; Bh[jp * 2 + 1][1] = r4[3];
            ldsm_x4(r4, kL + boff[jp] + co);
            Bl[jp * 2][0] = r4[0]; Bl[jp * 2][1] = r4[1];
            Bl[jp * 2 + 1][0] = r4[2]; Bl[jp * 2 + 1][1] = r4[3];
        }
        #pragma unroll
        for (int mi = 0; mi < 2; mi++)
            #pragma unroll
            for (int nj = 0; nj < 8; nj++) {
                mma_bf16(acc[mi][nj], Ah[mi], Bh[nj]);
                mma_bf16(acc[mi][nj], Ah[mi], Bl[nj]);
                mma_bf16(acc[mi][nj], Al[mi], Bh[nj]);
            }
    }

    float scl = 2.0f / scale_p[0];
    __nv_bfloat16* Ah_ = g_ath + (size_t)bh * SS * SS;
    __nv_bfloat16* Al_ = g_atl + (size_t)bh * SS * SS;
    int g = lane >> 2, t = lane & 3;
    #pragma unroll
    for (int mi = 0; mi < 2; mi++) {
        int r0 = m0 + wm * 32 + mi * 16 + g;
        #pragma unroll
        for (int nj = 0; nj < 8; nj++) {
            int cg = n0 + wn * 64 + nj * 8 + 2 * t;
            #pragma unroll
            for (int half = 0; half < 2; half++) {
                int rr = r0 + half * 8;
                float p0 = exp_fast(acc[mi][nj][half * 2 + 0] * scl);
                float p1 = exp_fast(acc[mi][nj][half * 2 + 1] * scl);
                __nv_bfloat16 h0 = __float2bfloat16(p0);
                __nv_bfloat16 h1 = __float2bfloat16(p1);
                __nv_bfloat162 hp; hp.x = h0; hp.y = h1;
                __nv_bfloat162 lp;
                lp.x = __float2bfloat16(p0 - __bfloat162float(h0));
                lp.y = __float2bfloat16(p1 - __bfloat162float(h1));
                *reinterpret_cast<__nv_bfloat162*>(Ah_ + (size_t)rr * SS + cg) = hp;
                *reinterpret_cast<__nv_bfloat162*>(Al_ + (size_t)rr * SS + cg) = lp;
            }
        }
    }
}

// ---------------- PV via bf16-split MMA + in-register Lorentz project ---------
// m[128][80] per (q-tile, bh); P unnormalized (project absorbs row scale).
#define PV_PHI 0
#define PV_PLO 16384
#define PV_VHI 32768
#define PV_VLO 43008
#define PV_STG 53248
__global__ void __launch_bounds__(256, 1) pv2_k() {
    extern __shared__ __align__(128) char dsm[];
    uint32_t sb = smem_u32(dsm);

    int tid = threadIdx.x;
    int wid = tid >> 5, lane = tid & 31;
    int bh = blockIdx.y;
    int m0 = blockIdx.x * 128;
    size_t attBase = (size_t)bh * SS * SS;
    size_t vBase = (size_t)bh * VE * SS;

    int lch = tid & 7, lr = tid >> 3;

    auto load_stage = [&](int ic, int st) {
        size_t kb = (size_t)ic * 64 + lch * 8;
        uint32_t sbase = sb + st * PV_STG;
        #pragma unroll
        for (int i = 0; i < 4; i++) {
            int q = lr + i * 32;
            uint32_t so = (uint32_t)(q * 128) + (uint32_t)((lch ^ (q & 7)) << 4);
            cp_async16(sbase + PV_PHI + so, g_ath + attBase + (size_t)(m0 + q) * SS + kb);
            cp_async16(sbase + PV_PLO + so, g_atl + attBase + (size_t)(m0 + q) * SS + kb);
        }
        for (int lin = tid; lin < 640; lin += 256) {
            int r = lin >> 3, c = lin & 7;
            size_t go = vBase + (size_t)r * SS + (size_t)ic * 64 + c * 8;
            uint32_t so = (uint32_t)(r * 128) + (uint32_t)((c ^ (r & 7)) << 4);
            cp_async16(sbase + PV_VHI + so, g_vh + go);
            cp_async16(sbase + PV_VLO + so, g_vl + go);
        }
        cp_commit();
    };

    // fragment offsets: warp wid owns rows wid*16..wid*16+15
    uint32_t aoff;
    {
        int khalf = lane >> 4;
        int r = wid * 16 + (lane & 15);
        aoff = (uint32_t)(r * 128) + (uint32_t)((khalf ^ (r & 7)) << 4);
    }
    uint32_t boff[5];
    {
        int idx = lane >> 3;
        int khalf = idx & 1;
        #pragma unroll
        for (int jp = 0; jp < 5; jp++) {
            int r = jp * 16 + (idx >> 1) * 8 + (lane & 7);
            boff[jp] = (uint32_t)(r * 128) + (uint32_t)((khalf ^ (r & 7)) << 4);
        }
    }

    float acc[10][4];
    #pragma unroll
    for (int j = 0; j < 10; j++)
        #pragma unroll
        for (int q = 0; q < 4; q++) acc[j][q] = 0.f;

    load_stage(0, 0);

    for (int ic = 0; ic < 16; ic++) {
        int st = ic & 1;
        if (ic + 1 < 16) {
            load_stage(ic + 1, st ^ 1);
            cp_wait<1>();
        } else {
            cp_wait<0>();
        }
        __syncthreads();

        uint32_t pH = sb + st * PV_STG + PV_PHI;
        uint32_t pL = sb + st * PV_STG + PV_PLO;
        uint32_t vH = sb + st * PV_STG + PV_VHI;
        uint32_t vL = sb + st * PV_STG + PV_VLO;

        #pragma unroll
        for (int ks = 0; ks < 4; ks++) {
            uint32_t kso = (uint32_t)(ks * 32);
            uint32_t Ah[4], Al[4];
            ldsm_x4(Ah, pH + (aoff ^ kso));
            ldsm_x4(Al, pL + (aoff ^ kso));
            uint32_t Bh[10][2], Bl[10][2];
            #pragma unroll
            for (int jp = 0; jp < 5; jp++) {
                uint32_t r4[4];
                ldsm_x4(r4, vH + (boff[jp] ^ kso));
                Bh[jp * 2][0] = r4[0]; Bh[jp * 2][1] = r4[1];
                Bh[jp * 2 + 1][0] = r4[2]; Bh[jp * 2 + 1][1] = r4[3];
                ldsm_x4(r4, vL + (boff[jp] ^ kso));
                Bl[jp * 2][0] = r4[0]; Bl[jp * 2][1] = r4[1];
                Bl[jp * 2 + 1][0] = r4[2]; Bl[jp * 2 + 1][1] = r4[3];
            }
            #pragma unroll
            for (int nj = 0; nj < 10; nj++) {
                mma_bf16(acc[nj], Ah, Bh[nj]);
                mma_bf16(acc[nj], Ah, Bl[nj]);
                mma_bf16(acc[nj], Al, Bh[nj]);
            }
        }
        __syncthreads();
    }

    // in-register Lorentz project: rows r = m0 + wid*16 + g (and +8)
    int g = lane >> 2, t = lane & 3;
    float s0 = 0.f, s1 = 0.f;
    #pragma unroll
    for (int nj = 0; nj < 10; nj++) {
        s0 += acc[nj][0] * acc[nj][0] + acc[nj][1] * acc[nj][1];
        s1 += acc[nj][2] * acc[nj][2] + acc[nj][3] * acc[nj][3];
    }
    s0 += __shfl_xor_sync(0xffffffffu, s0, 1);
    s0 += __shfl_xor_sync(0xffffffffu, s0, 2);
    s1 += __shfl_xor_sync(0xffffffffu, s1, 1);
    s1 += __shfl_xor_sync(0xffffffffu, s1, 2);
    float m00 = __shfl_sync(0xffffffffu, acc[0][0], lane & ~3);
    float m01 = __shfl_sync(0xffffffffu, acc[0][2], lane & ~3);
    float inv0 = rsqrtf(fmaxf(2.f * m00 * m00 - s0, 1e-6f));
    float inv1 = rsqrtf(fmaxf(2.f * m01 * m01 - s1, 1e-6f));

    int b = bh >> 4, h = bh & 15;
    int sq0 = m0 + wid * 16 + g;
    float* d0 = g_cat + (size_t)(b * SS + sq0) * CATW + h * HD1;
    float* d1 = g_cat + (size_t)(b * SS + sq0 + 8) * CATW + h * HD1;
    #pragma unroll
    for (int nj = 0; nj < 10; nj++) {
        int e = nj * 8 + 2 * t;
        if (e < 65) {
            d0[e] = acc[nj][0] * inv0;
            d1[e] = acc[nj][2] * inv1;
        }
        if (e + 1 < 65) {
            d0[e + 1] = acc[nj][1] * inv0;
            d1[e + 1] = acc[nj][3] * inv1;
        }
    }
}

// ---------------- residual + project ------------------------------------------
__global__ void __launch_bounds__(256) resproj_k(const float* __restrict__ Xext,
                                                 int useInternalX,
                                                 const float* __restrict__ wp,
                                                 float* __restrict__ Oext,
                                                 int outInternal) {
    __shared__ float sm[8];
    const float* X = useInternalX ? g_x2 : Xext;
    float* out = outInternal ? g_x2 : Oext;
    int row = blockIdx.x;
    const float* ao = g_tmp + (size_t)row * DD;
    const float* xr = X + (size_t)row * D1;
    float a[4], sa = 0.f;
    #pragma unroll
    for (int i = 0; i < 4; i++) {
        a[i] = ao[threadIdx.x + i * 256];
        sa += a[i] * a[i];
    }
    sa = blockReduceSum(sa, sm);
    float w = wp[0];
    float tao = sqrtf(1.f + sa);
    float z0 = xr[0] + w * tao;
    float z[4], sz = 0.f;
    #pragma unroll
    for (int i = 0; i < 4; i++) {
        z[i] = xr[1 + threadIdx.x + i * 256] + w * a[i];
        sz += z[i] * z[i];
    }
    sz = blockReduceSum(sz, sm);
    float dinv = rsqrtf(fmaxf(z0 * z0 - sz, 1e-6f));
    float* orow = out + (size_t)row * D1;
    if (threadIdx.x == 0) orow[0] = z0 * dinv;
    #pragma unroll
    for (int i = 0; i < 4; i++) orow[1 + threadIdx.x + i * 256] = z[i] * dinv;
}

// ---------------- ff time component -------------------------------------------
__global__ void __launch_bounds__(256) ffT_k() {
    __shared__ float sm[8];
    int row = blockIdx.x;
    float* fr = g_ff + (size_t)row * FFP;
    float ss = 0.f;
    #pragma unroll
    for (int i = 0; i < 16; i++) {
        float v = fr[1 + threadIdx.x + i * 256];
        ss += v * v;
    }
    ss = blockReduceSum(ss, sm);
    if (threadIdx.x == 0) fr[0] = sqrtf(1.f + ss);
}

// ---------------- launcher ----------------------------------------------------
extern "C" void kernel_launch(void* const* d_in, const int* in_sizes, int n_in,
                              void* d_out, int out_size) {
    const float* x      = (const float*)d_in[0];
    const float* rc     = (const float*)d_in[1];
    const float* rs     = (const float*)d_in[2];
    const float* n1g    = (const float*)d_in[3];
    const float* n1b    = (const float*)d_in[4];
    const float* Wq     = (const float*)d_in[5];
    const float* bq     = (const float*)d_in[6];
    const float* Wk     = (const float*)d_in[7];
    const float* bk     = (const float*)d_in[8];
    const float* Wv     = (const float*)d_in[9];
    const float* bv     = (const float*)d_in[10];
    const float* ascale = (const float*)d_in[11];
    const float* Wo     = (const float*)d_in[13];
    const float* bo     = (const float*)d_in[14];
    const float* wr1    = (const float*)d_in[15];
    const float* n2g    = (const float*)d_in[16];
    const float* n2b    = (const float*)d_in[17];
    const float* W1     = (const float*)d_in[18];
    const float* b1     = (const float*)d_in[19];
    const float* W2     = (const float*)d_in[20];
    const float* b2     = (const float*)d_in[21];
    const float* wr2    = (const float*)d_in[22];
    float* out = (float*)d_out;

    const int DSM = 3 * STG;          // 192 KB
    const int DSM_S = 4 * STILE;      // 90112 B
    const int DSM_PV = 2 * PV_STG;    // 106496 B
    cudaFuncSetAttribute(mmagemm_k<0>, cudaFuncAttributeMaxDynamicSharedMemorySize, DSM);
    cudaFuncSetAttribute(mmagemm_k<1>, cudaFuncAttributeMaxDynamicSharedMemorySize, DSM);
    cudaFuncSetAttribute(scores2_k, cudaFuncAttributeMaxDynamicSharedMemorySize, DSM_S);
    cudaFuncSetAttribute(pv2_k, cudaFuncAttributeMaxDynamicSharedMemorySize, DSM_PV);

    const int BIG = 1 << 30;

    // ---- attention half ----
    ln_kernel<<<NROW, 256>>>(x, 0, n1g, n1b);
    transW_k<<<dim3(KP1 / 32, 32), 256>>>(Wq, 0,    D1, KP1, HDIM, D1 * HDIM, HDIM);
    transW_k<<<dim3(KP1 / 32, 32), 256>>>(Wk, 1024, D1, KP1, HDIM, D1 * HDIM, HDIM);
    transW_k<<<dim3(KP1 / 32, 32), 256>>>(Wv, 2048, D1, KP1, HDIM, D1 * HDIM, HDIM);
    mmagemm_k<0><<<dim3(24, 32), 256, DSM>>>(0, bq, bk, bv, KP1, 3072, 1024);

    rope_k<<<24576, 256>>>(rc, rs);
    scores2_k<<<dim3(8, 8, 64), 256, DSM_S>>>(ascale);
    pv2_k<<<dim3(8, 64), 256, DSM_PV>>>();

    splitA_k<<<dim3((KP1 + 255) / 256, NROW), 256>>>(1, CATW, CATW, KP1);
    transW_k<<<dim3(KP1 / 32, 32), 256>>>(Wo, 0, CATW, KP1, DD, 0, DD);
    mmagemm_k<0><<<dim3(8, 32), 256, DSM>>>(1, bo, bo, bo, KP1, DD, BIG);
    resproj_k<<<NROW, 256>>>(x, 0, wr1, nullptr, 1);

    // ---- MLP half ----
    ln_kernel<<<NROW, 256>>>(nullptr, 1, n2g, n2b);
    transW_k<<<dim3(KP1 / 32, FFDIM / 32), 256>>>(W1, 0, D1, KP1, FFDIM, 0, FFDIM);
    mmagemm_k<1><<<dim3(32, 32), 256, DSM>>>(2, b1, b1, b1, KP1, FFP, BIG);
    ffT_k<<<NROW, 256>>>();

    splitA_k<<<dim3((KP2 + 255) / 256, NROW), 256>>>(2, FFP, FFDIM + 1, KP2);
    transW_k<<<dim3(KP2 / 32, 32), 256>>>(W2, 0, FFDIM + 1, KP2, DD, 0, DD);
    mmagemm_k<0><<<dim3(8, 32), 256, DSM>>>(1, b2, b2, b2, KP2, DD, BIG);
    resproj_k<<<NROW, 256>>>(nullptr, 1, wr2, out, 0);
}

// round 10
// speedup vs baseline: 2.9218x; 1.0380x over previous
#include <cuda_runtime.h>
#include <cuda_bf16.h>
#include <math.h>
#include <stdint.h>

#define SS 1024
#define DD 1024
#define HH 16
#define HDIM 64
#define FFDIM 4096
#define NROW 4096      // B*S
#define D1 1025
#define HD1 65
#define BHN 64         // B*H
#define CATW 1040      // H*(HD+1)
#define EP 80          // padded head-dim+1 (65 -> 80) for bf16 q/k
#define VE 80          // e-major V rows (65 data + 15 zero pad)

#define KP1 1088       // padded K (17*64)
#define KP2 4160       // padded K (65*64)

// ---------------- scratch (device globals; no allocation allowed) ----------
__device__ float g_qkv[NROW * 3072];
__device__ float g_tmp[NROW * DD];
__device__ float g_x2 [NROW * D1];

// bf16 split A buffers
__device__ __align__(16) __nv_bfloat16 gA_hi[(size_t)NROW * KP1];
__device__ __align__(16) __nv_bfloat16 gA_lo[(size_t)NROW * KP1];
__device__ __align__(16) __nv_bfloat16 gA2_hi[(size_t)NROW * KP2];
__device__ __align__(16) __nv_bfloat16 gA2_lo[(size_t)NROW * KP2];
__device__ __align__(16) __nv_bfloat16 gB_hi[(size_t)4096 * KP1];
__device__ __align__(16) __nv_bfloat16 gB_lo[(size_t)4096 * KP1];

// bf16 split q/k for scores: [bh][s][EP], q time-comp pre-negated
__device__ __align__(16) __nv_bfloat16 g_qh[(size_t)BHN * SS * EP];
__device__ __align__(16) __nv_bfloat16 g_ql[(size_t)BHN * SS * EP];
__device__ __align__(16) __nv_bfloat16 g_kh[(size_t)BHN * SS * EP];
__device__ __align__(16) __nv_bfloat16 g_kl[(size_t)BHN * SS * EP];

// V e-major bf16 hi/lo: [bh][e(80)][s]
__device__ __align__(16) __nv_bfloat16 g_vh[(size_t)BHN * VE * SS];
__device__ __align__(16) __nv_bfloat16 g_vl[(size_t)BHN * VE * SS];

// ---------------- small helpers ----------------------------------------------
__device__ __forceinline__ uint32_t smem_u32(const void* p) {
    uint32_t a;
    asm("{ .reg .u64 t; cvta.to.shared.u64 t, %1; cvt.u32.u64 %0, t; }"
        : "=r"(a) : "l"(p));
    return a;
}
__device__ __forceinline__ void cp_async16(uint32_t s, const void* g) {
    asm volatile("{ .reg .u64 gp; cvta.to.global.u64 gp, %1; "
                 "cp.async.cg.shared.global [%0], [gp], 16; }"
                 :: "r"(s), "l"(g) : "memory");
}
__device__ __forceinline__ void cp_commit() {
    asm volatile("cp.async.commit_group;" ::: "memory");
}
template<int N>
__device__ __forceinline__ void cp_wait() {
    asm volatile("cp.async.wait_group %0;" :: "n"(N) : "memory");
}
__device__ __forceinline__ void ldsm_x4(uint32_t* r, uint32_t addr) {
    asm volatile("ldmatrix.sync.aligned.m8n8.x4.shared.b16 {%0,%1,%2,%3}, [%4];"
                 : "=r"(r[0]), "=r"(r[1]), "=r"(r[2]), "=r"(r[3]) : "r"(addr));
}
__device__ __forceinline__ void mma_bf16(float* c, const uint32_t* a, const uint32_t* b) {
    asm volatile("mma.sync.aligned.m16n8k16.row.col.f32.bf16.bf16.f32 "
                 "{%0,%1,%2,%3}, {%4,%5,%6,%7}, {%8,%9}, {%0,%1,%2,%3};"
                 : "+f"(c[0]), "+f"(c[1]), "+f"(c[2]), "+f"(c[3])
                 : "r"(a[0]), "r"(a[1]), "r"(a[2]), "r"(a[3]), "r"(b[0]), "r"(b[1]));
}
__device__ __forceinline__ uint32_t pack2(float a, float b) {
    __nv_bfloat162 t;
    t.x = __float2bfloat16(a);
    t.y = __float2bfloat16(b);
    return *reinterpret_cast<uint32_t*>(&t);
}

// fast exp for logits in ~[-0.6, 0]
__device__ __forceinline__ float exp_fast(float x) {
    float t = fmaxf(x * 1.4426950408889634f, -100.f);
    float r = t + 12582912.0f;
    int ri = __float_as_int(r);
    float fi = r - 12582912.0f;
    float f = t - fi;
    float p = 0.00133335581f;
    p = fmaf(p, f, 0.00961812911f);
    p = fmaf(p, f, 0.05550410866f);
    p = fmaf(p, f, 0.24022650696f);
    p = fmaf(p, f, 0.69314718056f);
    p = fmaf(p, f, 1.0f);
    float s = __int_as_float((ri + 127) << 23);
    return p * s;
}

// ---------------- reductions --------------------------------------------------
__device__ __forceinline__ float blockReduceSum(float v, float* sm) {
    #pragma unroll
    for (int o = 16; o; o >>= 1) v += __shfl_xor_sync(0xffffffffu, v, o);
    int w = threadIdx.x >> 5;
    if ((threadIdx.x & 31) == 0) sm[w] = v;
    __syncthreads();
    if (threadIdx.x < 32) {
        float t = (threadIdx.x < 8) ? sm[threadIdx.x] : 0.f;
        #pragma unroll
        for (int o = 4; o; o >>= 1) t += __shfl_xor_sync(0xffffffffu, t, o);
        if (threadIdx.x == 0) sm[0] = t;
    }
    __syncthreads();
    float r = sm[0];
    __syncthreads();
    return r;
}
__device__ __forceinline__ float gelu_tanh(float x) {
    float x3 = x * x * x;
    float t = tanhf(0.7978845608028654f * (x + 0.044715f * x3));
    return 0.5f * x * (1.0f + t);
}

// ---------------- layernorm (writes bf16 hi/lo gA directly) -------------------
__global__ void __launch_bounds__(256) ln_kernel(const float* __restrict__ Xext,
                                                 int useInternal,
                                                 const float* __restrict__ g,
                                                 const float* __restrict__ b) {
    __shared__ float sm[8];
    const float* X = useInternal ? g_x2 : Xext;
    int row = blockIdx.x;
    const float* xr = X + (size_t)row * D1 + 1;
    float v[4], s = 0.f, sq = 0.f;
    #pragma unroll
    for (int i = 0; i < 4; i++) {
        v[i] = xr[threadIdx.x + i * 256];
        s += v[i]; sq += v[i] * v[i];
    }
    s  = blockReduceSum(s,  sm);
    sq = blockReduceSum(sq, sm);
    float mu = s * (1.f / DD);
    float var = sq * (1.f / DD) - mu * mu;
    float rstd = rsqrtf(var + 1e-5f);
    float o[4], ss = 0.f;
    #pragma unroll
    for (int i = 0; i < 4; i++) {
        int c = threadIdx.x + i * 256;
        o[i] = (v[i] - mu) * rstd * g[c] + b[c];
        ss += o[i] * o[i];
    }
    ss = blockReduceSum(ss, sm);
    size_t ob = (size_t)row * KP1;
    if (threadIdx.x == 0) {
        float t = sqrtf(1.f + ss);
        __nv_bfloat16 h = __float2bfloat16(t);
        gA_hi[ob] = h;
        gA_lo[ob] = __float2bfloat16(t - __bfloat162float(h));
    }
    #pragma unroll
    for (int i = 0; i < 4; i++) {
        __nv_bfloat16 h = __float2bfloat16(o[i]);
        size_t idx = ob + 1 + threadIdx.x + i * 256;
        gA_hi[idx] = h;
        gA_lo[idx] = __float2bfloat16(o[i] - __bfloat162float(h));
    }
    if (threadIdx.x < KP1 - 1025) {
        size_t idx = ob + 1025 + threadIdx.x;
        gA_hi[idx] = __float2bfloat16(0.f);
        gA_lo[idx] = __float2bfloat16(0.f);
    }
}

// ---------------- weight transpose + split ------------------------------------
__global__ void __launch_bounds__(256) transW_k(const float* __restrict__ src,
                                                int dstRow0, int K, int Kp,
                                                int strideK, int headStride,
                                                int headWidth) {
    __shared__ float t[32][33];
    int tx = threadIdx.x & 31, ty = threadIdx.x >> 5;
    int k0 = blockIdx.x * 32, n0 = blockIdx.y * 32;
    #pragma unroll
    for (int i = 0; i < 4; i++) {
        int k = k0 + ty + i * 8;
        int n = n0 + tx;
        float v = 0.f;
        if (k < K)
            v = src[(size_t)(n / headWidth) * headStride + (size_t)k * strideK + (n % headWidth)];
        t[ty + i * 8][tx] = v;
    }
    __syncthreads();
    #pragma unroll
    for (int i = 0; i < 4; i++) {
        int n = n0 + ty + i * 8;
        int k = k0 + tx;
        float v = t[tx][ty + i * 8];
        __nv_bfloat16 h = __float2bfloat16(v);
        __nv_bfloat16 l = __float2bfloat16(v - __bfloat162float(h));
        size_t o = (size_t)(dstRow0 + n) * Kp + k;
        gB_hi[o] = h;
        gB_lo[o] = l;
    }
}

// ---------------- warp-MMA bf16-split GEMM (128x128 C tile, 3-stage) ----------
// csel: 0=g_qkv f32, 1=g_tmp f32, 2=split-write gelu into gA2 at col k=1+n
#define TCS 16384
#define STG 65536
template<int EPI>
__global__ void __launch_bounds__(256, 1) mmagemm_k(
    int asel, int csel,
    const float* __restrict__ bias0, const float* __restrict__ bias1,
    const float* __restrict__ bias2,
    int Kp, int ldc, int nPerMat)
{
    extern __shared__ __align__(128) char dsm[];
    uint32_t sb0 = smem_u32(dsm);

    int tid = threadIdx.x;
    int wid = tid >> 5, lane = tid & 31;
    int wm = wid & 3, wn = wid >> 2;
    int m0 = blockIdx.y * 128, n0 = blockIdx.x * 128;

    int lchunk = tid & 7;
    int lrow = tid >> 3;

    const __nv_bfloat16* srcs[4] = {asel ? gA2_hi : gA_hi, asel ? gA2_lo : gA_lo,
                                    gB_hi, gB_lo};
    const int NC = Kp >> 6;

    uint32_t aoff[2];
    {
        int khalf = lane >> 4;
        #pragma unroll
        for (int mi = 0; mi < 2; mi++) {
            int r = wm * 32 + mi * 16 + (lane & 15);
            aoff[mi] = (uint32_t)(r * 128) + (uint32_t)(((khalf) ^ (r & 7)) << 4);
        }
    }
    uint32_t boff[4];
    {
        int idx = lane >> 3;
        int khalf = idx & 1;
        #pragma unroll
        for (int jp = 0; jp < 4; jp++) {
            int r = wn * 64 + jp * 16 + (idx >> 1) * 8 + (lane & 7);
            boff[jp] = (uint32_t)(r * 128) + (uint32_t)((khalf ^ (r & 7)) << 4);
        }
    }

    float acc[2][8][4];
    #pragma unroll
    for (int i = 0; i < 2; i++)
        #pragma unroll
        for (int j = 0; j < 8; j++)
            #pragma unroll
            for (int q = 0; q < 4; q++) acc[i][j][q] = 0.f;

    auto load_stage = [&](int ic, int st) {
        size_t kbase = (size_t)ic * 64 + lchunk * 8;
        uint32_t sbase = sb0 + st * STG;
        #pragma unroll
        for (int t = 0; t < 4; t++) {
            int rowBase = (t < 2) ? m0 : n0;
            const __nv_bfloat16* src = srcs[t];
            #pragma unroll
            for (int i = 0; i < 4; i++) {
                int r = lrow + i * 32;
                const void* gp = src + (size_t)(rowBase + r) * Kp + kbase;
                uint32_t sp = sbase + t * TCS + (uint32_t)(r * 128) +
                              (uint32_t)((lchunk ^ (r & 7)) << 4);
                cp_async16(sp, gp);
            }
        }
        cp_commit();
    };

    load_stage(0, 0);
    if (NC > 1) load_stage(1, 1);

    int st = 0;
    for (int ic = 0; ic < NC; ic++) {
        if (ic + 2 < NC) {
            int st2 = (st + 2) % 3;
            load_stage(ic + 2, st2);
            cp_wait<2>();
        } else if (ic + 1 < NC) {
            cp_wait<1>();
        } else {
            cp_wait<0>();
        }
        __syncthreads();

        uint32_t aH = sb0 + st * STG;
        uint32_t aL = aH + TCS;
        uint32_t bH = aH + 2 * TCS;
        uint32_t bL = aH + 3 * TCS;

        #pragma unroll
        for (int ks = 0; ks < 4; ks++) {
            uint32_t kso = (uint32_t)(ks * 32);
            uint32_t Ah[2][4], Al[2][4];
            #pragma unroll
            for (int mi = 0; mi < 2; mi++) {
                ldsm_x4(Ah[mi], aH + (aoff[mi] ^ kso));
                ldsm_x4(Al[mi], aL + (aoff[mi] ^ kso));
            }
            uint32_t Bh[8][2], Bl[8][2];
            #pragma unroll
            for (int jp = 0; jp < 4; jp++) {
                uint32_t r4[4];
                ldsm_x4(r4, bH + (boff[jp] ^ kso));
                Bh[jp * 2][0] = r4[0]; Bh[jp * 2][1] = r4[1];
                Bh[jp * 2 + 1][0] = r4[2]; Bh[jp * 2 + 1][1] = r4[3];
                ldsm_x4(r4, bL + (boff[jp] ^ kso));
                Bl[jp * 2][0] = r4[0]; Bl[jp * 2][1] = r4[1];
                Bl[jp * 2 + 1][0] = r4[2]; Bl[jp * 2 + 1][1] = r4[3];
            }
            #pragma unroll
            for (int mi = 0; mi < 2; mi++)
                #pragma unroll
                for (int nj = 0; nj < 8; nj++) {
                    mma_bf16(acc[mi][nj], Ah[mi], Bh[nj]);
                    mma_bf16(acc[mi][nj], Ah[mi], Bl[nj]);
                    mma_bf16(acc[mi][nj], Al[mi], Bh[nj]);
                }
        }
        __syncthreads();
        st = (st + 1) % 3;
    }

    int selB = (n0 / nPerMat);
    const float* bias = (selB == 0) ? bias0 : (selB == 1 ? bias1 : bias2);
    int nL0 = n0 - selB * nPerMat;

    int g = lane >> 2, t = lane & 3;
    if (csel == 2) {
        // gelu + bf16 split into gA2 at col k = 1 + n (ldc = KP2)
        #pragma unroll
        for (int mi = 0; mi < 2; mi++) {
            int r0 = m0 + wm * 32 + mi * 16 + g;
            #pragma unroll
            for (int nj = 0; nj < 8; nj++) {
                int col = wn * 64 + nj * 8 + 2 * t;
                float b0 = bias[nL0 + col], b1 = bias[nL0 + col + 1];
                #pragma unroll
                for (int half = 0; half < 2; half++) {
                    float v0 = gelu_tanh(acc[mi][nj][half * 2 + 0] + b0);
                    float v1 = gelu_tanh(acc[mi][nj][half * 2 + 1] + b1);
                    size_t o = (size_t)(r0 + half * 8) * ldc + 1 + n0 + col;
                    __nv_bfloat16 h0 = __float2bfloat16(v0);
                    __nv_bfloat16 h1 = __float2bfloat16(v1);
                    gA2_hi[o] = h0;
                    gA2_hi[o + 1] = h1;
                    gA2_lo[o] = __float2bfloat16(v0 - __bfloat162float(h0));
                    gA2_lo[o + 1] = __float2bfloat16(v1 - __bfloat162float(h1));
                }
            }
        }
    } else {
        float* C = (csel == 0) ? g_qkv : g_tmp;
        #pragma unroll
        for (int mi = 0; mi < 2; mi++) {
            int r0 = m0 + wm * 32 + mi * 16 + g;
            #pragma unroll
            for (int nj = 0; nj < 8; nj++) {
                int col = wn * 64 + nj * 8 + 2 * t;
                int cg = n0 + col;
                float b0 = bias[nL0 + col], b1 = bias[nL0 + col + 1];
                float* p0 = C + (size_t)r0 * ldc + cg;
                float* p1 = C + (size_t)(r0 + 8) * ldc + cg;
                p0[0] = acc[mi][nj][0] + b0; p0[1] = acc[mi][nj][1] + b1;
                p1[0] = acc[mi][nj][2] + b0; p1[1] = acc[mi][nj][3] + b1;
            }
        }
    }
}

// ---------------- RoPE + unit-norm + lift; q/k row-major, V e-major -----------
__global__ void __launch_bounds__(256) rope_k(const float* __restrict__ rc,
                                              const float* __restrict__ rs) {
    int gw = (blockIdx.x * 256 + threadIdx.x) >> 5;
    int lane = threadIdx.x & 31;
    int mat = gw / (NROW * HH);
    int rem = gw - mat * (NROW * HH);
    int row = rem >> 4;
    int h = rem & 15;
    int b = row >> 10, s = row & 1023;
    int bh = b * HH + h;
    const float* src = g_qkv + (size_t)row * 3072 + mat * 1024 + h * 64 + 2 * lane;
    float x0 = src[0], x1 = src[1];
    if (mat < 2) {
        float c = rc[s * 32 + lane], sn = rs[s * 32 + lane];
        float xr = x0 * c - x1 * sn;
        float xi = x0 * sn + x1 * c;
        float ss = xr * xr + xi * xi;
        #pragma unroll
        for (int o = 16; o; o >>= 1) ss += __shfl_xor_sync(0xffffffffu, ss, o);
        float inv = rsqrtf(ss + 1e-6f);
        float t = sqrtf(1.f + ss * inv * inv);
        __nv_bfloat16* dh = ((mat == 0) ? g_qh : g_kh) + (size_t)(bh * SS + s) * EP;
        __nv_bfloat16* dl = ((mat == 0) ? g_ql : g_kl) + (size_t)(bh * SS + s) * EP;
        float e1 = xr * inv, e2 = xi * inv;
        __nv_bfloat16 h1 = __float2bfloat16(e1);
        __nv_bfloat16 h2 = __float2bfloat16(e2);
        dh[1 + 2 * lane] = h1; dl[1 + 2 * lane] = __float2bfloat16(e1 - __bfloat162float(h1));
        dh[2 + 2 * lane] = h2; dl[2 + 2 * lane] = __float2bfloat16(e2 - __bfloat162float(h2));
        if (lane == 0) {
            float e0 = (mat == 0) ? -t : t;
            __nv_bfloat16 h0 = __float2bfloat16(e0);
            dh[0] = h0; dl[0] = __float2bfloat16(e0 - __bfloat162float(h0));
        }
        if (lane < 15) {
            dh[65 + lane] = __float2bfloat16(0.f);
            dl[65 + lane] = __float2bfloat16(0.f);
        }
    } else {
        float ss = x0 * x0 + x1 * x1;
        #pragma unroll
        for (int o = 16; o; o >>= 1) ss += __shfl_xor_sync(0xffffffffu, ss, o);
        __nv_bfloat16* vh = g_vh + (size_t)bh * VE * SS;
        __nv_bfloat16* vl = g_vl + (size_t)bh * VE * SS;
        __nv_bfloat16 h1 = __float2bfloat16(x0);
        __nv_bfloat16 h2 = __float2bfloat16(x1);
        vh[(size_t)(1 + 2 * lane) * SS + s] = h1;
        vl[(size_t)(1 + 2 * lane) * SS + s] = __float2bfloat16(x0 - __bfloat162float(h1));
        vh[(size_t)(2 + 2 * lane) * SS + s] = h2;
        vl[(size_t)(2 + 2 * lane) * SS + s] = __float2bfloat16(x1 - __bfloat162float(h2));
        if (lane == 0) {
            float t = sqrtf(1.f + ss);
            __nv_bfloat16 h0 = __float2bfloat16(t);
            vh[s] = h0;
            vl[s] = __float2bfloat16(t - __bfloat162float(h0));
        }
        if (lane < 15) {
            vh[(size_t)(65 + lane) * SS + s] = __float2bfloat16(0.f);
            vl[(size_t)(65 + lane) * SS + s] = __float2bfloat16(0.f);
        }
    }
}

// ---------------- flash attention: S-MMA -> exp -> P-frag -> PV-MMA -> project
// Grid (8 q-tiles, 64 bh). Q persistent in smem; K/V k-tiles of 64 double-buf.
// Output written as bf16 hi/lo into gA (cat layout, KP1 stride).
#define SROW 176
#define FQ_SZ  45056                  // Q hi + Q lo (2 x 128*176)
#define FK_HI  0
#define FK_LO  11264
#define FV_HI  22528
#define FV_LO  32768
#define F_STG  43008
__global__ void __launch_bounds__(256, 1) flash_k(const float* __restrict__ scale_p) {
    extern __shared__ __align__(128) char dsm[];
    uint32_t sb = smem_u32(dsm);

    int tid = threadIdx.x;
    int wid = tid >> 5, lane = tid & 31;
    int bh = blockIdx.y;
    int m0 = blockIdx.x * 128;
    size_t qkBase = (size_t)bh * SS;
    size_t vBase = (size_t)bh * VE * SS;

    // load Q hi/lo (128 rows x 160B, stride 176B)
    #pragma unroll
    for (int i = 0; i < 5; i++) {
        int id = i * 256 + tid;
        int r = id / 10, c = id - r * 10;
        size_t go = (qkBase + m0 + r) * EP + c * 8;
        cp_async16(sb + r * SROW + c * 16, g_qh + go);
        cp_async16(sb + 22528 + r * SROW + c * 16, g_ql + go);
    }
    cp_commit();

    auto load_kv = [&](int ic, int st) {
        uint32_t sbase = sb + FQ_SZ + st * F_STG;
        for (int lin = tid; lin < 640; lin += 256) {
            int r = lin / 10, c = lin - r * 10;       // K: 64 rows x 10 chunks
            size_t go = (qkBase + ic * 64 + r) * EP + c * 8;
            cp_async16(sbase + FK_HI + r * SROW + c * 16, g_kh + go);
            cp_async16(sbase + FK_LO + r * SROW + c * 16, g_kl + go);
        }
        for (int lin = tid; lin < 640; lin += 256) {
            int r = lin >> 3, c = lin & 7;            // V: 80 rows x 8 chunks
            size_t go = vBase + (size_t)r * SS + ic * 64 + c * 8;
            uint32_t so = (uint32_t)(r * 128) + (uint32_t)((c ^ (r & 7)) << 4);
            cp_async16(sbase + FV_HI + so, g_vh + go);
            cp_async16(sbase + FV_LO + so, g_vl + go);
        }
        cp_commit();
    };

    // fragment offsets
    uint32_t qoff;                 // Q rows wid*16..+15, SROW stride, additive k
    {
        int khalf = lane >> 4;
        int r = wid * 16 + (lane & 15);
        qoff = (uint32_t)(r * SROW + khalf * 16);
    }
    uint32_t koff[4];              // K rows 0..63, SROW stride, additive k
    {
        int idx = lane >> 3;
        int khalf = idx & 1;
        #pragma unroll
        for (int jp = 0; jp < 4; jp++) {
            int r = jp * 16 + (idx >> 1) * 8 + (lane & 7);
            koff[jp] = (uint32_t)(r * SROW + khalf * 16);
        }
    }
    uint32_t voff[5];              // V rows 0..79, 128B swizzled, XOR k
    {
        int idx = lane >> 3;
        int khalf = idx & 1;
        #pragma unroll
        for (int jp = 0; jp < 5; jp++) {
            int r = jp * 16 + (idx >> 1) * 8 + (lane & 7);
            voff[jp] = (uint32_t)(r * 128) + (uint32_t)((khalf ^ (r & 7)) << 4);
        }
    }

    float O[10][4];
    #pragma unroll
    for (int j = 0; j < 10; j++)
        #pragma unroll
        for (int q = 0; q < 4; q++) O[j][q] = 0.f;

    float scl = 2.0f / scale_p[0];
    load_kv(0, 0);

    for (int ic = 0; ic < 16; ic++) {
        int st = ic & 1;
        if (ic + 1 < 16) {
            load_kv(ic + 1, st ^ 1);
            cp_wait<1>();
        } else {
            cp_wait<0>();
        }
        __syncthreads();

        uint32_t kb = sb + FQ_SZ + st * F_STG;
        uint32_t qH = sb, qL = sb + 22528;
        uint32_t kH = kb + FK_HI, kL = kb + FK_LO;
        uint32_t vH = kb + FV_HI, vL = kb + FV_LO;

        // ---- S = Q K^T (16 rows x 64 cols per warp, 3-term split)
        float S[8][4];
        #pragma unroll
        for (int j = 0; j < 8; j++)
            #pragma unroll
            for (int q = 0; q < 4; q++) S[j][q] = 0.f;

        #pragma unroll
        for (int ks = 0; ks < 5; ks++) {
            uint32_t co = (uint32_t)(ks * 32);
            uint32_t Ah[4], Al[4];
            ldsm_x4(Ah, qH + qoff + co);
            ldsm_x4(Al, qL + qoff + co);
            uint32_t Bh[8][2], Bl[8][2];
            #pragma unroll
            for (int jp = 0; jp < 4; jp++) {
                uint32_t r4[4];
                ldsm_x4(r4, kH + koff[jp] + co);
                Bh[jp * 2][0] = r4[0]; Bh[jp * 2][1] = r4[1];
                Bh[jp * 2 + 1][0] = r4[2]; Bh[jp * 2 + 1][1] = r4[3];
                ldsm_x4(r4, kL + koff[jp] + co);
                Bl[jp * 2][0] = r4[0]; Bl[jp * 2][1] = r4[1];
                Bl[jp * 2 + 1][0] = r4[2]; Bl[jp * 2 + 1][1] = r4[3];
            }
            #pragma unroll
            for (int nj = 0; nj < 8; nj++) {
                mma_bf16(S[nj], Ah, Bh[nj]);
                mma_bf16(S[nj], Ah, Bl[nj]);
                mma_bf16(S[nj], Al, Bh[nj]);
            }
        }

        // ---- P = exp(S*scl); repack C-frags as A-frags; O += P V
        #pragma unroll
        for (int kc = 0; kc < 4; kc++) {
            float p[8];
            #pragma unroll
            for (int q = 0; q < 4; q++) {
                p[q]     = exp_fast(S[2 * kc][q] * scl);
                p[4 + q] = exp_fast(S[2 * kc + 1][q] * scl);
            }
            uint32_t Pah[4], Pal[4];
            Pah[0] = pack2(p[0], p[1]);
            Pah[1] = pack2(p[2], p[3]);
            Pah[2] = pack2(p[4], p[5]);
            Pah[3] = pack2(p[6], p[7]);
            {
                __nv_bfloat162 h0 = *reinterpret_cast<__nv_bfloat162*>(&Pah[0]);
                __nv_bfloat162 h1 = *reinterpret_cast<__nv_bfloat162*>(&Pah[1]);
                __nv_bfloat162 h2 = *reinterpret_cast<__nv_bfloat162*>(&Pah[2]);
                __nv_bfloat162 h3 = *reinterpret_cast<__nv_bfloat162*>(&Pah[3]);
                Pal[0] = pack2(p[0] - __bfloat162float(h0.x), p[1] - __bfloat162float(h0.y));
                Pal[1] = pack2(p[2] - __bfloat162float(h1.x), p[3] - __bfloat162float(h1.y));
                Pal[2] = pack2(p[4] - __bfloat162float(h2.x), p[5] - __bfloat162float(h2.y));
                Pal[3] = pack2(p[6] - __bfloat162float(h3.x), p[7] - __bfloat162float(h3.y));
            }
            uint32_t kso = (uint32_t)(kc * 32);
            uint32_t Vh[10][2], Vl[10][2];
            #pragma unroll
            for (int jp = 0; jp < 5; jp++) {
                uint32_t r4[4];
                ldsm_x4(r4, vH + (voff[jp] ^ kso));
                Vh[jp * 2][0] = r4[0]; Vh[jp * 2][1] = r4[1];
                Vh[jp * 2 + 1][0] = r4[2]; Vh[jp * 2 + 1][1] = r4[3];
                ldsm_x4(r4, vL + (voff[jp] ^ kso));
                Vl[jp * 2][0] = r4[0]; Vl[jp * 2][1] = r4[1];
                Vl[jp * 2 + 1][0] = r4[2]; Vl[jp * 2 + 1][1] = r4[3];
            }
            #pragma unroll
            for (int nj = 0; nj < 10; nj++) {
                mma_bf16(O[nj], Pah, Vh[nj]);
                mma_bf16(O[nj], Pah, Vl[nj]);
                mma_bf16(O[nj], Pal, Vh[nj]);
            }
        }
        __syncthreads();
    }

    // ---- in-register Lorentz project; write bf16 split into gA (cat layout)
    int g = lane >> 2, t = lane & 3;
    float s0 = 0.f, s1 = 0.f;
    #pragma unroll
    for (int nj = 0; nj < 10; nj++) {
        s0 += O[nj][0] * O[nj][0] + O[nj][1] * O[nj][1];
        s1 += O[nj][2] * O[nj][2] + O[nj][3] * O[nj][3];
    }
    s0 += __shfl_xor_sync(0xffffffffu, s0, 1);
    s0 += __shfl_xor_sync(0xffffffffu, s0, 2);
    s1 += __shfl_xor_sync(0xffffffffu, s1, 1);
    s1 += __shfl_xor_sync(0xffffffffu, s1, 2);
    float m00 = __shfl_sync(0xffffffffu, O[0][0], lane & ~3);
    float m01 = __shfl_sync(0xffffffffu, O[0][2], lane & ~3);
    float inv0 = rsqrtf(fmaxf(2.f * m00 * m00 - s0, 1e-6f));
    float inv1 = rsqrtf(fmaxf(2.f * m01 * m01 - s1, 1e-6f));

    int b = bh >> 4, h = bh & 15;
    int sq0 = m0 + wid * 16 + g;
    size_t r0 = (size_t)(b * SS + sq0) * KP1 + h * HD1;
    size_t r1 = (size_t)(b * SS + sq0 + 8) * KP1 + h * HD1;
    #pragma unroll
    for (int nj = 0; nj < 10; nj++) {
        int e = nj * 8 + 2 * t;
        #pragma unroll
        for (int q = 0; q < 2; q++) {
            if (e + q < 65) {
                float v0 = O[nj][q] * inv0;
                float v1 = O[nj][2 + q] * inv1;
                __nv_bfloat16 h0 = __float2bfloat16(v0);
                __nv_bfloat16 h1 = __float2bfloat16(v1);
                gA_hi[r0 + e + q] = h0;
                gA_lo[r0 + e + q] = __float2bfloat16(v0 - __bfloat162float(h0));
                gA_hi[r1 + e + q] = h1;
                gA_lo[r1 + e + q] = __float2bfloat16(v1 - __bfloat162float(h1));
            }
        }
    }
    // zero K-pad cols 1040..1087 (once per row; h==0 blocks own it)
    if (h == 0) {
        for (int lin = tid; lin < 128 * 48; lin += 256) {
            int rr = lin / 48, cc = lin - (lin / 48) * 48;
            size_t o = (size_t)(b * SS + m0 + rr) * KP1 + 1040 + cc;
            gA_hi[o] = __float2bfloat16(0.f);
            gA_lo[o] = __float2bfloat16(0.f);
        }
    }
}

// ---------------- residual + project ------------------------------------------
__global__ void __launch_bounds__(256) resproj_k(const float* __restrict__ Xext,
                                                 int useInternalX,
                                                 const float* __restrict__ wp,
                                                 float* __restrict__ Oext,
                                                 int outInternal) {
    __shared__ float sm[8];
    const float* X = useInternalX ? g_x2 : Xext;
    float* out = outInternal ? g_x2 : Oext;
    int row = blockIdx.x;
    const float* ao = g_tmp + (size_t)row * DD;
    const float* xr = X + (size_t)row * D1;
    float a[4], sa = 0.f;
    #pragma unroll
    for (int i = 0; i < 4; i++) {
        a[i] = ao[threadIdx.x + i * 256];
        sa += a[i] * a[i];
    }
    sa = blockReduceSum(sa, sm);
    float w = wp[0];
    float tao = sqrtf(1.f + sa);
    float z0 = xr[0] + w * tao;
    float z[4], sz = 0.f;
    #pragma unroll
    for (int i = 0; i < 4; i++) {
        z[i] = xr[1 + threadIdx.x + i * 256] + w * a[i];
        sz += z[i] * z[i];
    }
    sz = blockReduceSum(sz, sm);
    float dinv = rsqrtf(fmaxf(z0 * z0 - sz, 1e-6f));
    float* orow = out + (size_t)row * D1;
    if (threadIdx.x == 0) orow[0] = z0 * dinv;
    #pragma unroll
    for (int i = 0; i < 4; i++) orow[1 + threadIdx.x + i * 256] = z[i] * dinv;
}

// ---------------- ff time component (reads gA2, writes col0 + K-pad) ----------
__global__ void __launch_bounds__(256) ffT_k() {
    __shared__ float sm[8];
    int row = blockIdx.x;
    size_t ob = (size_t)row * KP2;
    float ss = 0.f;
    #pragma unroll
    for (int i = 0; i < 16; i++) {
        size_t idx = ob + 1 + threadIdx.x + i * 256;
        float v = __bfloat162float(gA2_hi[idx]) + __bfloat162float(gA2_lo[idx]);
        ss += v * v;
    }
    ss = blockReduceSum(ss, sm);
    if (threadIdx.x == 0) {
        float t = sqrtf(1.f + ss);
        __nv_bfloat16 h = __float2bfloat16(t);
        gA2_hi[ob] = h;
        gA2_lo[ob] = __float2bfloat16(t - __bfloat162float(h));
    }
    if (threadIdx.x < KP2 - 4097) {
        size_t idx = ob + 4097 + threadIdx.x;
        gA2_hi[idx] = __float2bfloat16(0.f);
        gA2_lo[idx] = __float2bfloat16(0.f);
    }
}

// ---------------- launcher ----------------------------------------------------
extern "C" void kernel_launch(void* const* d_in, const int* in_sizes, int n_in,
                              void* d_out, int out_size) {
    const float* x      = (const float*)d_in[0];
    const float* rc     = (const float*)d_in[1];
    const float* rs     = (const float*)d_in[2];
    const float* n1g    = (const float*)d_in[3];
    const float* n1b    = (const float*)d_in[4];
    const float* Wq     = (const float*)d_in[5];
    const float* bq     = (const float*)d_in[6];
    const float* Wk     = (const float*)d_in[7];
    const float* bk     = (const float*)d_in[8];
    const float* Wv     = (const float*)d_in[9];
    const float* bv     = (const float*)d_in[10];
    const float* ascale = (const float*)d_in[11];
    const float* Wo     = (const float*)d_in[13];
    const float* bo     = (const float*)d_in[14];
    const float* wr1    = (const float*)d_in[15];
    const float* n2g    = (const float*)d_in[16];
    const float* n2b    = (const float*)d_in[17];
    const float* W1     = (const float*)d_in[18];
    const float* b1     = (const float*)d_in[19];
    const float* W2     = (const float*)d_in[20];
    const float* b2     = (const float*)d_in[21];
    const float* wr2    = (const float*)d_in[22];
    float* out = (float*)d_out;

    const int DSM   = 3 * STG;               // 192 KB
    const int DSM_F = FQ_SZ + 2 * F_STG;     // 131072 B
    cudaFuncSetAttribute(mmagemm_k<0>, cudaFuncAttributeMaxDynamicSharedMemorySize, DSM);
    cudaFuncSetAttribute(mmagemm_k<1>, cudaFuncAttributeMaxDynamicSharedMemorySize, DSM);
    cudaFuncSetAttribute(flash_k, cudaFuncAttributeMaxDynamicSharedMemorySize, DSM_F);

    const int BIG = 1 << 30;

    // ---- attention half ----
    ln_kernel<<<NROW, 256>>>(x, 0, n1g, n1b);
    transW_k<<<dim3(KP1 / 32, 32), 256>>>(Wq, 0,    D1, KP1, HDIM, D1 * HDIM, HDIM);
    transW_k<<<dim3(KP1 / 32, 32), 256>>>(Wk, 1024, D1, KP1, HDIM, D1 * HDIM, HDIM);
    transW_k<<<dim3(KP1 / 32, 32), 256>>>(Wv, 2048, D1, KP1, HDIM, D1 * HDIM, HDIM);
    mmagemm_k<0><<<dim3(24, 32), 256, DSM>>>(0, 0, bq, bk, bv, KP1, 3072, 1024);

    rope_k<<<24576, 256>>>(rc, rs);
    flash_k<<<dim3(8, 64), 256, DSM_F>>>(ascale);

    transW_k<<<dim3(KP1 / 32, 32), 256>>>(Wo, 0, CATW, KP1, DD, 0, DD);
    mmagemm_k<0><<<dim3(8, 32), 256, DSM>>>(0, 1, bo, bo, bo, KP1, DD, BIG);
    resproj_k<<<NROW, 256>>>(x, 0, wr1, nullptr, 1);

    // ---- MLP half ----
    ln_kernel<<<NROW, 256>>>(nullptr, 1, n2g, n2b);
    transW_k<<<dim3(KP1 / 32, FFDIM / 32), 256>>>(W1, 0, D1, KP1, FFDIM, 0, FFDIM);
    mmagemm_k<1><<<dim3(32, 32), 256, DSM>>>(0, 2, b1, b1, b1, KP1, KP2, BIG);
    ffT_k<<<NROW, 256>>>();

    transW_k<<<dim3(KP2 / 32, 32), 256>>>(W2, 0, FFDIM + 1, KP2, DD, 0, DD);
    mmagemm_k<0><<<dim3(8, 32), 256, DSM>>>(1, 1, b2, b2, b2, KP2, DD, BIG);
    resproj_k<<<NROW, 256>>>(nullptr, 1, wr2, out, 0);
}

// round 11
// speedup vs baseline: 3.9860x; 1.3642x over previous
#include <cuda_runtime.h>
#include <cuda_fp16.h>
#include <math.h>
#include <stdint.h>

#define SS 1024
#define DD 1024
#define HH 16
#define HDIM 64
#define FFDIM 4096
#define NROW 4096      // B*S
#define D1 1025
#define HD1 65
#define BHN 64         // B*H
#define CATW 1040      // H*(HD+1)
#define EP 80          // padded head-dim+1 (65 -> 80)
#define VE 80          // e-major V rows (65 data + 15 zero pad)

#define KP1 1088       // padded K (17*64)
#define KP2 4160       // padded K (65*64)

// ---------------- scratch (device globals; no allocation allowed) ----------
__device__ float g_qkv[NROW * 3072];
__device__ float g_tmp[NROW * DD];
__device__ float g_x2 [NROW * D1];

// fp16 A buffers (hi only — A-side low bits dropped in 2-term scheme)
__device__ __align__(16) __half gA_hi [(size_t)NROW * KP1];
__device__ __align__(16) __half gA2_hi[(size_t)NROW * KP2];
// fp16 B buffers (weights: hi + lo)
__device__ __align__(16) __half gB_hi[(size_t)4096 * KP1];
__device__ __align__(16) __half gB_lo[(size_t)4096 * KP1];

// q (hi only, time-comp pre-negated), k (hi+lo): [bh][s][EP]
__device__ __align__(16) __half g_qh[(size_t)BHN * SS * EP];
__device__ __align__(16) __half g_kh[(size_t)BHN * SS * EP];
__device__ __align__(16) __half g_kl[(size_t)BHN * SS * EP];

// V e-major hi/lo: [bh][e(80)][s]
__device__ __align__(16) __half g_vh[(size_t)BHN * VE * SS];
__device__ __align__(16) __half g_vl[(size_t)BHN * VE * SS];

// ---------------- small helpers ----------------------------------------------
__device__ __forceinline__ uint32_t smem_u32(const void* p) {
    uint32_t a;
    asm("{ .reg .u64 t; cvta.to.shared.u64 t, %1; cvt.u32.u64 %0, t; }"
        : "=r"(a) : "l"(p));
    return a;
}
__device__ __forceinline__ void cp_async16(uint32_t s, const void* g) {
    asm volatile("{ .reg .u64 gp; cvta.to.global.u64 gp, %1; "
                 "cp.async.cg.shared.global [%0], [gp], 16; }"
                 :: "r"(s), "l"(g) : "memory");
}
__device__ __forceinline__ void cp_commit() {
    asm volatile("cp.async.commit_group;" ::: "memory");
}
template<int N>
__device__ __forceinline__ void cp_wait() {
    asm volatile("cp.async.wait_group %0;" :: "n"(N) : "memory");
}
__device__ __forceinline__ void ldsm_x4(uint32_t* r, uint32_t addr) {
    asm volatile("ldmatrix.sync.aligned.m8n8.x4.shared.b16 {%0,%1,%2,%3}, [%4];"
                 : "=r"(r[0]), "=r"(r[1]), "=r"(r[2]), "=r"(r[3]) : "r"(addr));
}
__device__ __forceinline__ void mma_f16(float* c, const uint32_t* a, const uint32_t* b) {
    asm volatile("mma.sync.aligned.m16n8k16.row.col.f32.f16.f16.f32 "
                 "{%0,%1,%2,%3}, {%4,%5,%6,%7}, {%8,%9}, {%0,%1,%2,%3};"
                 : "+f"(c[0]), "+f"(c[1]), "+f"(c[2]), "+f"(c[3])
                 : "r"(a[0]), "r"(a[1]), "r"(a[2]), "r"(a[3]), "r"(b[0]), "r"(b[1]));
}
__device__ __forceinline__ uint32_t pack2h(float a, float b) {
    __half2 t;
    t.x = __float2half_rn(a);
    t.y = __float2half_rn(b);
    return *reinterpret_cast<uint32_t*>(&t);
}

// fast exp for logits in ~[-0.6, 0]
__device__ __forceinline__ float exp_fast(float x) {
    float t = fmaxf(x * 1.4426950408889634f, -100.f);
    float r = t + 12582912.0f;
    int ri = __float_as_int(r);
    float fi = r - 12582912.0f;
    float f = t - fi;
    float p = 0.00133335581f;
    p = fmaf(p, f, 0.00961812911f);
    p = fmaf(p, f, 0.05550410866f);
    p = fmaf(p, f, 0.24022650696f);
    p = fmaf(p, f, 0.69314718056f);
    p = fmaf(p, f, 1.0f);
    float s = __int_as_float((ri + 127) << 23);
    return p * s;
}

// ---------------- reductions --------------------------------------------------
__device__ __forceinline__ float blockReduceSum(float v, float* sm) {
    #pragma unroll
    for (int o = 16; o; o >>= 1) v += __shfl_xor_sync(0xffffffffu, v, o);
    int w = threadIdx.x >> 5;
    if ((threadIdx.x & 31) == 0) sm[w] = v;
    __syncthreads();
    if (threadIdx.x < 32) {
        float t = (threadIdx.x < 8) ? sm[threadIdx.x] : 0.f;
        #pragma unroll
        for (int o = 4; o; o >>= 1) t += __shfl_xor_sync(0xffffffffu, t, o);
        if (threadIdx.x == 0) sm[0] = t;
    }
    __syncthreads();
    float r = sm[0];
    __syncthreads();
    return r;
}
__device__ __forceinline__ float gelu_tanh(float x) {
    float x3 = x * x * x;
    float t = tanhf(0.7978845608028654f * (x + 0.044715f * x3));
    return 0.5f * x * (1.0f + t);
}

// ---------------- layernorm (writes fp16 gA_hi directly) ----------------------
__global__ void __launch_bounds__(256) ln_kernel(const float* __restrict__ Xext,
                                                 int useInternal,
                                                 const float* __restrict__ g,
                                                 const float* __restrict__ b) {
    __shared__ float sm[8];
    const float* X = useInternal ? g_x2 : Xext;
    int row = blockIdx.x;
    const float* xr = X + (size_t)row * D1 + 1;
    float v[4], s = 0.f, sq = 0.f;
    #pragma unroll
    for (int i = 0; i < 4; i++) {
        v[i] = xr[threadIdx.x + i * 256];
        s += v[i]; sq += v[i] * v[i];
    }
    s  = blockReduceSum(s,  sm);
    sq = blockReduceSum(sq, sm);
    float mu = s * (1.f / DD);
    float var = sq * (1.f / DD) - mu * mu;
    float rstd = rsqrtf(var + 1e-5f);
    float o[4], ss = 0.f;
    #pragma unroll
    for (int i = 0; i < 4; i++) {
        int c = threadIdx.x + i * 256;
        o[i] = (v[i] - mu) * rstd * g[c] + b[c];
        ss += o[i] * o[i];
    }
    ss = blockReduceSum(ss, sm);
    size_t ob = (size_t)row * KP1;
    if (threadIdx.x == 0)
        gA_hi[ob] = __float2half_rn(sqrtf(1.f + ss));
    #pragma unroll
    for (int i = 0; i < 4; i++)
        gA_hi[ob + 1 + threadIdx.x + i * 256] = __float2half_rn(o[i]);
    if (threadIdx.x < KP1 - 1025)
        gA_hi[ob + 1025 + threadIdx.x] = __float2half_rn(0.f);
}

// ---------------- weight transpose + fp16 split -------------------------------
__global__ void __launch_bounds__(256) transW_k(const float* __restrict__ src,
                                                int dstRow0, int K, int Kp,
                                                int strideK, int headStride,
                                                int headWidth) {
    __shared__ float t[32][33];
    int tx = threadIdx.x & 31, ty = threadIdx.x >> 5;
    int k0 = blockIdx.x * 32, n0 = blockIdx.y * 32;
    #pragma unroll
    for (int i = 0; i < 4; i++) {
        int k = k0 + ty + i * 8;
        int n = n0 + tx;
        float v = 0.f;
        if (k < K)
            v = src[(size_t)(n / headWidth) * headStride + (size_t)k * strideK + (n % headWidth)];
        t[ty + i * 8][tx] = v;
    }
    __syncthreads();
    #pragma unroll
    for (int i = 0; i < 4; i++) {
        int n = n0 + ty + i * 8;
        int k = k0 + tx;
        float v = t[tx][ty + i * 8];
        __half h = __float2half_rn(v);
        __half l = __float2half_rn(v - __half2float(h));
        size_t o = (size_t)(dstRow0 + n) * Kp + k;
        gB_hi[o] = h;
        gB_lo[o] = l;
    }
}

// ---------------- warp-MMA fp16 2-term GEMM (128x128 C tile, 3-stage) ---------
// C = A * B^T; terms: Ah*Bh + Ah*Bl
#define TCS 16384
#define STG 49152
template<int EPI>
__global__ void __launch_bounds__(256, 1) mmagemm_k(
    int asel, int csel,
    const float* __restrict__ bias0, const float* __restrict__ bias1,
    const float* __restrict__ bias2,
    int Kp, int ldc, int nPerMat)
{
    extern __shared__ __align__(128) char dsm[];
    uint32_t sb0 = smem_u32(dsm);

    int tid = threadIdx.x;
    int wid = tid >> 5, lane = tid & 31;
    int wm = wid & 3, wn = wid >> 2;
    int m0 = blockIdx.y * 128, n0 = blockIdx.x * 128;

    int lchunk = tid & 7;
    int lrow = tid >> 3;

    const __half* srcs[3] = {asel ? gA2_hi : gA_hi, gB_hi, gB_lo};
    const int NC = Kp >> 6;

    uint32_t aoff[2];
    {
        int khalf = lane >> 4;
        #pragma unroll
        for (int mi = 0; mi < 2; mi++) {
            int r = wm * 32 + mi * 16 + (lane & 15);
            aoff[mi] = (uint32_t)(r * 128) + (uint32_t)(((khalf) ^ (r & 7)) << 4);
        }
    }
    uint32_t boff[4];
    {
        int idx = lane >> 3;
        int khalf = idx & 1;
        #pragma unroll
        for (int jp = 0; jp < 4; jp++) {
            int r = wn * 64 + jp * 16 + (idx >> 1) * 8 + (lane & 7);
            boff[jp] = (uint32_t)(r * 128) + (uint32_t)((khalf ^ (r & 7)) << 4);
        }
    }

    float acc[2][8][4];
    #pragma unroll
    for (int i = 0; i < 2; i++)
        #pragma unroll
        for (int j = 0; j < 8; j++)
            #pragma unroll
            for (int q = 0; q < 4; q++) acc[i][j][q] = 0.f;

    auto load_stage = [&](int ic, int st) {
        size_t kbase = (size_t)ic * 64 + lchunk * 8;
        uint32_t sbase = sb0 + st * STG;
        #pragma unroll
        for (int t = 0; t < 3; t++) {
            int rowBase = (t == 0) ? m0 : n0;
            const __half* src = srcs[t];
            #pragma unroll
            for (int i = 0; i < 4; i++) {
                int r = lrow + i * 32;
                const void* gp = src + (size_t)(rowBase + r) * Kp + kbase;
                uint32_t sp = sbase + t * TCS + (uint32_t)(r * 128) +
                              (uint32_t)((lchunk ^ (r & 7)) << 4);
                cp_async16(sp, gp);
            }
        }
        cp_commit();
    };

    load_stage(0, 0);
    if (NC > 1) load_stage(1, 1);

    int st = 0;
    for (int ic = 0; ic < NC; ic++) {
        if (ic + 2 < NC) {
            int st2 = (st + 2) % 3;
            load_stage(ic + 2, st2);
            cp_wait<2>();
        } else if (ic + 1 < NC) {
            cp_wait<1>();
        } else {
            cp_wait<0>();
        }
        __syncthreads();

        uint32_t aH = sb0 + st * STG;
        uint32_t bH = aH + TCS;
        uint32_t bL = aH + 2 * TCS;

        #pragma unroll
        for (int ks = 0; ks < 4; ks++) {
            uint32_t kso = (uint32_t)(ks * 32);
            uint32_t Ah[2][4];
            #pragma unroll
            for (int mi = 0; mi < 2; mi++)
                ldsm_x4(Ah[mi], aH + (aoff[mi] ^ kso));
            uint32_t Bh[8][2], Bl[8][2];
            #pragma unroll
            for (int jp = 0; jp < 4; jp++) {
                uint32_t r4[4];
                ldsm_x4(r4, bH + (boff[jp] ^ kso));
                Bh[jp * 2][0] = r4[0]; Bh[jp * 2][1] = r4[1];
                Bh[jp * 2 + 1][0] = r4[2]; Bh[jp * 2 + 1][1] = r4[3];
                ldsm_x4(r4, bL + (boff[jp] ^ kso));
                Bl[jp * 2][0] = r4[0]; Bl[jp * 2][1] = r4[1];
                Bl[jp * 2 + 1][0] = r4[2]; Bl[jp * 2 + 1][1] = r4[3];
            }
            #pragma unroll
            for (int mi = 0; mi < 2; mi++)
                #pragma unroll
                for (int nj = 0; nj < 8; nj++) {
                    mma_f16(acc[mi][nj], Ah[mi], Bh[nj]);
                    mma_f16(acc[mi][nj], Ah[mi], Bl[nj]);
                }
        }
        __syncthreads();
        st = (st + 1) % 3;
    }

    int selB = (n0 / nPerMat);
    const float* bias = (selB == 0) ? bias0 : (selB == 1 ? bias1 : bias2);
    int nL0 = n0 - selB * nPerMat;

    int g = lane >> 2, t = lane & 3;
    if (csel == 2) {
        // gelu + fp16 write into gA2_hi at col k = 1 + n (ldc = KP2)
        #pragma unroll
        for (int mi = 0; mi < 2; mi++) {
            int r0 = m0 + wm * 32 + mi * 16 + g;
            #pragma unroll
            for (int nj = 0; nj < 8; nj++) {
                int col = wn * 64 + nj * 8 + 2 * t;
                float b0 = bias[nL0 + col], b1 = bias[nL0 + col + 1];
                #pragma unroll
                for (int half = 0; half < 2; half++) {
                    float v0 = gelu_tanh(acc[mi][nj][half * 2 + 0] + b0);
                    float v1 = gelu_tanh(acc[mi][nj][half * 2 + 1] + b1);
                    size_t o = (size_t)(r0 + half * 8) * ldc + 1 + n0 + col;
                    gA2_hi[o] = __float2half_rn(v0);
                    gA2_hi[o + 1] = __float2half_rn(v1);
                }
            }
        }
    } else {
        float* C = (csel == 0) ? g_qkv : g_tmp;
        #pragma unroll
        for (int mi = 0; mi < 2; mi++) {
            int r0 = m0 + wm * 32 + mi * 16 + g;
            #pragma unroll
            for (int nj = 0; nj < 8; nj++) {
                int col = wn * 64 + nj * 8 + 2 * t;
                int cg = n0 + col;
                float b0 = bias[nL0 + col], b1 = bias[nL0 + col + 1];
                float* p0 = C + (size_t)r0 * ldc + cg;
                float* p1 = C + (size_t)(r0 + 8) * ldc + cg;
                p0[0] = acc[mi][nj][0] + b0; p0[1] = acc[mi][nj][1] + b1;
                p1[0] = acc[mi][nj][2] + b0; p1[1] = acc[mi][nj][3] + b1;
            }
        }
    }
}

// ---------------- RoPE + unit-norm + lift; q hi, k hi/lo, V e-major hi/lo -----
__global__ void __launch_bounds__(256) rope_k(const float* __restrict__ rc,
                                              const float* __restrict__ rs) {
    int gw = (blockIdx.x * 256 + threadIdx.x) >> 5;
    int lane = threadIdx.x & 31;
    int mat = gw / (NROW * HH);
    int rem = gw - mat * (NROW * HH);
    int row = rem >> 4;
    int h = rem & 15;
    int b = row >> 10, s = row & 1023;
    int bh = b * HH + h;
    const float* src = g_qkv + (size_t)row * 3072 + mat * 1024 + h * 64 + 2 * lane;
    float x0 = src[0], x1 = src[1];
    if (mat == 0) {
        float c = rc[s * 32 + lane], sn = rs[s * 32 + lane];
        float xr = x0 * c - x1 * sn;
        float xi = x0 * sn + x1 * c;
        float ss = xr * xr + xi * xi;
        #pragma unroll
        for (int o = 16; o; o >>= 1) ss += __shfl_xor_sync(0xffffffffu, ss, o);
        float inv = rsqrtf(ss + 1e-6f);
        float t = sqrtf(1.f + ss * inv * inv);
        __half* dh = g_qh + (size_t)(bh * SS + s) * EP;
        dh[1 + 2 * lane] = __float2half_rn(xr * inv);
        dh[2 + 2 * lane] = __float2half_rn(xi * inv);
        if (lane == 0) dh[0] = __float2half_rn(-t);
        if (lane < 15) dh[65 + lane] = __float2half_rn(0.f);
    } else if (mat == 1) {
        float c = rc[s * 32 + lane], sn = rs[s * 32 + lane];
        float xr = x0 * c - x1 * sn;
        float xi = x0 * sn + x1 * c;
        float ss = xr * xr + xi * xi;
        #pragma unroll
        for (int o = 16; o; o >>= 1) ss += __shfl_xor_sync(0xffffffffu, ss, o);
        float inv = rsqrtf(ss + 1e-6f);
        float t = sqrtf(1.f + ss * inv * inv);
        __half* dh = g_kh + (size_t)(bh * SS + s) * EP;
        __half* dl = g_kl + (size_t)(bh * SS + s) * EP;
        float e1 = xr * inv, e2 = xi * inv;
        __half h1 = __float2half_rn(e1);
        __half h2 = __float2half_rn(e2);
        dh[1 + 2 * lane] = h1; dl[1 + 2 * lane] = __float2half_rn(e1 - __half2float(h1));
        dh[2 + 2 * lane] = h2; dl[2 + 2 * lane] = __float2half_rn(e2 - __half2float(h2));
        if (lane == 0) {
            __half h0 = __float2half_rn(t);
            dh[0] = h0; dl[0] = __float2half_rn(t - __half2float(h0));
        }
        if (lane < 15) {
            dh[65 + lane] = __float2half_rn(0.f);
            dl[65 + lane] = __float2half_rn(0.f);
        }
    } else {
        float ss = x0 * x0 + x1 * x1;
        #pragma unroll
        for (int o = 16; o; o >>= 1) ss += __shfl_xor_sync(0xffffffffu, ss, o);
        __half* vh = g_vh + (size_t)bh * VE * SS;
        __half* vl = g_vl + (size_t)bh * VE * SS;
        __half h1 = __float2half_rn(x0);
        __half h2 = __float2half_rn(x1);
        vh[(size_t)(1 + 2 * lane) * SS + s] = h1;
        vl[(size_t)(1 + 2 * lane) * SS + s] = __float2half_rn(x0 - __half2float(h1));
        vh[(size_t)(2 + 2 * lane) * SS + s] = h2;
        vl[(size_t)(2 + 2 * lane) * SS + s] = __float2half_rn(x1 - __half2float(h2));
        if (lane == 0) {
            float t = sqrtf(1.f + ss);
            __half h0 = __float2half_rn(t);
            vh[s] = h0;
            vl[s] = __float2half_rn(t - __half2float(h0));
        }
        if (lane < 15) {
            vh[(size_t)(65 + lane) * SS + s] = __float2half_rn(0.f);
            vl[(size_t)(65 + lane) * SS + s] = __float2half_rn(0.f);
        }
    }
}

// ---------------- flash attention (fp16 2-term) -------------------------------
// S = Qh(Kh+Kl); P = exp(S*scl) unnormalized; O += Ph(Vh+Vl); project; -> gA_hi.
#define SROW 176
#define FQ_SZ  22528                  // Q hi only
#define FK_HI  0
#define FK_LO  11264
#define FV_HI  22528
#define FV_LO  32768
#define F_STG  43008
__global__ void __launch_bounds__(256, 1) flash_k(const float* __restrict__ scale_p) {
    extern __shared__ __align__(128) char dsm[];
    uint32_t sb = smem_u32(dsm);

    int tid = threadIdx.x;
    int wid = tid >> 5, lane = tid & 31;
    int bh = blockIdx.y;
    int m0 = blockIdx.x * 128;
    size_t qkBase = (size_t)bh * SS;
    size_t vBase = (size_t)bh * VE * SS;

    // load Q hi (128 rows x 160B, stride 176B)
    #pragma unroll
    for (int i = 0; i < 5; i++) {
        int id = i * 256 + tid;
        int r = id / 10, c = id - r * 10;
        cp_async16(sb + r * SROW + c * 16, g_qh + (qkBase + m0 + r) * EP + c * 8);
    }
    cp_commit();

    auto load_kv = [&](int ic, int st) {
        uint32_t sbase = sb + FQ_SZ + st * F_STG;
        for (int lin = tid; lin < 640; lin += 256) {
            int r = lin / 10, c = lin - (lin / 10) * 10;   // K: 64 rows x 10 chunks
            size_t go = (qkBase + ic * 64 + r) * EP + c * 8;
            cp_async16(sbase + FK_HI + r * SROW + c * 16, g_kh + go);
            cp_async16(sbase + FK_LO + r * SROW + c * 16, g_kl + go);
        }
        for (int lin = tid; lin < 640; lin += 256) {
            int r = lin >> 3, c = lin & 7;                 // V: 80 rows x 8 chunks
            size_t go = vBase + (size_t)r * SS + ic * 64 + c * 8;
            uint32_t so = (uint32_t)(r * 128) + (uint32_t)((c ^ (r & 7)) << 4);
            cp_async16(sbase + FV_HI + so, g_vh + go);
            cp_async16(sbase + FV_LO + so, g_vl + go);
        }
        cp_commit();
    };

    uint32_t qoff;
    {
        int khalf = lane >> 4;
        int r = wid * 16 + (lane & 15);
        qoff = (uint32_t)(r * SROW + khalf * 16);
    }
    uint32_t koff[4];
    {
        int idx = lane >> 3;
        int khalf = idx & 1;
        #pragma unroll
        for (int jp = 0; jp < 4; jp++) {
            int r = jp * 16 + (idx >> 1) * 8 + (lane & 7);
            koff[jp] = (uint32_t)(r * SROW + khalf * 16);
        }
    }
    uint32_t voff[5];
    {
        int idx = lane >> 3;
        int khalf = idx & 1;
        #pragma unroll
        for (int jp = 0; jp < 5; jp++) {
            int r = jp * 16 + (idx >> 1) * 8 + (lane & 7);
            voff[jp] = (uint32_t)(r * 128) + (uint32_t)((khalf ^ (r & 7)) << 4);
        }
    }

    float O[10][4];
    #pragma unroll
    for (int j = 0; j < 10; j++)
        #pragma unroll
        for (int q = 0; q < 4; q++) O[j][q] = 0.f;

    float scl = 2.0f / scale_p[0];
    load_kv(0, 0);

    for (int ic = 0; ic < 16; ic++) {
        int st = ic & 1;
        if (ic + 1 < 16) {
            load_kv(ic + 1, st ^ 1);
            cp_wait<1>();
        } else {
            cp_wait<0>();
        }
        __syncthreads();

        uint32_t kb = sb + FQ_SZ + st * F_STG;
        uint32_t qH = sb;
        uint32_t kH = kb + FK_HI, kL = kb + FK_LO;
        uint32_t vH = kb + FV_HI, vL = kb + FV_LO;

        // ---- S = Q K^T (16 rows x 64 cols per warp, 2-term)
        float S[8][4];
        #pragma unroll
        for (int j = 0; j < 8; j++)
            #pragma unroll
            for (int q = 0; q < 4; q++) S[j][q] = 0.f;

        #pragma unroll
        for (int ks = 0; ks < 5; ks++) {
            uint32_t co = (uint32_t)(ks * 32);
            uint32_t Ah[4];
            ldsm_x4(Ah, qH + qoff + co);
            uint32_t Bh[8][2], Bl[8][2];
            #pragma unroll
            for (int jp = 0; jp < 4; jp++) {
                uint32_t r4[4];
                ldsm_x4(r4, kH + koff[jp] + co);
                Bh[jp * 2][0] = r4[0]; Bh[jp * 2][1] = r4[1];
                Bh[jp * 2 + 1][0] = r4[2]; Bh[jp * 2 + 1][1] = r4[3];
                ldsm_x4(r4, kL + koff[jp] + co);
                Bl[jp * 2][0] = r4[0]; Bl[jp * 2][1] = r4[1];
                Bl[jp * 2 + 1][0] = r4[2]; Bl[jp * 2 + 1][1] = r4[3];
            }
            #pragma unroll
            for (int nj = 0; nj < 8; nj++) {
                mma_f16(S[nj], Ah, Bh[nj]);
                mma_f16(S[nj], Ah, Bl[nj]);
            }
        }

        // ---- P = exp(S*scl); repack C-frags as A-frags; O += P V (2-term)
        #pragma unroll
        for (int kc = 0; kc < 4; kc++) {
            float p[8];
            #pragma unroll
            for (int q = 0; q < 4; q++) {
                p[q]     = exp_fast(S[2 * kc][q] * scl);
                p[4 + q] = exp_fast(S[2 * kc + 1][q] * scl);
            }
            uint32_t Pah[4];
            Pah[0] = pack2h(p[0], p[1]);
            Pah[1] = pack2h(p[2], p[3]);
            Pah[2] = pack2h(p[4], p[5]);
            Pah[3] = pack2h(p[6], p[7]);
            uint32_t kso = (uint32_t)(kc * 32);
            uint32_t Vh[10][2], Vl[10][2];
            #pragma unroll
            for (int jp = 0; jp < 5; jp++) {
                uint32_t r4[4];
                ldsm_x4(r4, vH + (voff[jp] ^ kso));
                Vh[jp * 2][0] = r4[0]; Vh[jp * 2][1] = r4[1];
                Vh[jp * 2 + 1][0] = r4[2]; Vh[jp * 2 + 1][1] = r4[3];
                ldsm_x4(r4, vL + (voff[jp] ^ kso));
                Vl[jp * 2][0] = r4[0]; Vl[jp * 2][1] = r4[1];
                Vl[jp * 2 + 1][0] = r4[2]; Vl[jp * 2 + 1][1] = r4[3];
            }
            #pragma unroll
            for (int nj = 0; nj < 10; nj++) {
                mma_f16(O[nj], Pah, Vh[nj]);
                mma_f16(O[nj], Pah, Vl[nj]);
            }
        }
        __syncthreads();
    }

    // ---- in-register Lorentz project; write fp16 into gA_hi (cat layout)
    int g = lane >> 2, t = lane & 3;
    float s0 = 0.f, s1 = 0.f;
    #pragma unroll
    for (int nj = 0; nj < 10; nj++) {
        s0 += O[nj][0] * O[nj][0] + O[nj][1] * O[nj][1];
        s1 += O[nj][2] * O[nj][2] + O[nj][3] * O[nj][3];
    }
    s0 += __shfl_xor_sync(0xffffffffu, s0, 1);
    s0 += __shfl_xor_sync(0xffffffffu, s0, 2);
    s1 += __shfl_xor_sync(0xffffffffu, s1, 1);
    s1 += __shfl_xor_sync(0xffffffffu, s1, 2);
    float m00 = __shfl_sync(0xffffffffu, O[0][0], lane & ~3);
    float m01 = __shfl_sync(0xffffffffu, O[0][2], lane & ~3);
    float inv0 = rsqrtf(fmaxf(2.f * m00 * m00 - s0, 1e-6f));
    float inv1 = rsqrtf(fmaxf(2.f * m01 * m01 - s1, 1e-6f));

    int b = bh >> 4, h = bh & 15;
    int sq0 = m0 + wid * 16 + g;
    size_t r0 = (size_t)(b * SS + sq0) * KP1 + h * HD1;
    size_t r1 = (size_t)(b * SS + sq0 + 8) * KP1 + h * HD1;
    #pragma unroll
    for (int nj = 0; nj < 10; nj++) {
        int e = nj * 8 + 2 * t;
        #pragma unroll
        for (int q = 0; q < 2; q++) {
            if (e + q < 65) {
                gA_hi[r0 + e + q] = __float2half_rn(O[nj][q] * inv0);
                gA_hi[r1 + e + q] = __float2half_rn(O[nj][2 + q] * inv1);
            }
        }
    }
    if (h == 0) {
        for (int lin = tid; lin < 128 * 48; lin += 256) {
            int rr = lin / 48, cc = lin - (lin / 48) * 48;
            gA_hi[(size_t)(b * SS + m0 + rr) * KP1 + 1040 + cc] = __float2half_rn(0.f);
        }
    }
}

// ---------------- residual + project ------------------------------------------
__global__ void __launch_bounds__(256) resproj_k(const float* __restrict__ Xext,
                                                 int useInternalX,
                                                 const float* __restrict__ wp,
                                                 float* __restrict__ Oext,
                                                 int outInternal) {
    __shared__ float sm[8];
    const float* X = useInternalX ? g_x2 : Xext;
    float* out = outInternal ? g_x2 : Oext;
    int row = blockIdx.x;
    const float* ao = g_tmp + (size_t)row * DD;
    const float* xr = X + (size_t)row * D1;
    float a[4], sa = 0.f;
    #pragma unroll
    for (int i = 0; i < 4; i++) {
        a[i] = ao[threadIdx.x + i * 256];
        sa += a[i] * a[i];
    }
    sa = blockReduceSum(sa, sm);
    float w = wp[0];
    float tao = sqrtf(1.f + sa);
    float z0 = xr[0] + w * tao;
    float z[4], sz = 0.f;
    #pragma unroll
    for (int i = 0; i < 4; i++) {
        z[i] = xr[1 + threadIdx.x + i * 256] + w * a[i];
        sz += z[i] * z[i];
    }
    sz = blockReduceSum(sz, sm);
    float dinv = rsqrtf(fmaxf(z0 * z0 - sz, 1e-6f));
    float* orow = out + (size_t)row * D1;
    if (threadIdx.x == 0) orow[0] = z0 * dinv;
    #pragma unroll
    for (int i = 0; i < 4; i++) orow[1 + threadIdx.x + i * 256] = z[i] * dinv;
}

// ---------------- ff time component (reads gA2_hi, writes col0 + K-pad) -------
__global__ void __launch_bounds__(256) ffT_k() {
    __shared__ float sm[8];
    int row = blockIdx.x;
    size_t ob = (size_t)row * KP2;
    float ss = 0.f;
    #pragma unroll
    for (int i = 0; i < 16; i++) {
        float v = __half2float(gA2_hi[ob + 1 + threadIdx.x + i * 256]);
        ss += v * v;
    }
    ss = blockReduceSum(ss, sm);
    if (threadIdx.x == 0)
        gA2_hi[ob] = __float2half_rn(sqrtf(1.f + ss));
    if (threadIdx.x < KP2 - 4097)
        gA2_hi[ob + 4097 + threadIdx.x] = __float2half_rn(0.f);
}

// ---------------- launcher ----------------------------------------------------
extern "C" void kernel_launch(void* const* d_in, const int* in_sizes, int n_in,
                              void* d_out, int out_size) {
    const float* x      = (const float*)d_in[0];
    const float* rc     = (const float*)d_in[1];
    const float* rs     = (const float*)d_in[2];
    const float* n1g    = (const float*)d_in[3];
    const float* n1b    = (const float*)d_in[4];
    const float* Wq     = (const float*)d_in[5];
    const float* bq     = (const float*)d_in[6];
    const float* Wk     = (const float*)d_in[7];
    const float* bk     = (const float*)d_in[8];
    const float* Wv     = (const float*)d_in[9];
    const float* bv     = (const float*)d_in[10];
    const float* ascale = (const float*)d_in[11];
    const float* Wo     = (const float*)d_in[13];
    const float* bo     = (const float*)d_in[14];
    const float* wr1    = (const float*)d_in[15];
    const float* n2g    = (const float*)d_in[16];
    const float* n2b    = (const float*)d_in[17];
    const float* W1     = (const float*)d_in[18];
    const float* b1     = (const float*)d_in[19];
    const float* W2     = (const float*)d_in[20];
    const float* b2     = (const float*)d_in[21];
    const float* wr2    = (const float*)d_in[22];
    float* out = (float*)d_out;

    const int DSM   = 3 * STG;               // 147456 B
    const int DSM_F = FQ_SZ + 2 * F_STG;     // 108544 B
    cudaFuncSetAttribute(mmagemm_k<0>, cudaFuncAttributeMaxDynamicSharedMemorySize, DSM);
    cudaFuncSetAttribute(mmagemm_k<1>, cudaFuncAttributeMaxDynamicSharedMemorySize, DSM);
    cudaFuncSetAttribute(flash_k, cudaFuncAttributeMaxDynamicSharedMemorySize, DSM_F);

    const int BIG = 1 << 30;

    // ---- attention half ----
    ln_kernel<<<NROW, 256>>>(x, 0, n1g, n1b);
    transW_k<<<dim3(KP1 / 32, 32), 256>>>(Wq, 0,    D1, KP1, HDIM, D1 * HDIM, HDIM);
    transW_k<<<dim3(KP1 / 32, 32), 256>>>(Wk, 1024, D1, KP1, HDIM, D1 * HDIM, HDIM);
    transW_k<<<dim3(KP1 / 32, 32), 256>>>(Wv, 2048, D1, KP1, HDIM, D1 * HDIM, HDIM);
    mmagemm_k<0><<<dim3(24, 32), 256, DSM>>>(0, 0, bq, bk, bv, KP1, 3072, 1024);

    rope_k<<<24576, 256>>>(rc, rs);
    flash_k<<<dim3(8, 64), 256, DSM_F>>>(ascale);

    transW_k<<<dim3(KP1 / 32, 32), 256>>>(Wo, 0, CATW, KP1, DD, 0, DD);
    mmagemm_k<0><<<dim3(8, 32), 256, DSM>>>(0, 1, bo, bo, bo, KP1, DD, BIG);
    resproj_k<<<NROW, 256>>>(x, 0, wr1, nullptr, 1);

    // ---- MLP half ----
    ln_kernel<<<NROW, 256>>>(nullptr, 1, n2g, n2b);
    transW_k<<<dim3(KP1 / 32, FFDIM / 32), 256>>>(W1, 0, D1, KP1, FFDIM, 0, FFDIM);
    mmagemm_k<1><<<dim3(32, 32), 256, DSM>>>(0, 2, b1, b1, b1, KP1, KP2, BIG);
    ffT_k<<<NROW, 256>>>();

    transW_k<<<dim3(KP2 / 32, 32), 256>>>(W2, 0, FFDIM + 1, KP2, DD, 0, DD);
    mmagemm_k<0><<<dim3(8, 32), 256, DSM>>>(1, 1, b2, b2, b2, KP2, DD, BIG);
    resproj_k<<<NROW, 256>>>(nullptr, 1, wr2, out, 0);
}